// round 5
// baseline (speedup 1.0000x reference)
#include <cuda_runtime.h>
#include <cuda_fp16.h>
#include <cstdint>

// ---------------------------------------------------------------------------
// Problem shape (fixed by setup_inputs: B=4, S=2048, K=4096, N=4096)
// ---------------------------------------------------------------------------
namespace {
constexpr int M_DIM = 8192;
constexpr int N_DIM = 4096;
constexpr int K_DIM = 4096;
constexpr int K0C   = 256;
constexpr int KT    = K_DIM - K0C;          // 3840 tail K
constexpr float TAU = 3.0f;
constexpr float EPS = 1e-6f;

// Tail HMMA tiling (single-pass fp16)
constexpr int BM = 128;
constexpr int BN = 128;
constexpr int BK = 64;                       // fp16 K elems per chunk (128B rows)
constexpr int NCHUNK = KT / BK;              // 60

constexpr int STAGE_A = BM * 128;            // 16384 B
constexpr int STAGE_B = BN * 128;            // 16384 B
constexpr int STAGE_BYTES = STAGE_A + STAGE_B;   // 32768
constexpr int NSTAGE = 3;
constexpr int SMEM_FUSED = NSTAGE * STAGE_BYTES; // 98304

constexpr int N_TAIL_CTAS = (M_DIM / BM) * (N_DIM / BN);   // 2048
constexpr int N_HEAD_CTAS = (M_DIM / 128) * (N_DIM / 64);  // 4096
constexpr int N_FUSED_CTAS = N_TAIL_CTAS + N_HEAD_CTAS;    // 6144
}

// ---------------------------------------------------------------------------
// Device scratch (static; no dynamic allocation allowed)
// ---------------------------------------------------------------------------
__device__ __align__(1024) unsigned char g_mask[(size_t)M_DIM * N_DIM];
__device__ __align__(1024) float         g_tail[(size_t)M_DIM * N_DIM];
__device__ __align__(1024) __half        g_Xh[(size_t)M_DIM * KT];
__device__ __align__(1024) __half        g_Wh[(size_t)N_DIM * KT];

// ---------------------------------------------------------------------------
// Helpers (base-ISA only: cp.async / ldmatrix / mma.sync)
// ---------------------------------------------------------------------------
__device__ __forceinline__ uint32_t smem_u32(const void* p) {
    uint32_t a;
    asm("{ .reg .u64 t; cvta.to.shared.u64 t, %1; cvt.u32.u64 %0, t; }" : "=r"(a) : "l"(p));
    return a;
}
#define SWZ128(off) ((off) ^ (((off) >> 3) & 0x70))

__device__ __forceinline__ void cp_async16(uint32_t dst, const void* src) {
    asm volatile("cp.async.cg.shared.global [%0], [%1], 16;"
                 :: "r"(dst), "l"(__cvta_generic_to_global(src)) : "memory");
}
#define CP_COMMIT() asm volatile("cp.async.commit_group;" ::: "memory")
#define CP_WAIT2()  asm volatile("cp.async.wait_group 2;" ::: "memory")

__device__ __forceinline__ void ldsm_x4(uint32_t& r0, uint32_t& r1, uint32_t& r2,
                                        uint32_t& r3, uint32_t addr) {
    asm volatile("ldmatrix.sync.aligned.m8n8.x4.shared.b16 {%0,%1,%2,%3}, [%4];"
                 : "=r"(r0), "=r"(r1), "=r"(r2), "=r"(r3) : "r"(addr));
}
__device__ __forceinline__ void mma_fp16(float* c, const uint32_t* a,
                                         uint32_t b0, uint32_t b1) {
    asm volatile("mma.sync.aligned.m16n8k16.row.col.f32.f16.f16.f32 "
                 "{%0,%1,%2,%3}, {%4,%5,%6,%7}, {%8,%9}, {%0,%1,%2,%3};"
                 : "+f"(c[0]), "+f"(c[1]), "+f"(c[2]), "+f"(c[3])
                 : "r"(a[0]), "r"(a[1]), "r"(a[2]), "r"(a[3]), "r"(b0), "r"(b1));
}

// ---------------------------------------------------------------------------
// Convert: fp32 tail cols [256,4096) -> fp16 scratch (RN)
// ---------------------------------------------------------------------------
__global__ __launch_bounds__(256)
void conv_half(const float* __restrict__ src, __half* __restrict__ dst, int nrows)
{
    const int per_row = KT / 4;
    int idx = blockIdx.x * 256 + threadIdx.x;
    if (idx >= nrows * per_row) return;
    int row = idx / per_row;
    int c   = (idx - row * per_row) * 4;
    float4 v = *reinterpret_cast<const float4*>(src + (size_t)row * K_DIM + K0C + c);
    __half2 h0 = __floats2half2_rn(v.x, v.y);
    __half2 h1 = __floats2half2_rn(v.z, v.w);
    uint2 out;
    out.x = *reinterpret_cast<uint32_t*>(&h0);
    out.y = *reinterpret_cast<uint32_t*>(&h1);
    *reinterpret_cast<uint2*>(dst + (size_t)row * KT + c) = out;
}

// ---------------------------------------------------------------------------
// Head body (fp32 SIMT decision path — unchanged math, dynamic smem overlay)
// ---------------------------------------------------------------------------
__device__ __forceinline__
void head_body(int sub, char* smem_raw,
               const float* __restrict__ X, const float* __restrict__ W,
               const float* __restrict__ Bv, float* __restrict__ Out)
{
    float (*As)[132] = reinterpret_cast<float(*)[132]>(smem_raw);              // 16x132
    float (*Bs)[68]  = reinterpret_cast<float(*)[68]>(smem_raw + 16*132*4);    // 16x68

    const int bm  = (sub >> 6) * 128;
    const int bn  = (sub & 63) * 64;
    const int tid = threadIdx.x;
    const int tx  = tid & 15;
    const int ty  = tid >> 4;

    float accY[8][4] = {};
    float accS[8][4] = {};

    for (int k0 = 0; k0 < K0C; k0 += 16) {
        #pragma unroll
        for (int l = 0; l < 2; ++l) {
            int idx = tid + l * 256;
            int row = idx >> 2;
            int kq  = idx & 3;
            float4 v = *reinterpret_cast<const float4*>(
                &X[(size_t)(bm + row) * K_DIM + k0 + kq * 4]);
            As[kq * 4 + 0][row] = v.x; As[kq * 4 + 1][row] = v.y;
            As[kq * 4 + 2][row] = v.z; As[kq * 4 + 3][row] = v.w;
        }
        {
            int row = tid >> 2;
            int kq  = tid & 3;
            float4 v = *reinterpret_cast<const float4*>(
                &W[(size_t)(bn + row) * K_DIM + k0 + kq * 4]);
            Bs[kq * 4 + 0][row] = v.x; Bs[kq * 4 + 1][row] = v.y;
            Bs[kq * 4 + 2][row] = v.z; Bs[kq * 4 + 3][row] = v.w;
        }
        __syncthreads();

        #pragma unroll
        for (int kk = 0; kk < 16; ++kk) {
            float a[8], b[4], aa[8], bb[4];
            const float4* ap = reinterpret_cast<const float4*>(&As[kk][ty * 8]);
            float4 a0 = ap[0], a1 = ap[1];
            a[0]=a0.x; a[1]=a0.y; a[2]=a0.z; a[3]=a0.w;
            a[4]=a1.x; a[5]=a1.y; a[6]=a1.z; a[7]=a1.w;
            const float4* bp = reinterpret_cast<const float4*>(&Bs[kk][tx * 4]);
            float4 b0 = bp[0];
            b[0]=b0.x; b[1]=b0.y; b[2]=b0.z; b[3]=b0.w;
            #pragma unroll
            for (int i = 0; i < 8; ++i) aa[i] = a[i] * a[i];
            #pragma unroll
            for (int j = 0; j < 4; ++j) bb[j] = b[j] * b[j];
            #pragma unroll
            for (int i = 0; i < 8; ++i)
                #pragma unroll
                for (int j = 0; j < 4; ++j) {
                    accY[i][j] = fmaf(a[i],  b[j],  accY[i][j]);
                    accS[i][j] = fmaf(aa[i], bb[j], accS[i][j]);
                }
        }
        __syncthreads();
    }

    #pragma unroll
    for (int i = 0; i < 8; ++i) {
        const int m = bm + ty * 8 + i;
        #pragma unroll
        for (int j = 0; j < 4; ++j) {
            const int n = bn + tx * 4 + j;
            const float y1    = accY[i][j];
            const float denom = sqrtf(accS[i][j] * (1.0f / 256.0f) + EPS);
            const float t     = fabsf(y1) / fmaxf(denom, EPS);
            const bool passed = t < TAU;
            const size_t o = (size_t)m * N_DIM + n;
            Out[o]    = passed ? Bv[n] : (y1 + Bv[n]);
            g_mask[o] = passed ? 0 : 1;
        }
    }
}

// ---------------------------------------------------------------------------
// Tail body: single-pass fp16 HMMA GEMM, writes raw sums to g_tail (no mask).
// ---------------------------------------------------------------------------
__device__ __forceinline__
void tail_body(int sub, char* smem_raw)
{
    const uint32_t sbase = smem_u32(smem_raw);
    const int tid  = threadIdx.x;
    const int wid  = tid >> 5;
    const int lane = tid & 31;

    const int bm = (sub >> 5) * BM;
    const int bn = (sub & 31) * BN;

    const int warpM = (wid & 3) * 32;
    const int warpN = (wid >> 2) * 64;

    const int subl = lane >> 3;
    const int tr   = lane & 7;
    const int aRow = (subl & 1) * 8 + tr;
    const int aK8  = (subl >> 1);
    const int bRow = (subl >> 1) * 8 + tr;
    const int bK8  = (subl & 1);

    float acc[2][8][4];
    #pragma unroll
    for (int i = 0; i < 2; ++i)
        #pragma unroll
        for (int j = 0; j < 8; ++j)
            #pragma unroll
            for (int q = 0; q < 4; ++q) acc[i][j][q] = 0.0f;

    auto load_chunk = [&](int it, int buf) {
        const __half* Ap = g_Xh + (size_t)bm * KT + it * BK;
        const __half* Bp = g_Wh + (size_t)bn * KT + it * BK;
        const uint32_t aOff = buf * STAGE_BYTES;
        const uint32_t bOff = aOff + STAGE_A;
        #pragma unroll
        for (int l = 0; l < 4; ++l) {
            int idx = tid + l * 256;
            int r = idx >> 3, c = idx & 7;
            cp_async16(sbase + aOff + SWZ128((uint32_t)(r * 128 + c * 16)),
                       Ap + (size_t)r * KT + c * 8);
        }
        #pragma unroll
        for (int l = 0; l < 4; ++l) {
            int idx = tid + l * 256;
            int r = idx >> 3, c = idx & 7;
            cp_async16(sbase + bOff + SWZ128((uint32_t)(r * 128 + c * 16)),
                       Bp + (size_t)r * KT + c * 8);
        }
    };

    load_chunk(0, 0); CP_COMMIT();
    load_chunk(1, 1); CP_COMMIT();

    int buf = 0;
    for (int it = 0; it < NCHUNK; ++it) {
        if (it + 2 < NCHUNK) {
            int nb = buf + 2; if (nb >= NSTAGE) nb -= NSTAGE;
            load_chunk(it + 2, nb);
        }
        CP_COMMIT();
        CP_WAIT2();
        __syncthreads();

        const uint32_t aBase = sbase + buf * STAGE_BYTES;
        const uint32_t bBase = aBase + STAGE_A;

        #pragma unroll
        for (int ks = 0; ks < 4; ++ks) {
            uint32_t afrag[2][4];
            #pragma unroll
            for (int mi = 0; mi < 2; ++mi) {
                int row = warpM + mi * 16 + aRow;
                uint32_t byte = (uint32_t)(row * 128) +
                                ((uint32_t)((ks * 2 + aK8) * 16) ^ ((row & 7) * 16));
                ldsm_x4(afrag[mi][0], afrag[mi][1], afrag[mi][2], afrag[mi][3],
                        aBase + byte);
            }
            #pragma unroll
            for (int pr = 0; pr < 4; ++pr) {
                int row = warpN + pr * 16 + bRow;
                uint32_t byte = (uint32_t)(row * 128) +
                                ((uint32_t)((ks * 2 + bK8) * 16) ^ ((row & 7) * 16));
                uint32_t b0, b1, b2, b3;
                ldsm_x4(b0, b1, b2, b3, bBase + byte);
                #pragma unroll
                for (int mi = 0; mi < 2; ++mi) {
                    mma_fp16(acc[mi][pr * 2 + 0], afrag[mi], b0, b1);
                    mma_fp16(acc[mi][pr * 2 + 1], afrag[mi], b2, b3);
                }
            }
        }
        __syncthreads();
        ++buf; if (buf == NSTAGE) buf = 0;
    }

    // Plain 64-bit stores of raw tail sums (no mask read, no RMW)
    const int mrow = lane >> 2;
    const int ncol = (lane & 3) * 2;
    #pragma unroll
    for (int mi = 0; mi < 2; ++mi) {
        #pragma unroll
        for (int ni = 0; ni < 8; ++ni) {
            const int m = bm + warpM + mi * 16 + mrow;
            const int n = bn + warpN + ni * 8 + ncol;
            size_t o  = (size_t)m * N_DIM + n;
            size_t o2 = o + (size_t)8 * N_DIM;
            float2 v0 = {acc[mi][ni][0], acc[mi][ni][1]};
            float2 v1 = {acc[mi][ni][2], acc[mi][ni][3]};
            *reinterpret_cast<float2*>(&g_tail[o])  = v0;
            *reinterpret_cast<float2*>(&g_tail[o2]) = v1;
        }
    }
}

// ---------------------------------------------------------------------------
// Fused kernel: CTA-type dispatch. Per 6 CTAs: 2 tail + 4 head (mixes types
// across co-resident CTAs so tensor and fma pipes run concurrently).
// ---------------------------------------------------------------------------
__global__ __launch_bounds__(256, 2)
void fused_kernel(const float* __restrict__ X, const float* __restrict__ W,
                  const float* __restrict__ Bv, float* __restrict__ Out)
{
    extern __shared__ __align__(1024) char smem[];
    const int bid = blockIdx.x;
    const int g6  = bid / 6;
    const int r   = bid - g6 * 6;
    if (r < 2) {
        tail_body(g6 * 2 + r, smem);
    } else {
        head_body(g6 * 4 + (r - 2), smem, X, W, Bv, Out);
    }
}

// ---------------------------------------------------------------------------
// Merge: Out += g_tail where mask set. Vectorized x4.
// ---------------------------------------------------------------------------
__global__ __launch_bounds__(256)
void merge_kernel(float* __restrict__ Out)
{
    size_t i4 = (size_t)blockIdx.x * 256 + threadIdx.x;   // one float4 per thread
    const uchar4 m = reinterpret_cast<const uchar4*>(g_mask)[i4];
    if ((m.x | m.y | m.z | m.w) == 0) return;
    const float4 t = reinterpret_cast<const float4*>(g_tail)[i4];
    float4 o = reinterpret_cast<float4*>(Out)[i4];
    if (m.x) o.x += t.x;
    if (m.y) o.y += t.y;
    if (m.z) o.z += t.z;
    if (m.w) o.w += t.w;
    reinterpret_cast<float4*>(Out)[i4] = o;
}

// ---------------------------------------------------------------------------
extern "C" void kernel_launch(void* const* d_in, const int* in_sizes, int n_in,
                              void* d_out, int out_size)
{
    const float* x  = (const float*)d_in[0];   // [8192, 4096]
    const float* w  = (const float*)d_in[1];   // [4096, 4096]
    const float* bv = (const float*)d_in[2];   // [4096]
    float* out      = (float*)d_out;           // [8192, 4096]
    (void)in_sizes; (void)n_in; (void)out_size;

    cudaFuncSetAttribute(fused_kernel,
                         cudaFuncAttributeMaxDynamicSharedMemorySize, SMEM_FUSED);

    __half *xh, *wh;
    cudaGetSymbolAddress((void**)&xh, g_Xh);
    cudaGetSymbolAddress((void**)&wh, g_Wh);

    // fp16 conversions (tail value path only)
    conv_half<<<(M_DIM * (KT / 4) + 255) / 256, 256>>>(x, xh, M_DIM);
    conv_half<<<(N_DIM * (KT / 4) + 255) / 256, 256>>>(w, wh, N_DIM);

    // Co-resident head (fma pipe) + tail (tensor pipe)
    fused_kernel<<<N_FUSED_CTAS, 256, SMEM_FUSED>>>(x, w, bv, out);

    // Apply masked tail
    merge_kernel<<<(int)(((size_t)M_DIM * N_DIM / 4) / 256), 256>>>(out);
}

// round 7
// speedup vs baseline: 1.3780x; 1.3780x over previous
#include <cuda_runtime.h>
#include <cuda_fp16.h>
#include <cstdint>

// ---------------------------------------------------------------------------
// Problem shape (fixed by setup_inputs: B=4, S=2048, K=4096, N=4096)
// ---------------------------------------------------------------------------
namespace {
constexpr int M_DIM = 8192;
constexpr int N_DIM = 4096;
constexpr int K_DIM = 4096;
constexpr int K0C   = 256;
constexpr float TAU = 3.0f;
constexpr float EPS = 1e-6f;
constexpr float BAND = 0.05f;              // gate uncertainty band on t (~8 sigma)
constexpr float SQS  = 50.0f;              // w-square prescale; s2 = accS/(50^2 * 256)

// Big GEMM tiling: CTA 128x256, 8 warps (2m x 4n), warp 64x64, BK=64
constexpr int BM = 128;
constexpr int BN = 256;
constexpr int BK = 64;
constexpr int NCHUNK = K_DIM / BK;          // 64
constexpr int STAGE_A = BM * 128;           // 16384
constexpr int STAGE_B = BN * 128;           // 32768
constexpr int STAGE_BYTES = STAGE_A + STAGE_B;     // 49152
constexpr int NSTAGE = 3;
constexpr int SMEM_BIG = NSTAGE * STAGE_BYTES;     // 147456

// Gate GEMM tiling: CTA 128x64, 8 warps (4m x 2n), warp 32x32, K=256 (4 chunks)
constexpr int GBM = 128;
constexpr int GBN = 64;
constexpr int G_AH = GBM * 128;             // 16384
constexpr int G_BH = GBN * 128;             // 8192
constexpr int G_ASQ = G_AH;                 // 16384
constexpr int G_BSQ = G_BH;                 // 8192
constexpr int G_STAGE = G_AH + G_BH + G_ASQ + G_BSQ;  // 49152
constexpr int SMEM_GATE = 2 * G_STAGE;      // 98304

constexpr int LIST_CAP = 1 << 25;           // 33.5M (full-size safe)
}

// ---------------------------------------------------------------------------
// Device scratch (static; no dynamic allocation allowed)
// ---------------------------------------------------------------------------
__device__ __align__(1024) unsigned char g_mask[(size_t)M_DIM * N_DIM];
__device__ __align__(1024) float         g_full[(size_t)M_DIM * N_DIM];
__device__ __align__(1024) __half        g_Xh[(size_t)M_DIM * K_DIM];
__device__ __align__(1024) __half        g_Wh[(size_t)N_DIM * K_DIM];
__device__ __align__(1024) __half        g_Xsq[(size_t)M_DIM * K0C];
__device__ __align__(1024) __half        g_Wsq[(size_t)N_DIM * K0C];
__device__ __align__(1024) uint32_t      g_list[LIST_CAP];
__device__ int                           g_count;

// ---------------------------------------------------------------------------
// Helpers (base-ISA only: cp.async / ldmatrix / mma.sync)
// ---------------------------------------------------------------------------
__device__ __forceinline__ uint32_t smem_u32(const void* p) {
    uint32_t a;
    asm("{ .reg .u64 t; cvta.to.shared.u64 t, %1; cvt.u32.u64 %0, t; }" : "=r"(a) : "l"(p));
    return a;
}
#define SWZ128(off) ((off) ^ (((off) >> 3) & 0x70))

__device__ __forceinline__ void cp_async16(uint32_t dst, const void* src) {
    asm volatile("cp.async.cg.shared.global [%0], [%1], 16;"
                 :: "r"(dst), "l"(__cvta_generic_to_global(src)) : "memory");
}
#define CP_COMMIT() asm volatile("cp.async.commit_group;" ::: "memory")
#define CP_WAIT0()  asm volatile("cp.async.wait_group 0;" ::: "memory")
#define CP_WAIT1()  asm volatile("cp.async.wait_group 1;" ::: "memory")
#define CP_WAIT2()  asm volatile("cp.async.wait_group 2;" ::: "memory")

__device__ __forceinline__ void ldsm_x4(uint32_t& r0, uint32_t& r1, uint32_t& r2,
                                        uint32_t& r3, uint32_t addr) {
    asm volatile("ldmatrix.sync.aligned.m8n8.x4.shared.b16 {%0,%1,%2,%3}, [%4];"
                 : "=r"(r0), "=r"(r1), "=r"(r2), "=r"(r3) : "r"(addr));
}
__device__ __forceinline__ void mma_fp16(float* c, const uint32_t* a,
                                         uint32_t b0, uint32_t b1) {
    asm volatile("mma.sync.aligned.m16n8k16.row.col.f32.f16.f16.f32 "
                 "{%0,%1,%2,%3}, {%4,%5,%6,%7}, {%8,%9}, {%0,%1,%2,%3};"
                 : "+f"(c[0]), "+f"(c[1]), "+f"(c[2]), "+f"(c[3])
                 : "r"(a[0]), "r"(a[1]), "r"(a[2]), "r"(a[3]), "r"(b0), "r"(b1));
}

// ---------------------------------------------------------------------------
// Zero the uncertain-list counter (determinism across graph replays)
// ---------------------------------------------------------------------------
__global__ void zero_count() { g_count = 0; }

// ---------------------------------------------------------------------------
// Convert: fp32 [rows x 4096] -> fp16 full + fp16 squares (first 256 cols)
// ---------------------------------------------------------------------------
__global__ __launch_bounds__(256)
void conv_kernel(const float* __restrict__ src, __half* __restrict__ dstH,
                 __half* __restrict__ dstSq, float sqscale, int rows)
{
    int idx = blockIdx.x * 256 + threadIdx.x;     // one float4 per thread
    if (idx >= rows * (K_DIM / 4)) return;
    int r  = idx >> 10;                            // / 1024
    int c4 = idx & 1023;
    float4 v = *reinterpret_cast<const float4*>(src + (size_t)r * K_DIM + c4 * 4);
    __half2 h0 = __floats2half2_rn(v.x, v.y);
    __half2 h1 = __floats2half2_rn(v.z, v.w);
    uint2 H;
    H.x = *reinterpret_cast<uint32_t*>(&h0);
    H.y = *reinterpret_cast<uint32_t*>(&h1);
    *reinterpret_cast<uint2*>(dstH + (size_t)r * K_DIM + c4 * 4) = H;
    if (c4 < K0C / 4) {
        float sx = v.x * sqscale, sy = v.y * sqscale;
        float sz = v.z * sqscale, sw = v.w * sqscale;
        __half2 q0 = __floats2half2_rn(sx * sx, sy * sy);
        __half2 q1 = __floats2half2_rn(sz * sz, sw * sw);
        uint2 Q;
        Q.x = *reinterpret_cast<uint32_t*>(&q0);
        Q.y = *reinterpret_cast<uint32_t*>(&q1);
        *reinterpret_cast<uint2*>(dstSq + (size_t)r * K0C + c4 * 4) = Q;
    }
}

// ---------------------------------------------------------------------------
// Big GEMM: g_full = Xh @ Wh^T over full K=4096. CTA 128x256, warp 64x64.
// 3-stage ring, prefetch distance 2 (distinct buffers mod 3 — safe).
// ---------------------------------------------------------------------------
__global__ __launch_bounds__(256, 1)
void big_gemm()
{
    extern __shared__ __align__(1024) char smem[];
    const uint32_t sbase = smem_u32(smem);
    const int tid  = threadIdx.x;
    const int wid  = tid >> 5;
    const int lane = tid & 31;

    const int bm = blockIdx.y * BM;
    const int bn = blockIdx.x * BN;

    const int warpM = (wid & 1) * 64;
    const int warpN = (wid >> 1) * 64;

    const int subl = lane >> 3;
    const int tr   = lane & 7;
    const int aRow = (subl & 1) * 8 + tr;
    const int aK8  = (subl >> 1);
    const int bRow = (subl >> 1) * 8 + tr;
    const int bK8  = (subl & 1);

    float acc[4][8][4];
    #pragma unroll
    for (int i = 0; i < 4; ++i)
        #pragma unroll
        for (int j = 0; j < 8; ++j)
            #pragma unroll
            for (int q = 0; q < 4; ++q) acc[i][j][q] = 0.0f;

    auto load_chunk = [&](int it, int buf) {
        const __half* Ap = g_Xh + (size_t)bm * K_DIM + it * BK;
        const __half* Bp = g_Wh + (size_t)bn * K_DIM + it * BK;
        const uint32_t aOff = buf * STAGE_BYTES;
        const uint32_t bOff = aOff + STAGE_A;
        #pragma unroll
        for (int l = 0; l < 4; ++l) {                 // A: 1024 16B lines
            int idx = tid + l * 256;
            int r = idx >> 3, c = idx & 7;
            cp_async16(sbase + aOff + SWZ128((uint32_t)(r * 128 + c * 16)),
                       Ap + (size_t)r * K_DIM + c * 8);
        }
        #pragma unroll
        for (int l = 0; l < 8; ++l) {                 // B: 2048 16B lines
            int idx = tid + l * 256;
            int r = idx >> 3, c = idx & 7;
            cp_async16(sbase + bOff + SWZ128((uint32_t)(r * 128 + c * 16)),
                       Bp + (size_t)r * K_DIM + c * 8);
        }
    };

    load_chunk(0, 0); CP_COMMIT();
    load_chunk(1, 1); CP_COMMIT();

    int buf = 0;
    for (int it = 0; it < NCHUNK; ++it) {
        if (it + 2 < NCHUNK) {
            int nb = buf + 2; if (nb >= NSTAGE) nb -= NSTAGE;
            load_chunk(it + 2, nb);
        }
        CP_COMMIT();
        CP_WAIT2();
        __syncthreads();

        const uint32_t aBase = sbase + buf * STAGE_BYTES;
        const uint32_t bBase = aBase + STAGE_A;

        #pragma unroll
        for (int ks = 0; ks < 4; ++ks) {
            uint32_t afrag[4][4];
            #pragma unroll
            for (int mi = 0; mi < 4; ++mi) {
                int row = warpM + mi * 16 + aRow;
                uint32_t byte = (uint32_t)(row * 128) +
                                ((uint32_t)((ks * 2 + aK8) * 16) ^ ((row & 7) * 16));
                ldsm_x4(afrag[mi][0], afrag[mi][1], afrag[mi][2], afrag[mi][3],
                        aBase + byte);
            }
            #pragma unroll
            for (int pr = 0; pr < 4; ++pr) {
                int row = warpN + pr * 16 + bRow;
                uint32_t byte = (uint32_t)(row * 128) +
                                ((uint32_t)((ks * 2 + bK8) * 16) ^ ((row & 7) * 16));
                uint32_t b0, b1, b2, b3;
                ldsm_x4(b0, b1, b2, b3, bBase + byte);
                #pragma unroll
                for (int mi = 0; mi < 4; ++mi) {
                    mma_fp16(acc[mi][pr * 2 + 0], afrag[mi], b0, b1);
                    mma_fp16(acc[mi][pr * 2 + 1], afrag[mi], b2, b3);
                }
            }
        }
        __syncthreads();
        ++buf; if (buf == NSTAGE) buf = 0;
    }

    // Plain stores of raw full sums (no mask read)
    const int mrow = lane >> 2;
    const int ncol = (lane & 3) * 2;
    #pragma unroll
    for (int mi = 0; mi < 4; ++mi) {
        #pragma unroll
        for (int ni = 0; ni < 8; ++ni) {
            const int m = bm + warpM + mi * 16 + mrow;
            const int n = bn + warpN + ni * 8 + ncol;
            size_t o  = (size_t)m * N_DIM + n;
            size_t o2 = o + (size_t)8 * N_DIM;
            float2 v0 = {acc[mi][ni][0], acc[mi][ni][1]};
            float2 v1 = {acc[mi][ni][2], acc[mi][ni][3]};
            *reinterpret_cast<float2*>(&g_full[o])  = v0;
            *reinterpret_cast<float2*>(&g_full[o2]) = v1;
        }
    }
}

// ---------------------------------------------------------------------------
// Gate GEMM: y1h = Xh0@Wh0^T, s2h = Xsq@Wsq^T over K0=256. Classify with band;
// certain -> mask; uncertain -> list for exact fixup. CTA 128x64, warp 32x32.
// FIX vs R6: correct distance-1 double buffer (no overwrite-in-flight race).
// ---------------------------------------------------------------------------
__global__ __launch_bounds__(256, 1)
void gate_gemm()
{
    extern __shared__ __align__(1024) char smem[];
    const uint32_t sbase = smem_u32(smem);
    const int tid  = threadIdx.x;
    const int wid  = tid >> 5;
    const int lane = tid & 31;

    const int bm = blockIdx.y * GBM;
    const int bn = blockIdx.x * GBN;

    const int warpM = (wid & 3) * 32;
    const int warpN = (wid >> 2) * 32;

    const int subl = lane >> 3;
    const int tr   = lane & 7;
    const int aRow = (subl & 1) * 8 + tr;
    const int aK8  = (subl >> 1);
    const int bRow = (subl >> 1) * 8 + tr;
    const int bK8  = (subl & 1);

    float accY[2][4][4], accS[2][4][4];
    #pragma unroll
    for (int i = 0; i < 2; ++i)
        #pragma unroll
        for (int j = 0; j < 4; ++j)
            #pragma unroll
            for (int q = 0; q < 4; ++q) { accY[i][j][q] = 0.0f; accS[i][j][q] = 0.0f; }

    auto load_chunk = [&](int ck, int buf) {
        const __half* Ah = g_Xh  + (size_t)bm * K_DIM + ck * 64;
        const __half* Bh = g_Wh  + (size_t)bn * K_DIM + ck * 64;
        const __half* Aq = g_Xsq + (size_t)bm * K0C   + ck * 64;
        const __half* Bq = g_Wsq + (size_t)bn * K0C   + ck * 64;
        const uint32_t s0 = buf * G_STAGE;
        #pragma unroll
        for (int l = 0; l < 4; ++l) {                 // Ah: 1024 lines
            int idx = tid + l * 256;
            int r = idx >> 3, c = idx & 7;
            cp_async16(sbase + s0 + SWZ128((uint32_t)(r * 128 + c * 16)),
                       Ah + (size_t)r * K_DIM + c * 8);
        }
        #pragma unroll
        for (int l = 0; l < 2; ++l) {                 // Bh: 512 lines
            int idx = tid + l * 256;
            int r = idx >> 3, c = idx & 7;
            cp_async16(sbase + s0 + G_AH + SWZ128((uint32_t)(r * 128 + c * 16)),
                       Bh + (size_t)r * K_DIM + c * 8);
        }
        #pragma unroll
        for (int l = 0; l < 4; ++l) {                 // Asq: 1024 lines
            int idx = tid + l * 256;
            int r = idx >> 3, c = idx & 7;
            cp_async16(sbase + s0 + G_AH + G_BH + SWZ128((uint32_t)(r * 128 + c * 16)),
                       Aq + (size_t)r * K0C + c * 8);
        }
        #pragma unroll
        for (int l = 0; l < 2; ++l) {                 // Bsq: 512 lines
            int idx = tid + l * 256;
            int r = idx >> 3, c = idx & 7;
            cp_async16(sbase + s0 + G_AH + G_BH + G_ASQ + SWZ128((uint32_t)(r * 128 + c * 16)),
                       Bq + (size_t)r * K0C + c * 8);
        }
    };

    load_chunk(0, 0); CP_COMMIT();

    #pragma unroll
    for (int ck = 0; ck < 4; ++ck) {
        // Prefetch next chunk into the OTHER buffer (distance 1, no overlap
        // with the buffer being consumed this iteration).
        if (ck + 1 < 4) { load_chunk(ck + 1, (ck + 1) & 1); CP_COMMIT(); }
        if (ck + 1 < 4) { CP_WAIT1(); } else { CP_WAIT0(); }
        __syncthreads();

        const uint32_t hA = sbase + (ck & 1) * G_STAGE;
        const uint32_t hB = hA + G_AH;
        const uint32_t qA = hB + G_BH;
        const uint32_t qB = qA + G_ASQ;

        #pragma unroll
        for (int ks = 0; ks < 4; ++ks) {
            uint32_t ah[2][4], aq[2][4];
            #pragma unroll
            for (int mi = 0; mi < 2; ++mi) {
                int row = warpM + mi * 16 + aRow;
                uint32_t byte = (uint32_t)(row * 128) +
                                ((uint32_t)((ks * 2 + aK8) * 16) ^ ((row & 7) * 16));
                ldsm_x4(ah[mi][0], ah[mi][1], ah[mi][2], ah[mi][3], hA + byte);
                ldsm_x4(aq[mi][0], aq[mi][1], aq[mi][2], aq[mi][3], qA + byte);
            }
            #pragma unroll
            for (int pr = 0; pr < 2; ++pr) {
                int row = warpN + pr * 16 + bRow;
                uint32_t byte = (uint32_t)(row * 128) +
                                ((uint32_t)((ks * 2 + bK8) * 16) ^ ((row & 7) * 16));
                uint32_t h0, h1, h2, h3, q0, q1, q2, q3;
                ldsm_x4(h0, h1, h2, h3, hB + byte);
                ldsm_x4(q0, q1, q2, q3, qB + byte);
                #pragma unroll
                for (int mi = 0; mi < 2; ++mi) {
                    mma_fp16(accY[mi][pr * 2 + 0], ah[mi], h0, h1);
                    mma_fp16(accY[mi][pr * 2 + 1], ah[mi], h2, h3);
                    mma_fp16(accS[mi][pr * 2 + 0], aq[mi], q0, q1);
                    mma_fp16(accS[mi][pr * 2 + 1], aq[mi], q2, q3);
                }
            }
        }
        // All reads of this buffer done before next iteration's prefetch may
        // overwrite it.
        __syncthreads();
    }

    // Epilogue: classify each element
    const int mrow = lane >> 2;
    const int ncol = (lane & 3) * 2;
    #pragma unroll
    for (int mi = 0; mi < 2; ++mi) {
        #pragma unroll
        for (int ni = 0; ni < 4; ++ni) {
            #pragma unroll
            for (int h = 0; h < 2; ++h) {             // row halves (+0, +8)
                const int m = bm + warpM + mi * 16 + mrow + h * 8;
                const int n = bn + warpN + ni * 8 + ncol;
                #pragma unroll
                for (int q = 0; q < 2; ++q) {
                    float y = accY[mi][ni][h * 2 + q];
                    float s = accS[mi][ni][h * 2 + q];
                    float denom = sqrtf(s * (1.0f / (SQS * SQS * 256.0f)) + EPS);
                    float t = fabsf(y) / fmaxf(denom, EPS);
                    size_t o = (size_t)m * N_DIM + n + q;
                    if (t < TAU - BAND) {
                        g_mask[o] = 0;
                    } else if (t > TAU + BAND) {
                        g_mask[o] = 1;
                    } else {
                        g_mask[o] = 1;                 // placeholder; fixup overwrites
                        int idx = atomicAdd(&g_count, 1);
                        if (idx < LIST_CAP)
                            g_list[idx] = ((uint32_t)m << 12) | (uint32_t)(n + q);
                    }
                }
            }
        }
    }
}

// ---------------------------------------------------------------------------
// Fixup: exact fp32 recompute of y1/s2 for uncertain elements (1 warp each).
// ---------------------------------------------------------------------------
__global__ __launch_bounds__(256)
void fixup_kernel(const float* __restrict__ X, const float* __restrict__ W)
{
    const int lane = threadIdx.x & 31;
    const int wglobal = (blockIdx.x * 256 + threadIdx.x) >> 5;
    const int nwarps = (gridDim.x * 256) >> 5;
    int total = g_count; if (total > LIST_CAP) total = LIST_CAP;

    for (int i = wglobal; i < total; i += nwarps) {
        uint32_t p = g_list[i];
        int m = p >> 12;
        int n = p & 4095;
        const float* xr = X + (size_t)m * K_DIM;
        const float* wr = W + (size_t)n * K_DIM;
        float y = 0.0f, s = 0.0f;
        #pragma unroll
        for (int j = 0; j < 2; ++j) {
            float4 a = *reinterpret_cast<const float4*>(xr + lane * 8 + j * 4);
            float4 b = *reinterpret_cast<const float4*>(wr + lane * 8 + j * 4);
            y = fmaf(a.x, b.x, y); y = fmaf(a.y, b.y, y);
            y = fmaf(a.z, b.z, y); y = fmaf(a.w, b.w, y);
            float px = a.x * b.x, py = a.y * b.y, pz = a.z * b.z, pw = a.w * b.w;
            s = fmaf(px, px, s); s = fmaf(py, py, s);
            s = fmaf(pz, pz, s); s = fmaf(pw, pw, s);
        }
        #pragma unroll
        for (int off = 16; off > 0; off >>= 1) {
            y += __shfl_xor_sync(0xFFFFFFFF, y, off);
            s += __shfl_xor_sync(0xFFFFFFFF, s, off);
        }
        if (lane == 0) {
            float denom = sqrtf(s * (1.0f / 256.0f) + EPS);
            float t = fabsf(y) / fmaxf(denom, EPS);
            g_mask[(size_t)m * N_DIM + n] = (t < TAU) ? 0 : 1;
        }
    }
}

// ---------------------------------------------------------------------------
// Merge: Out = bias + (mask ? g_full : 0)
// ---------------------------------------------------------------------------
__global__ __launch_bounds__(256)
void merge_kernel(float* __restrict__ Out, const float* __restrict__ Bv)
{
    size_t i4 = (size_t)blockIdx.x * 256 + threadIdx.x;   // one float4 per thread
    const uchar4 m = reinterpret_cast<const uchar4*>(g_mask)[i4];
    const int nb = ((int)(i4 & 1023)) * 4;
    const float4 b = *reinterpret_cast<const float4*>(Bv + nb);
    const float4 t = reinterpret_cast<const float4*>(g_full)[i4];
    float4 o;
    o.x = b.x + (m.x ? t.x : 0.0f);
    o.y = b.y + (m.y ? t.y : 0.0f);
    o.z = b.z + (m.z ? t.z : 0.0f);
    o.w = b.w + (m.w ? t.w : 0.0f);
    reinterpret_cast<float4*>(Out)[i4] = o;
}

// ---------------------------------------------------------------------------
extern "C" void kernel_launch(void* const* d_in, const int* in_sizes, int n_in,
                              void* d_out, int out_size)
{
    const float* x  = (const float*)d_in[0];   // [8192, 4096]
    const float* w  = (const float*)d_in[1];   // [4096, 4096]
    const float* bv = (const float*)d_in[2];   // [4096]
    float* out      = (float*)d_out;           // [8192, 4096]
    (void)in_sizes; (void)n_in; (void)out_size;

    cudaFuncSetAttribute(big_gemm,
                         cudaFuncAttributeMaxDynamicSharedMemorySize, SMEM_BIG);
    cudaFuncSetAttribute(gate_gemm,
                         cudaFuncAttributeMaxDynamicSharedMemorySize, SMEM_GATE);

    __half *xh, *wh, *xq, *wq;
    cudaGetSymbolAddress((void**)&xh, g_Xh);
    cudaGetSymbolAddress((void**)&wh, g_Wh);
    cudaGetSymbolAddress((void**)&xq, g_Xsq);
    cudaGetSymbolAddress((void**)&wq, g_Wsq);

    zero_count<<<1, 1>>>();
    conv_kernel<<<M_DIM * (K_DIM / 4) / 256, 256>>>(x, xh, xq, 1.0f, M_DIM);
    conv_kernel<<<N_DIM * (K_DIM / 4) / 256, 256>>>(w, wh, wq, SQS, N_DIM);

    // Gate (classify + uncertain list), then exact fixup
    dim3 gateGrid(N_DIM / GBN, M_DIM / GBM);   // (64, 64)
    gate_gemm<<<gateGrid, 256, SMEM_GATE>>>();
    fixup_kernel<<<512, 256>>>(x, w);

    // Full-K value GEMM on tensor pipe
    dim3 bigGrid(N_DIM / BN, M_DIM / BM);      // (16, 64)
    big_gemm<<<bigGrid, 256, SMEM_BIG>>>();

    // Final compose
    merge_kernel<<<(int)(((size_t)M_DIM * N_DIM / 4) / 256), 256>>>(out, bv);
}

// round 8
// speedup vs baseline: 1.4716x; 1.0680x over previous
#include <cuda_runtime.h>
#include <cuda_fp16.h>
#include <cstdint>

// ---------------------------------------------------------------------------
// Problem shape (fixed by setup_inputs: B=4, S=2048, K=4096, N=4096)
// ---------------------------------------------------------------------------
namespace {
constexpr int M_DIM = 8192;
constexpr int N_DIM = 4096;
constexpr int K_DIM = 4096;
constexpr int K0C   = 256;
constexpr float TAU = 3.0f;
constexpr float EPS = 1e-6f;
constexpr float BAND = 0.05f;              // gate uncertainty band on t (~8 sigma)
constexpr float SQS  = 50.0f;              // w-square prescale; s2 = accS/(50^2 * 256)

// Big GEMM tiling: CTA 128x256, 8 warps (2m x 4n), warp 64x64, BK=64
constexpr int BM = 128;
constexpr int BN = 256;
constexpr int BK = 64;
constexpr int NCHUNK = K_DIM / BK;          // 64
constexpr int STAGE_A = BM * 128;           // 16384
constexpr int STAGE_B = BN * 128;           // 32768
constexpr int STAGE_BYTES = STAGE_A + STAGE_B;     // 49152
constexpr int NSTAGE = 3;
constexpr int SMEM_BIG = NSTAGE * STAGE_BYTES;     // 147456

// Gate GEMM tiling: CTA 128x128, 16 warps (4m x 4n), warp 32x32, K=256
constexpr int GBM = 128;
constexpr int GBN = 128;
constexpr int G_AH  = GBM * 128;            // 16384
constexpr int G_BH  = GBN * 128;            // 16384
constexpr int G_ASQ = G_AH;                 // 16384
constexpr int G_BSQ = G_BH;                 // 16384
constexpr int G_STAGE = G_AH + G_BH + G_ASQ + G_BSQ;  // 65536
constexpr int SMEM_GATE = 2 * G_STAGE;      // 131072

constexpr int LIST_CAP = 1 << 25;           // 33.5M (full-size safe)
}

// ---------------------------------------------------------------------------
// Device scratch (static; no dynamic allocation allowed)
// ---------------------------------------------------------------------------
__device__ __align__(1024) unsigned char g_mask[(size_t)M_DIM * N_DIM];
__device__ __align__(1024) __half        g_Xh[(size_t)M_DIM * K_DIM];
__device__ __align__(1024) __half        g_Wh[(size_t)N_DIM * K_DIM];
__device__ __align__(1024) __half        g_Xsq[(size_t)M_DIM * K0C];
__device__ __align__(1024) __half        g_Wsq[(size_t)N_DIM * K0C];
__device__ __align__(1024) uint32_t      g_list[LIST_CAP];
__device__ int                           g_count;

// ---------------------------------------------------------------------------
// Helpers (base-ISA only: cp.async / ldmatrix / mma.sync)
// ---------------------------------------------------------------------------
__device__ __forceinline__ uint32_t smem_u32(const void* p) {
    uint32_t a;
    asm("{ .reg .u64 t; cvta.to.shared.u64 t, %1; cvt.u32.u64 %0, t; }" : "=r"(a) : "l"(p));
    return a;
}
#define SWZ128(off) ((off) ^ (((off) >> 3) & 0x70))

__device__ __forceinline__ void cp_async16(uint32_t dst, const void* src) {
    asm volatile("cp.async.cg.shared.global [%0], [%1], 16;"
                 :: "r"(dst), "l"(__cvta_generic_to_global(src)) : "memory");
}
#define CP_COMMIT() asm volatile("cp.async.commit_group;" ::: "memory")
#define CP_WAIT0()  asm volatile("cp.async.wait_group 0;" ::: "memory")
#define CP_WAIT1()  asm volatile("cp.async.wait_group 1;" ::: "memory")
#define CP_WAIT2()  asm volatile("cp.async.wait_group 2;" ::: "memory")

__device__ __forceinline__ void ldsm_x4(uint32_t& r0, uint32_t& r1, uint32_t& r2,
                                        uint32_t& r3, uint32_t addr) {
    asm volatile("ldmatrix.sync.aligned.m8n8.x4.shared.b16 {%0,%1,%2,%3}, [%4];"
                 : "=r"(r0), "=r"(r1), "=r"(r2), "=r"(r3) : "r"(addr));
}
__device__ __forceinline__ void mma_fp16(float* c, const uint32_t* a,
                                         uint32_t b0, uint32_t b1) {
    asm volatile("mma.sync.aligned.m16n8k16.row.col.f32.f16.f16.f32 "
                 "{%0,%1,%2,%3}, {%4,%5,%6,%7}, {%8,%9}, {%0,%1,%2,%3};"
                 : "+f"(c[0]), "+f"(c[1]), "+f"(c[2]), "+f"(c[3])
                 : "r"(a[0]), "r"(a[1]), "r"(a[2]), "r"(a[3]), "r"(b0), "r"(b1));
}

// ---------------------------------------------------------------------------
// Zero the uncertain-list counter (determinism across graph replays)
// ---------------------------------------------------------------------------
__global__ void zero_count() { g_count = 0; }

// ---------------------------------------------------------------------------
// Convert: fp32 [rows x 4096] -> fp16 full + fp16 squares (first 256 cols)
// ---------------------------------------------------------------------------
__global__ __launch_bounds__(256)
void conv_kernel(const float* __restrict__ src, __half* __restrict__ dstH,
                 __half* __restrict__ dstSq, float sqscale, int rows)
{
    int idx = blockIdx.x * 256 + threadIdx.x;     // one float4 per thread
    if (idx >= rows * (K_DIM / 4)) return;
    int r  = idx >> 10;                            // / 1024
    int c4 = idx & 1023;
    float4 v = *reinterpret_cast<const float4*>(src + (size_t)r * K_DIM + c4 * 4);
    __half2 h0 = __floats2half2_rn(v.x, v.y);
    __half2 h1 = __floats2half2_rn(v.z, v.w);
    uint2 H;
    H.x = *reinterpret_cast<uint32_t*>(&h0);
    H.y = *reinterpret_cast<uint32_t*>(&h1);
    *reinterpret_cast<uint2*>(dstH + (size_t)r * K_DIM + c4 * 4) = H;
    if (c4 < K0C / 4) {
        float sx = v.x * sqscale, sy = v.y * sqscale;
        float sz = v.z * sqscale, sw = v.w * sqscale;
        __half2 q0 = __floats2half2_rn(sx * sx, sy * sy);
        __half2 q1 = __floats2half2_rn(sz * sz, sw * sw);
        uint2 Q;
        Q.x = *reinterpret_cast<uint32_t*>(&q0);
        Q.y = *reinterpret_cast<uint32_t*>(&q1);
        *reinterpret_cast<uint2*>(dstSq + (size_t)r * K0C + c4 * 4) = Q;
    }
}

// ---------------------------------------------------------------------------
// Big GEMM + fused merge: Out = bias + (mask ? Xh@Wh^T : 0) over full K=4096.
// CTA 128x256, warp 64x64, 3-stage ring (distance 2, distinct mod-3 buffers).
// Requires g_mask finalized (gate+fixup run before this kernel).
// ---------------------------------------------------------------------------
__global__ __launch_bounds__(256, 1)
void big_gemm(float* __restrict__ Out, const float* __restrict__ Bv)
{
    extern __shared__ __align__(1024) char smem[];
    const uint32_t sbase = smem_u32(smem);
    const int tid  = threadIdx.x;
    const int wid  = tid >> 5;
    const int lane = tid & 31;

    const int bm = blockIdx.y * BM;
    const int bn = blockIdx.x * BN;

    const int warpM = (wid & 1) * 64;
    const int warpN = (wid >> 1) * 64;

    const int subl = lane >> 3;
    const int tr   = lane & 7;
    const int aRow = (subl & 1) * 8 + tr;
    const int aK8  = (subl >> 1);
    const int bRow = (subl >> 1) * 8 + tr;
    const int bK8  = (subl & 1);

    float acc[4][8][4];
    #pragma unroll
    for (int i = 0; i < 4; ++i)
        #pragma unroll
        for (int j = 0; j < 8; ++j)
            #pragma unroll
            for (int q = 0; q < 4; ++q) acc[i][j][q] = 0.0f;

    auto load_chunk = [&](int it, int buf) {
        const __half* Ap = g_Xh + (size_t)bm * K_DIM + it * BK;
        const __half* Bp = g_Wh + (size_t)bn * K_DIM + it * BK;
        const uint32_t aOff = buf * STAGE_BYTES;
        const uint32_t bOff = aOff + STAGE_A;
        #pragma unroll
        for (int l = 0; l < 4; ++l) {                 // A: 1024 16B lines
            int idx = tid + l * 256;
            int r = idx >> 3, c = idx & 7;
            cp_async16(sbase + aOff + SWZ128((uint32_t)(r * 128 + c * 16)),
                       Ap + (size_t)r * K_DIM + c * 8);
        }
        #pragma unroll
        for (int l = 0; l < 8; ++l) {                 // B: 2048 16B lines
            int idx = tid + l * 256;
            int r = idx >> 3, c = idx & 7;
            cp_async16(sbase + bOff + SWZ128((uint32_t)(r * 128 + c * 16)),
                       Bp + (size_t)r * K_DIM + c * 8);
        }
    };

    load_chunk(0, 0); CP_COMMIT();
    load_chunk(1, 1); CP_COMMIT();

    int buf = 0;
    for (int it = 0; it < NCHUNK; ++it) {
        if (it + 2 < NCHUNK) {
            int nb = buf + 2; if (nb >= NSTAGE) nb -= NSTAGE;
            load_chunk(it + 2, nb);
        }
        CP_COMMIT();
        CP_WAIT2();
        __syncthreads();

        const uint32_t aBase = sbase + buf * STAGE_BYTES;
        const uint32_t bBase = aBase + STAGE_A;

        #pragma unroll
        for (int ks = 0; ks < 4; ++ks) {
            uint32_t afrag[4][4];
            #pragma unroll
            for (int mi = 0; mi < 4; ++mi) {
                int row = warpM + mi * 16 + aRow;
                uint32_t byte = (uint32_t)(row * 128) +
                                ((uint32_t)((ks * 2 + aK8) * 16) ^ ((row & 7) * 16));
                ldsm_x4(afrag[mi][0], afrag[mi][1], afrag[mi][2], afrag[mi][3],
                        aBase + byte);
            }
            #pragma unroll
            for (int pr = 0; pr < 4; ++pr) {
                int row = warpN + pr * 16 + bRow;
                uint32_t byte = (uint32_t)(row * 128) +
                                ((uint32_t)((ks * 2 + bK8) * 16) ^ ((row & 7) * 16));
                uint32_t b0, b1, b2, b3;
                ldsm_x4(b0, b1, b2, b3, bBase + byte);
                #pragma unroll
                for (int mi = 0; mi < 4; ++mi) {
                    mma_fp16(acc[mi][pr * 2 + 0], afrag[mi], b0, b1);
                    mma_fp16(acc[mi][pr * 2 + 1], afrag[mi], b2, b3);
                }
            }
        }
        __syncthreads();
        ++buf; if (buf == NSTAGE) buf = 0;
    }

    // Fused merge epilogue: Out = bias + (mask ? acc : 0)
    const int mrow = lane >> 2;
    const int ncol = (lane & 3) * 2;
    #pragma unroll
    for (int mi = 0; mi < 4; ++mi) {
        #pragma unroll
        for (int ni = 0; ni < 8; ++ni) {
            const int m = bm + warpM + mi * 16 + mrow;
            const int n = bn + warpN + ni * 8 + ncol;
            const float bx = __ldg(Bv + n);
            const float by = __ldg(Bv + n + 1);
            size_t o  = (size_t)m * N_DIM + n;
            size_t o2 = o + (size_t)8 * N_DIM;
            float2 v0, v1;
            v0.x = bx + (g_mask[o]      ? acc[mi][ni][0] : 0.0f);
            v0.y = by + (g_mask[o + 1]  ? acc[mi][ni][1] : 0.0f);
            v1.x = bx + (g_mask[o2]     ? acc[mi][ni][2] : 0.0f);
            v1.y = by + (g_mask[o2 + 1] ? acc[mi][ni][3] : 0.0f);
            *reinterpret_cast<float2*>(&Out[o])  = v0;
            *reinterpret_cast<float2*>(&Out[o2]) = v1;
        }
    }
}

// ---------------------------------------------------------------------------
// Gate GEMM: y1h = Xh0@Wh0^T, s2h = Xsq@Wsq^T over K0=256. Classify with band;
// certain -> mask; uncertain -> list for exact fixup.
// CTA 128x128, 512 threads (16 warps, 4m x 4n), warp 32x32, distance-1 ring.
// ---------------------------------------------------------------------------
__global__ __launch_bounds__(512, 1)
void gate_gemm()
{
    extern __shared__ __align__(1024) char smem[];
    const uint32_t sbase = smem_u32(smem);
    const int tid  = threadIdx.x;
    const int wid  = tid >> 5;
    const int lane = tid & 31;

    const int bm = blockIdx.y * GBM;
    const int bn = blockIdx.x * GBN;

    const int warpM = (wid & 3) * 32;     // 0..96
    const int warpN = (wid >> 2) * 32;    // 0..96

    const int subl = lane >> 3;
    const int tr   = lane & 7;
    const int aRow = (subl & 1) * 8 + tr;
    const int aK8  = (subl >> 1);
    const int bRow = (subl >> 1) * 8 + tr;
    const int bK8  = (subl & 1);

    float accY[2][4][4], accS[2][4][4];
    #pragma unroll
    for (int i = 0; i < 2; ++i)
        #pragma unroll
        for (int j = 0; j < 4; ++j)
            #pragma unroll
            for (int q = 0; q < 4; ++q) { accY[i][j][q] = 0.0f; accS[i][j][q] = 0.0f; }

    auto load_chunk = [&](int ck, int buf) {
        const __half* Ah = g_Xh  + (size_t)bm * K_DIM + ck * 64;
        const __half* Bh = g_Wh  + (size_t)bn * K_DIM + ck * 64;
        const __half* Aq = g_Xsq + (size_t)bm * K0C   + ck * 64;
        const __half* Bq = g_Wsq + (size_t)bn * K0C   + ck * 64;
        const uint32_t s0 = buf * G_STAGE;
        // Each array: 1024 16B lines, 512 threads -> 2 lines/thread/array
        #pragma unroll
        for (int l = 0; l < 2; ++l) {
            int idx = tid + l * 512;
            int r = idx >> 3, c = idx & 7;
            uint32_t sw = SWZ128((uint32_t)(r * 128 + c * 16));
            cp_async16(sbase + s0 + sw,                 Ah + (size_t)r * K_DIM + c * 8);
            cp_async16(sbase + s0 + G_AH + sw,          Bh + (size_t)r * K_DIM + c * 8);
            cp_async16(sbase + s0 + G_AH + G_BH + sw,   Aq + (size_t)r * K0C + c * 8);
            cp_async16(sbase + s0 + G_AH + G_BH + G_ASQ + sw,
                       Bq + (size_t)r * K0C + c * 8);
        }
    };

    load_chunk(0, 0); CP_COMMIT();

    #pragma unroll
    for (int ck = 0; ck < 4; ++ck) {
        if (ck + 1 < 4) { load_chunk(ck + 1, (ck + 1) & 1); CP_COMMIT(); }
        if (ck + 1 < 4) { CP_WAIT1(); } else { CP_WAIT0(); }
        __syncthreads();

        const uint32_t hA = sbase + (ck & 1) * G_STAGE;
        const uint32_t hB = hA + G_AH;
        const uint32_t qA = hB + G_BH;
        const uint32_t qB = qA + G_ASQ;

        #pragma unroll
        for (int ks = 0; ks < 4; ++ks) {
            uint32_t ah[2][4], aq[2][4];
            #pragma unroll
            for (int mi = 0; mi < 2; ++mi) {
                int row = warpM + mi * 16 + aRow;
                uint32_t byte = (uint32_t)(row * 128) +
                                ((uint32_t)((ks * 2 + aK8) * 16) ^ ((row & 7) * 16));
                ldsm_x4(ah[mi][0], ah[mi][1], ah[mi][2], ah[mi][3], hA + byte);
                ldsm_x4(aq[mi][0], aq[mi][1], aq[mi][2], aq[mi][3], qA + byte);
            }
            #pragma unroll
            for (int pr = 0; pr < 2; ++pr) {
                int row = warpN + pr * 16 + bRow;
                uint32_t byte = (uint32_t)(row * 128) +
                                ((uint32_t)((ks * 2 + bK8) * 16) ^ ((row & 7) * 16));
                uint32_t h0, h1, h2, h3, q0, q1, q2, q3;
                ldsm_x4(h0, h1, h2, h3, hB + byte);
                ldsm_x4(q0, q1, q2, q3, qB + byte);
                #pragma unroll
                for (int mi = 0; mi < 2; ++mi) {
                    mma_fp16(accY[mi][pr * 2 + 0], ah[mi], h0, h1);
                    mma_fp16(accY[mi][pr * 2 + 1], ah[mi], h2, h3);
                    mma_fp16(accS[mi][pr * 2 + 0], aq[mi], q0, q1);
                    mma_fp16(accS[mi][pr * 2 + 1], aq[mi], q2, q3);
                }
            }
        }
        __syncthreads();    // all reads done before next prefetch overwrites
    }

    // Epilogue: classify each element
    const int mrow = lane >> 2;
    const int ncol = (lane & 3) * 2;
    #pragma unroll
    for (int mi = 0; mi < 2; ++mi) {
        #pragma unroll
        for (int ni = 0; ni < 4; ++ni) {
            #pragma unroll
            for (int h = 0; h < 2; ++h) {             // row halves (+0, +8)
                const int m = bm + warpM + mi * 16 + mrow + h * 8;
                const int n = bn + warpN + ni * 8 + ncol;
                #pragma unroll
                for (int q = 0; q < 2; ++q) {
                    float y = accY[mi][ni][h * 2 + q];
                    float s = accS[mi][ni][h * 2 + q];
                    float denom = sqrtf(s * (1.0f / (SQS * SQS * 256.0f)) + EPS);
                    float t = fabsf(y) / fmaxf(denom, EPS);
                    size_t o = (size_t)m * N_DIM + n + q;
                    if (t < TAU - BAND) {
                        g_mask[o] = 0;
                    } else if (t > TAU + BAND) {
                        g_mask[o] = 1;
                    } else {
                        g_mask[o] = 1;                 // placeholder; fixup overwrites
                        int idx = atomicAdd(&g_count, 1);
                        if (idx < LIST_CAP)
                            g_list[idx] = ((uint32_t)m << 12) | (uint32_t)(n + q);
                    }
                }
            }
        }
    }
}

// ---------------------------------------------------------------------------
// Fixup: exact fp32 recompute of y1/s2 for uncertain elements (1 warp each).
// ---------------------------------------------------------------------------
__global__ __launch_bounds__(256)
void fixup_kernel(const float* __restrict__ X, const float* __restrict__ W)
{
    const int lane = threadIdx.x & 31;
    const int wglobal = (blockIdx.x * 256 + threadIdx.x) >> 5;
    const int nwarps = (gridDim.x * 256) >> 5;
    int total = g_count; if (total > LIST_CAP) total = LIST_CAP;

    for (int i = wglobal; i < total; i += nwarps) {
        uint32_t p = g_list[i];
        int m = p >> 12;
        int n = p & 4095;
        const float* xr = X + (size_t)m * K_DIM;
        const float* wr = W + (size_t)n * K_DIM;
        float y = 0.0f, s = 0.0f;
        #pragma unroll
        for (int j = 0; j < 2; ++j) {
            float4 a = *reinterpret_cast<const float4*>(xr + lane * 8 + j * 4);
            float4 b = *reinterpret_cast<const float4*>(wr + lane * 8 + j * 4);
            y = fmaf(a.x, b.x, y); y = fmaf(a.y, b.y, y);
            y = fmaf(a.z, b.z, y); y = fmaf(a.w, b.w, y);
            float px = a.x * b.x, py = a.y * b.y, pz = a.z * b.z, pw = a.w * b.w;
            s = fmaf(px, px, s); s = fmaf(py, py, s);
            s = fmaf(pz, pz, s); s = fmaf(pw, pw, s);
        }
        #pragma unroll
        for (int off = 16; off > 0; off >>= 1) {
            y += __shfl_xor_sync(0xFFFFFFFF, y, off);
            s += __shfl_xor_sync(0xFFFFFFFF, s, off);
        }
        if (lane == 0) {
            float denom = sqrtf(s * (1.0f / 256.0f) + EPS);
            float t = fabsf(y) / fmaxf(denom, EPS);
            g_mask[(size_t)m * N_DIM + n] = (t < TAU) ? 0 : 1;
        }
    }
}

// ---------------------------------------------------------------------------
extern "C" void kernel_launch(void* const* d_in, const int* in_sizes, int n_in,
                              void* d_out, int out_size)
{
    const float* x  = (const float*)d_in[0];   // [8192, 4096]
    const float* w  = (const float*)d_in[1];   // [4096, 4096]
    const float* bv = (const float*)d_in[2];   // [4096]
    float* out      = (float*)d_out;           // [8192, 4096]
    (void)in_sizes; (void)n_in; (void)out_size;

    cudaFuncSetAttribute(big_gemm,
                         cudaFuncAttributeMaxDynamicSharedMemorySize, SMEM_BIG);
    cudaFuncSetAttribute(gate_gemm,
                         cudaFuncAttributeMaxDynamicSharedMemorySize, SMEM_GATE);

    __half *xh, *wh, *xq, *wq;
    cudaGetSymbolAddress((void**)&xh, g_Xh);
    cudaGetSymbolAddress((void**)&wh, g_Wh);
    cudaGetSymbolAddress((void**)&xq, g_Xsq);
    cudaGetSymbolAddress((void**)&wq, g_Wsq);

    zero_count<<<1, 1>>>();
    conv_kernel<<<M_DIM * (K_DIM / 4) / 256, 256>>>(x, xh, xq, 1.0f, M_DIM);
    conv_kernel<<<N_DIM * (K_DIM / 4) / 256, 256>>>(w, wh, wq, SQS, N_DIM);

    // Gate (classify + uncertain list), then exact fixup -> mask final
    dim3 gateGrid(N_DIM / GBN, M_DIM / GBM);   // (32, 64)
    gate_gemm<<<gateGrid, 512, SMEM_GATE>>>();
    fixup_kernel<<<512, 256>>>(x, w);

    // Full-K value GEMM with fused mask+bias epilogue
    dim3 bigGrid(N_DIM / BN, M_DIM / BM);      // (16, 64)
    big_gemm<<<bigGrid, 256, SMEM_BIG>>>(out, bv);
}

// round 9
// speedup vs baseline: 1.5086x; 1.0251x over previous
#include <cuda_runtime.h>
#include <cuda_fp16.h>
#include <cstdint>

// ---------------------------------------------------------------------------
// Problem shape (fixed by setup_inputs: B=4, S=2048, K=4096, N=4096)
// ---------------------------------------------------------------------------
namespace {
constexpr int M_DIM = 8192;
constexpr int N_DIM = 4096;
constexpr int K_DIM = 4096;
constexpr int K0C   = 256;
constexpr float TAU = 3.0f;
constexpr float EPS = 1e-6f;
constexpr float BAND = 0.05f;              // gate uncertainty band on t (~8 sigma)
constexpr float SQS  = 50.0f;              // w-square prescale; s2 = accS/(50^2 * 256)

// Big GEMM tiling: CTA 128x256, 8 warps (2m x 4n), warp 64x64, BK=64
constexpr int BM = 128;
constexpr int BN = 256;
constexpr int BK = 64;
constexpr int NCHUNK = K_DIM / BK;          // 64
constexpr int STAGE_A = BM * 128;           // 16384
constexpr int STAGE_B = BN * 128;           // 32768
constexpr int STAGE_BYTES = STAGE_A + STAGE_B;     // 49152
constexpr int NSTAGE = 4;
constexpr int SMEM_BIG = NSTAGE * STAGE_BYTES;     // 196608

// Gate GEMM tiling: CTA 128x64, 256 threads (8 warps, 4m x 2n), warp 32x32
constexpr int GBM = 128;
constexpr int GBN = 64;
constexpr int G_AH  = GBM * 128;            // 16384
constexpr int G_BH  = GBN * 128;            // 8192
constexpr int G_ASQ = G_AH;                 // 16384
constexpr int G_BSQ = G_BH;                 // 8192
constexpr int G_STAGE = G_AH + G_BH + G_ASQ + G_BSQ;  // 49152
constexpr int SMEM_GATE = 2 * G_STAGE;      // 98304 -> 2 CTAs/SM

constexpr int LIST_CAP = 1 << 25;           // 33.5M (full-size safe)
}

// ---------------------------------------------------------------------------
// Device scratch (static; no dynamic allocation allowed)
// ---------------------------------------------------------------------------
__device__ __align__(1024) unsigned char g_mask[(size_t)M_DIM * N_DIM];
__device__ __align__(1024) __half        g_Xh[(size_t)M_DIM * K_DIM];
__device__ __align__(1024) __half        g_Wh[(size_t)N_DIM * K_DIM];
__device__ __align__(1024) __half        g_Xsq[(size_t)M_DIM * K0C];
__device__ __align__(1024) __half        g_Wsq[(size_t)N_DIM * K0C];
__device__ __align__(1024) uint32_t      g_list[LIST_CAP];
__device__ int                           g_count;

// ---------------------------------------------------------------------------
// Helpers (base-ISA only: cp.async / ldmatrix / mma.sync)
// ---------------------------------------------------------------------------
__device__ __forceinline__ uint32_t smem_u32(const void* p) {
    uint32_t a;
    asm("{ .reg .u64 t; cvta.to.shared.u64 t, %1; cvt.u32.u64 %0, t; }" : "=r"(a) : "l"(p));
    return a;
}
#define SWZ128(off) ((off) ^ (((off) >> 3) & 0x70))

__device__ __forceinline__ void cp_async16(uint32_t dst, const void* src) {
    asm volatile("cp.async.cg.shared.global [%0], [%1], 16;"
                 :: "r"(dst), "l"(__cvta_generic_to_global(src)) : "memory");
}
#define CP_COMMIT() asm volatile("cp.async.commit_group;" ::: "memory")
#define CP_WAIT0()  asm volatile("cp.async.wait_group 0;" ::: "memory")
#define CP_WAIT1()  asm volatile("cp.async.wait_group 1;" ::: "memory")
#define CP_WAIT3()  asm volatile("cp.async.wait_group 3;" ::: "memory")

__device__ __forceinline__ void ldsm_x4(uint32_t& r0, uint32_t& r1, uint32_t& r2,
                                        uint32_t& r3, uint32_t addr) {
    asm volatile("ldmatrix.sync.aligned.m8n8.x4.shared.b16 {%0,%1,%2,%3}, [%4];"
                 : "=r"(r0), "=r"(r1), "=r"(r2), "=r"(r3) : "r"(addr));
}
__device__ __forceinline__ void mma_fp16(float* c, const uint32_t* a,
                                         uint32_t b0, uint32_t b1) {
    asm volatile("mma.sync.aligned.m16n8k16.row.col.f32.f16.f16.f32 "
                 "{%0,%1,%2,%3}, {%4,%5,%6,%7}, {%8,%9}, {%0,%1,%2,%3};"
                 : "+f"(c[0]), "+f"(c[1]), "+f"(c[2]), "+f"(c[3])
                 : "r"(a[0]), "r"(a[1]), "r"(a[2]), "r"(a[3]), "r"(b0), "r"(b1));
}

// ---------------------------------------------------------------------------
// Zero the uncertain-list counter (determinism across graph replays)
// ---------------------------------------------------------------------------
__global__ void zero_count() { g_count = 0; }

// ---------------------------------------------------------------------------
// Convert: fp32 [rows x 4096] -> fp16 full + fp16 squares (first 256 cols)
// ---------------------------------------------------------------------------
__global__ __launch_bounds__(256)
void conv_kernel(const float* __restrict__ src, __half* __restrict__ dstH,
                 __half* __restrict__ dstSq, float sqscale, int rows)
{
    int idx = blockIdx.x * 256 + threadIdx.x;     // one float4 per thread
    if (idx >= rows * (K_DIM / 4)) return;
    int r  = idx >> 10;                            // / 1024
    int c4 = idx & 1023;
    float4 v = *reinterpret_cast<const float4*>(src + (size_t)r * K_DIM + c4 * 4);
    __half2 h0 = __floats2half2_rn(v.x, v.y);
    __half2 h1 = __floats2half2_rn(v.z, v.w);
    uint2 H;
    H.x = *reinterpret_cast<uint32_t*>(&h0);
    H.y = *reinterpret_cast<uint32_t*>(&h1);
    *reinterpret_cast<uint2*>(dstH + (size_t)r * K_DIM + c4 * 4) = H;
    if (c4 < K0C / 4) {
        float sx = v.x * sqscale, sy = v.y * sqscale;
        float sz = v.z * sqscale, sw = v.w * sqscale;
        __half2 q0 = __floats2half2_rn(sx * sx, sy * sy);
        __half2 q1 = __floats2half2_rn(sz * sz, sw * sw);
        uint2 Q;
        Q.x = *reinterpret_cast<uint32_t*>(&q0);
        Q.y = *reinterpret_cast<uint32_t*>(&q1);
        *reinterpret_cast<uint2*>(dstSq + (size_t)r * K0C + c4 * 4) = Q;
    }
}

// ---------------------------------------------------------------------------
// Big GEMM + fused merge: Out = bias + (mask ? Xh@Wh^T : 0) over full K=4096.
// CTA 128x256, warp 64x64, 4-stage ring (prefetch distance 3).
// Requires g_mask finalized (gate+fixup run before this kernel).
// ---------------------------------------------------------------------------
__global__ __launch_bounds__(256, 1)
void big_gemm(float* __restrict__ Out, const float* __restrict__ Bv)
{
    extern __shared__ __align__(1024) char smem[];
    const uint32_t sbase = smem_u32(smem);
    const int tid  = threadIdx.x;
    const int wid  = tid >> 5;
    const int lane = tid & 31;

    const int bm = blockIdx.y * BM;
    const int bn = blockIdx.x * BN;

    const int warpM = (wid & 1) * 64;
    const int warpN = (wid >> 1) * 64;

    const int subl = lane >> 3;
    const int tr   = lane & 7;
    const int aRow = (subl & 1) * 8 + tr;
    const int aK8  = (subl >> 1);
    const int bRow = (subl >> 1) * 8 + tr;
    const int bK8  = (subl & 1);

    float acc[4][8][4];
    #pragma unroll
    for (int i = 0; i < 4; ++i)
        #pragma unroll
        for (int j = 0; j < 8; ++j)
            #pragma unroll
            for (int q = 0; q < 4; ++q) acc[i][j][q] = 0.0f;

    auto load_chunk = [&](int it, int buf) {
        const __half* Ap = g_Xh + (size_t)bm * K_DIM + it * BK;
        const __half* Bp = g_Wh + (size_t)bn * K_DIM + it * BK;
        const uint32_t aOff = buf * STAGE_BYTES;
        const uint32_t bOff = aOff + STAGE_A;
        #pragma unroll
        for (int l = 0; l < 4; ++l) {                 // A: 1024 16B lines
            int idx = tid + l * 256;
            int r = idx >> 3, c = idx & 7;
            cp_async16(sbase + aOff + SWZ128((uint32_t)(r * 128 + c * 16)),
                       Ap + (size_t)r * K_DIM + c * 8);
        }
        #pragma unroll
        for (int l = 0; l < 8; ++l) {                 // B: 2048 16B lines
            int idx = tid + l * 256;
            int r = idx >> 3, c = idx & 7;
            cp_async16(sbase + bOff + SWZ128((uint32_t)(r * 128 + c * 16)),
                       Bp + (size_t)r * K_DIM + c * 8);
        }
    };

    load_chunk(0, 0); CP_COMMIT();
    load_chunk(1, 1); CP_COMMIT();
    load_chunk(2, 2); CP_COMMIT();

    int buf = 0;
    for (int it = 0; it < NCHUNK; ++it) {
        if (it + 3 < NCHUNK) {
            int nb = buf + 3; if (nb >= NSTAGE) nb -= NSTAGE;
            load_chunk(it + 3, nb);
        }
        CP_COMMIT();
        CP_WAIT3();
        __syncthreads();

        const uint32_t aBase = sbase + buf * STAGE_BYTES;
        const uint32_t bBase = aBase + STAGE_A;

        #pragma unroll
        for (int ks = 0; ks < 4; ++ks) {
            uint32_t afrag[4][4];
            #pragma unroll
            for (int mi = 0; mi < 4; ++mi) {
                int row = warpM + mi * 16 + aRow;
                uint32_t byte = (uint32_t)(row * 128) +
                                ((uint32_t)((ks * 2 + aK8) * 16) ^ ((row & 7) * 16));
                ldsm_x4(afrag[mi][0], afrag[mi][1], afrag[mi][2], afrag[mi][3],
                        aBase + byte);
            }
            #pragma unroll
            for (int pr = 0; pr < 4; ++pr) {
                int row = warpN + pr * 16 + bRow;
                uint32_t byte = (uint32_t)(row * 128) +
                                ((uint32_t)((ks * 2 + bK8) * 16) ^ ((row & 7) * 16));
                uint32_t b0, b1, b2, b3;
                ldsm_x4(b0, b1, b2, b3, bBase + byte);
                #pragma unroll
                for (int mi = 0; mi < 4; ++mi) {
                    mma_fp16(acc[mi][pr * 2 + 0], afrag[mi], b0, b1);
                    mma_fp16(acc[mi][pr * 2 + 1], afrag[mi], b2, b3);
                }
            }
        }
        __syncthreads();
        ++buf; if (buf == NSTAGE) buf = 0;
    }

    // Fused merge epilogue: Out = bias + (mask ? acc : 0)
    const int mrow = lane >> 2;
    const int ncol = (lane & 3) * 2;
    #pragma unroll
    for (int mi = 0; mi < 4; ++mi) {
        #pragma unroll
        for (int ni = 0; ni < 8; ++ni) {
            const int m = bm + warpM + mi * 16 + mrow;
            const int n = bn + warpN + ni * 8 + ncol;
            const float bx = __ldg(Bv + n);
            const float by = __ldg(Bv + n + 1);
            size_t o  = (size_t)m * N_DIM + n;
            size_t o2 = o + (size_t)8 * N_DIM;
            float2 v0, v1;
            v0.x = bx + (g_mask[o]      ? acc[mi][ni][0] : 0.0f);
            v0.y = by + (g_mask[o + 1]  ? acc[mi][ni][1] : 0.0f);
            v1.x = bx + (g_mask[o2]     ? acc[mi][ni][2] : 0.0f);
            v1.y = by + (g_mask[o2 + 1] ? acc[mi][ni][3] : 0.0f);
            *reinterpret_cast<float2*>(&Out[o])  = v0;
            *reinterpret_cast<float2*>(&Out[o2]) = v1;
        }
    }
}

// ---------------------------------------------------------------------------
// Gate GEMM: y1h = Xh0@Wh0^T, s2h = Xsq@Wsq^T over K0=256. Classify with band;
// certain -> mask; uncertain -> list for exact fixup.
// CTA 128x64, 256 threads (8 warps, 4m x 2n), warp 32x32, distance-1 ring.
// launch_bounds(256,2): <=128 regs -> 2 CTAs/SM (independent-CTA latency hiding).
// ---------------------------------------------------------------------------
__global__ __launch_bounds__(256, 2)
void gate_gemm()
{
    extern __shared__ __align__(1024) char smem[];
    const uint32_t sbase = smem_u32(smem);
    const int tid  = threadIdx.x;
    const int wid  = tid >> 5;
    const int lane = tid & 31;

    const int bm = blockIdx.y * GBM;
    const int bn = blockIdx.x * GBN;

    const int warpM = (wid & 3) * 32;     // 0..96
    const int warpN = (wid >> 2) * 32;    // 0 or 32

    const int subl = lane >> 3;
    const int tr   = lane & 7;
    const int aRow = (subl & 1) * 8 + tr;
    const int aK8  = (subl >> 1);
    const int bRow = (subl >> 1) * 8 + tr;
    const int bK8  = (subl & 1);

    float accY[2][4][4], accS[2][4][4];
    #pragma unroll
    for (int i = 0; i < 2; ++i)
        #pragma unroll
        for (int j = 0; j < 4; ++j)
            #pragma unroll
            for (int q = 0; q < 4; ++q) { accY[i][j][q] = 0.0f; accS[i][j][q] = 0.0f; }

    auto load_chunk = [&](int ck, int buf) {
        const __half* Ah = g_Xh  + (size_t)bm * K_DIM + ck * 64;
        const __half* Bh = g_Wh  + (size_t)bn * K_DIM + ck * 64;
        const __half* Aq = g_Xsq + (size_t)bm * K0C   + ck * 64;
        const __half* Bq = g_Wsq + (size_t)bn * K0C   + ck * 64;
        const uint32_t s0 = buf * G_STAGE;
        #pragma unroll
        for (int l = 0; l < 4; ++l) {                 // Ah, Aq: 1024 lines each
            int idx = tid + l * 256;
            int r = idx >> 3, c = idx & 7;
            uint32_t sw = SWZ128((uint32_t)(r * 128 + c * 16));
            cp_async16(sbase + s0 + sw,               Ah + (size_t)r * K_DIM + c * 8);
            cp_async16(sbase + s0 + G_AH + G_BH + sw, Aq + (size_t)r * K0C + c * 8);
        }
        #pragma unroll
        for (int l = 0; l < 2; ++l) {                 // Bh, Bq: 512 lines each
            int idx = tid + l * 256;
            int r = idx >> 3, c = idx & 7;
            uint32_t sw = SWZ128((uint32_t)(r * 128 + c * 16));
            cp_async16(sbase + s0 + G_AH + sw,                Bh + (size_t)r * K_DIM + c * 8);
            cp_async16(sbase + s0 + G_AH + G_BH + G_ASQ + sw, Bq + (size_t)r * K0C + c * 8);
        }
    };

    load_chunk(0, 0); CP_COMMIT();

    #pragma unroll
    for (int ck = 0; ck < 4; ++ck) {
        if (ck + 1 < 4) { load_chunk(ck + 1, (ck + 1) & 1); CP_COMMIT(); }
        if (ck + 1 < 4) { CP_WAIT1(); } else { CP_WAIT0(); }
        __syncthreads();

        const uint32_t hA = sbase + (ck & 1) * G_STAGE;
        const uint32_t hB = hA + G_AH;
        const uint32_t qA = hB + G_BH;
        const uint32_t qB = qA + G_ASQ;

        #pragma unroll
        for (int ks = 0; ks < 4; ++ks) {
            uint32_t ah[2][4], aq[2][4];
            #pragma unroll
            for (int mi = 0; mi < 2; ++mi) {
                int row = warpM + mi * 16 + aRow;
                uint32_t byte = (uint32_t)(row * 128) +
                                ((uint32_t)((ks * 2 + aK8) * 16) ^ ((row & 7) * 16));
                ldsm_x4(ah[mi][0], ah[mi][1], ah[mi][2], ah[mi][3], hA + byte);
                ldsm_x4(aq[mi][0], aq[mi][1], aq[mi][2], aq[mi][3], qA + byte);
            }
            #pragma unroll
            for (int pr = 0; pr < 2; ++pr) {
                int row = warpN + pr * 16 + bRow;
                uint32_t byte = (uint32_t)(row * 128) +
                                ((uint32_t)((ks * 2 + bK8) * 16) ^ ((row & 7) * 16));
                uint32_t h0, h1, h2, h3, q0, q1, q2, q3;
                ldsm_x4(h0, h1, h2, h3, hB + byte);
                ldsm_x4(q0, q1, q2, q3, qB + byte);
                #pragma unroll
                for (int mi = 0; mi < 2; ++mi) {
                    mma_fp16(accY[mi][pr * 2 + 0], ah[mi], h0, h1);
                    mma_fp16(accY[mi][pr * 2 + 1], ah[mi], h2, h3);
                    mma_fp16(accS[mi][pr * 2 + 0], aq[mi], q0, q1);
                    mma_fp16(accS[mi][pr * 2 + 1], aq[mi], q2, q3);
                }
            }
        }
        __syncthreads();    // all reads done before next prefetch overwrites
    }

    // Epilogue: classify each element
    const int mrow = lane >> 2;
    const int ncol = (lane & 3) * 2;
    #pragma unroll
    for (int mi = 0; mi < 2; ++mi) {
        #pragma unroll
        for (int ni = 0; ni < 4; ++ni) {
            #pragma unroll
            for (int h = 0; h < 2; ++h) {             // row halves (+0, +8)
                const int m = bm + warpM + mi * 16 + mrow + h * 8;
                const int n = bn + warpN + ni * 8 + ncol;
                #pragma unroll
                for (int q = 0; q < 2; ++q) {
                    float y = accY[mi][ni][h * 2 + q];
                    float s = accS[mi][ni][h * 2 + q];
                    float denom = sqrtf(s * (1.0f / (SQS * SQS * 256.0f)) + EPS);
                    float t = fabsf(y) / fmaxf(denom, EPS);
                    size_t o = (size_t)m * N_DIM + n + q;
                    if (t < TAU - BAND) {
                        g_mask[o] = 0;
                    } else if (t > TAU + BAND) {
                        g_mask[o] = 1;
                    } else {
                        g_mask[o] = 1;                 // placeholder; fixup overwrites
                        int idx = atomicAdd(&g_count, 1);
                        if (idx < LIST_CAP)
                            g_list[idx] = ((uint32_t)m << 12) | (uint32_t)(n + q);
                    }
                }
            }
        }
    }
}

// ---------------------------------------------------------------------------
// Fixup: exact fp32 recompute of y1/s2 for uncertain elements (1 warp each).
// ---------------------------------------------------------------------------
__global__ __launch_bounds__(256)
void fixup_kernel(const float* __restrict__ X, const float* __restrict__ W)
{
    const int lane = threadIdx.x & 31;
    const int wglobal = (blockIdx.x * 256 + threadIdx.x) >> 5;
    const int nwarps = (gridDim.x * 256) >> 5;
    int total = g_count; if (total > LIST_CAP) total = LIST_CAP;

    for (int i = wglobal; i < total; i += nwarps) {
        uint32_t p = g_list[i];
        int m = p >> 12;
        int n = p & 4095;
        const float* xr = X + (size_t)m * K_DIM;
        const float* wr = W + (size_t)n * K_DIM;
        float y = 0.0f, s = 0.0f;
        #pragma unroll
        for (int j = 0; j < 2; ++j) {
            float4 a = *reinterpret_cast<const float4*>(xr + lane * 8 + j * 4);
            float4 b = *reinterpret_cast<const float4*>(wr + lane * 8 + j * 4);
            y = fmaf(a.x, b.x, y); y = fmaf(a.y, b.y, y);
            y = fmaf(a.z, b.z, y); y = fmaf(a.w, b.w, y);
            float px = a.x * b.x, py = a.y * b.y, pz = a.z * b.z, pw = a.w * b.w;
            s = fmaf(px, px, s); s = fmaf(py, py, s);
            s = fmaf(pz, pz, s); s = fmaf(pw, pw, s);
        }
        #pragma unroll
        for (int off = 16; off > 0; off >>= 1) {
            y += __shfl_xor_sync(0xFFFFFFFF, y, off);
            s += __shfl_xor_sync(0xFFFFFFFF, s, off);
        }
        if (lane == 0) {
            float denom = sqrtf(s * (1.0f / 256.0f) + EPS);
            float t = fabsf(y) / fmaxf(denom, EPS);
            g_mask[(size_t)m * N_DIM + n] = (t < TAU) ? 0 : 1;
        }
    }
}

// ---------------------------------------------------------------------------
extern "C" void kernel_launch(void* const* d_in, const int* in_sizes, int n_in,
                              void* d_out, int out_size)
{
    const float* x  = (const float*)d_in[0];   // [8192, 4096]
    const float* w  = (const float*)d_in[1];   // [4096, 4096]
    const float* bv = (const float*)d_in[2];   // [4096]
    float* out      = (float*)d_out;           // [8192, 4096]
    (void)in_sizes; (void)n_in; (void)out_size;

    cudaFuncSetAttribute(big_gemm,
                         cudaFuncAttributeMaxDynamicSharedMemorySize, SMEM_BIG);
    cudaFuncSetAttribute(gate_gemm,
                         cudaFuncAttributeMaxDynamicSharedMemorySize, SMEM_GATE);

    __half *xh, *wh, *xq, *wq;
    cudaGetSymbolAddress((void**)&xh, g_Xh);
    cudaGetSymbolAddress((void**)&wh, g_Wh);
    cudaGetSymbolAddress((void**)&xq, g_Xsq);
    cudaGetSymbolAddress((void**)&wq, g_Wsq);

    zero_count<<<1, 1>>>();
    conv_kernel<<<M_DIM * (K_DIM / 4) / 256, 256>>>(x, xh, xq, 1.0f, M_DIM);
    conv_kernel<<<N_DIM * (K_DIM / 4) / 256, 256>>>(w, wh, wq, SQS, N_DIM);

    // Gate (classify + uncertain list), then exact fixup -> mask final
    dim3 gateGrid(N_DIM / GBN, M_DIM / GBM);   // (64, 64)
    gate_gemm<<<gateGrid, 256, SMEM_GATE>>>();
    fixup_kernel<<<512, 256>>>(x, w);

    // Full-K value GEMM with fused mask+bias epilogue
    dim3 bigGrid(N_DIM / BN, M_DIM / BM);      // (16, 64)
    big_gemm<<<bigGrid, 256, SMEM_BIG>>>(out, bv);
}

// round 10
// speedup vs baseline: 1.6163x; 1.0714x over previous
#include <cuda_runtime.h>
#include <cuda_fp16.h>
#include <cstdint>

// ---------------------------------------------------------------------------
// Problem shape (fixed by setup_inputs: B=4, S=2048, K=4096, N=4096)
// ---------------------------------------------------------------------------
namespace {
constexpr int M_DIM = 8192;
constexpr int N_DIM = 4096;
constexpr int K_DIM = 4096;
constexpr int K0C   = 256;
constexpr float TAU = 3.0f;
constexpr float EPS = 1e-6f;
constexpr float BAND = 0.05f;              // gate uncertainty band on t (~8 sigma)

// Big GEMM tiling: CTA 128x256, 8 warps (2m x 4n), warp 64x64, BK=64
constexpr int BM = 128;
constexpr int BN = 256;
constexpr int BK = 64;
constexpr int NCHUNK = K_DIM / BK;          // 64
constexpr int STAGE_A = BM * 128;           // 16384
constexpr int STAGE_B = BN * 128;           // 32768
constexpr int STAGE_BYTES = STAGE_A + STAGE_B;     // 49152
constexpr int NSTAGE = 4;
constexpr int SMEM_BIG = NSTAGE * STAGE_BYTES;     // 196608

// Gate GEMM tiling: CTA 128x64, 256 threads (8 warps, 4m x 2n), warp 32x32
// Squares computed IN REGISTERS from the same fragments (no Xsq/Wsq tiles).
constexpr int GBM = 128;
constexpr int GBN = 64;
constexpr int G_AH  = GBM * 128;            // 16384
constexpr int G_BH  = GBN * 128;            // 8192
constexpr int G_STAGE = G_AH + G_BH;        // 24576
constexpr int G_NSTAGE = 3;
constexpr int SMEM_GATE = G_NSTAGE * G_STAGE;  // 73728 -> 2 CTAs/SM

constexpr int LIST_CAP = 1 << 25;           // 33.5M (full-size safe)
}

// ---------------------------------------------------------------------------
// Device scratch (static; no dynamic allocation allowed)
// ---------------------------------------------------------------------------
__device__ __align__(1024) unsigned char g_mask[(size_t)M_DIM * N_DIM];
__device__ __align__(1024) __half        g_Xh[(size_t)M_DIM * K_DIM];
__device__ __align__(1024) __half        g_Wh[(size_t)N_DIM * K_DIM];
__device__ __align__(1024) uint32_t      g_list[LIST_CAP];
__device__ int                           g_count;

// ---------------------------------------------------------------------------
// Helpers (base-ISA only: cp.async / ldmatrix / mma.sync)
// ---------------------------------------------------------------------------
__device__ __forceinline__ uint32_t smem_u32(const void* p) {
    uint32_t a;
    asm("{ .reg .u64 t; cvta.to.shared.u64 t, %1; cvt.u32.u64 %0, t; }" : "=r"(a) : "l"(p));
    return a;
}
#define SWZ128(off) ((off) ^ (((off) >> 3) & 0x70))

__device__ __forceinline__ void cp_async16(uint32_t dst, const void* src) {
    asm volatile("cp.async.cg.shared.global [%0], [%1], 16;"
                 :: "r"(dst), "l"(__cvta_generic_to_global(src)) : "memory");
}
#define CP_COMMIT() asm volatile("cp.async.commit_group;" ::: "memory")
#define CP_WAIT0()  asm volatile("cp.async.wait_group 0;" ::: "memory")
#define CP_WAIT1()  asm volatile("cp.async.wait_group 1;" ::: "memory")
#define CP_WAIT2()  asm volatile("cp.async.wait_group 2;" ::: "memory")

__device__ __forceinline__ void ldsm_x4(uint32_t& r0, uint32_t& r1, uint32_t& r2,
                                        uint32_t& r3, uint32_t addr) {
    asm volatile("ldmatrix.sync.aligned.m8n8.x4.shared.b16 {%0,%1,%2,%3}, [%4];"
                 : "=r"(r0), "=r"(r1), "=r"(r2), "=r"(r3) : "r"(addr));
}
__device__ __forceinline__ void mma_fp16(float* c, const uint32_t* a,
                                         uint32_t b0, uint32_t b1) {
    asm volatile("mma.sync.aligned.m16n8k16.row.col.f32.f16.f16.f32 "
                 "{%0,%1,%2,%3}, {%4,%5,%6,%7}, {%8,%9}, {%0,%1,%2,%3};"
                 : "+f"(c[0]), "+f"(c[1]), "+f"(c[2]), "+f"(c[3])
                 : "r"(a[0]), "r"(a[1]), "r"(a[2]), "r"(a[3]), "r"(b0), "r"(b1));
}
// Elementwise fp16x2 square of a fragment register (for the S-GEMM operands)
__device__ __forceinline__ uint32_t sq_h2(uint32_t v) {
    uint32_t r;
    asm("mul.rn.f16x2 %0, %1, %1;" : "=r"(r) : "r"(v));
    return r;
}

// ---------------------------------------------------------------------------
// Zero the uncertain-list counter (determinism across graph replays)
// ---------------------------------------------------------------------------
__global__ void zero_count() { g_count = 0; }

// ---------------------------------------------------------------------------
// Convert: fp32 [rows x 4096] -> fp16 (RN)
// ---------------------------------------------------------------------------
__global__ __launch_bounds__(256)
void conv_kernel(const float* __restrict__ src, __half* __restrict__ dstH, int rows)
{
    int idx = blockIdx.x * 256 + threadIdx.x;     // one float4 per thread
    if (idx >= rows * (K_DIM / 4)) return;
    int r  = idx >> 10;
    int c4 = idx & 1023;
    float4 v = *reinterpret_cast<const float4*>(src + (size_t)r * K_DIM + c4 * 4);
    __half2 h0 = __floats2half2_rn(v.x, v.y);
    __half2 h1 = __floats2half2_rn(v.z, v.w);
    uint2 H;
    H.x = *reinterpret_cast<uint32_t*>(&h0);
    H.y = *reinterpret_cast<uint32_t*>(&h1);
    *reinterpret_cast<uint2*>(dstH + (size_t)r * K_DIM + c4 * 4) = H;
}

// ---------------------------------------------------------------------------
// Big GEMM + fused merge: Out = bias + (mask ? Xh@Wh^T : 0) over full K=4096.
// CTA 128x256, warp 64x64, 4-stage ring, prefetch distance 2, ONE sync/chunk
// (buffer reused >=2 iterations after last read; the intervening sync orders).
// Requires g_mask finalized (gate+fixup run before this kernel).
// ---------------------------------------------------------------------------
__global__ __launch_bounds__(256, 1)
void big_gemm(float* __restrict__ Out, const float* __restrict__ Bv)
{
    extern __shared__ __align__(1024) char smem[];
    const uint32_t sbase = smem_u32(smem);
    const int tid  = threadIdx.x;
    const int wid  = tid >> 5;
    const int lane = tid & 31;

    const int bm = blockIdx.y * BM;
    const int bn = blockIdx.x * BN;

    const int warpM = (wid & 1) * 64;
    const int warpN = (wid >> 1) * 64;

    const int subl = lane >> 3;
    const int tr   = lane & 7;
    const int aRow = (subl & 1) * 8 + tr;
    const int aK8  = (subl >> 1);
    const int bRow = (subl >> 1) * 8 + tr;
    const int bK8  = (subl & 1);

    float acc[4][8][4];
    #pragma unroll
    for (int i = 0; i < 4; ++i)
        #pragma unroll
        for (int j = 0; j < 8; ++j)
            #pragma unroll
            for (int q = 0; q < 4; ++q) acc[i][j][q] = 0.0f;

    auto load_chunk = [&](int it, int buf) {
        const __half* Ap = g_Xh + (size_t)bm * K_DIM + it * BK;
        const __half* Bp = g_Wh + (size_t)bn * K_DIM + it * BK;
        const uint32_t aOff = buf * STAGE_BYTES;
        const uint32_t bOff = aOff + STAGE_A;
        #pragma unroll
        for (int l = 0; l < 4; ++l) {                 // A: 1024 16B lines
            int idx = tid + l * 256;
            int r = idx >> 3, c = idx & 7;
            cp_async16(sbase + aOff + SWZ128((uint32_t)(r * 128 + c * 16)),
                       Ap + (size_t)r * K_DIM + c * 8);
        }
        #pragma unroll
        for (int l = 0; l < 8; ++l) {                 // B: 2048 16B lines
            int idx = tid + l * 256;
            int r = idx >> 3, c = idx & 7;
            cp_async16(sbase + bOff + SWZ128((uint32_t)(r * 128 + c * 16)),
                       Bp + (size_t)r * K_DIM + c * 8);
        }
    };

    load_chunk(0, 0); CP_COMMIT();
    load_chunk(1, 1); CP_COMMIT();

    int buf = 0;
    for (int it = 0; it < NCHUNK; ++it) {
        if (it + 2 < NCHUNK) {
            int nb = buf + 2; if (nb >= NSTAGE) nb -= NSTAGE;
            load_chunk(it + 2, nb);
        }
        CP_COMMIT();                 // unconditional: keeps group accounting exact
        CP_WAIT2();
        __syncthreads();             // single barrier per chunk

        const uint32_t aBase = sbase + buf * STAGE_BYTES;
        const uint32_t bBase = aBase + STAGE_A;

        #pragma unroll
        for (int ks = 0; ks < 4; ++ks) {
            uint32_t afrag[4][4];
            #pragma unroll
            for (int mi = 0; mi < 4; ++mi) {
                int row = warpM + mi * 16 + aRow;
                uint32_t byte = (uint32_t)(row * 128) +
                                ((uint32_t)((ks * 2 + aK8) * 16) ^ ((row & 7) * 16));
                ldsm_x4(afrag[mi][0], afrag[mi][1], afrag[mi][2], afrag[mi][3],
                        aBase + byte);
            }
            #pragma unroll
            for (int pr = 0; pr < 4; ++pr) {
                int row = warpN + pr * 16 + bRow;
                uint32_t byte = (uint32_t)(row * 128) +
                                ((uint32_t)((ks * 2 + bK8) * 16) ^ ((row & 7) * 16));
                uint32_t b0, b1, b2, b3;
                ldsm_x4(b0, b1, b2, b3, bBase + byte);
                #pragma unroll
                for (int mi = 0; mi < 4; ++mi) {
                    mma_fp16(acc[mi][pr * 2 + 0], afrag[mi], b0, b1);
                    mma_fp16(acc[mi][pr * 2 + 1], afrag[mi], b2, b3);
                }
            }
        }
        ++buf; if (buf == NSTAGE) buf = 0;
    }

    // Fused merge epilogue: Out = bias + (mask ? acc : 0)
    const int mrow = lane >> 2;
    const int ncol = (lane & 3) * 2;
    #pragma unroll
    for (int mi = 0; mi < 4; ++mi) {
        #pragma unroll
        for (int ni = 0; ni < 8; ++ni) {
            const int m = bm + warpM + mi * 16 + mrow;
            const int n = bn + warpN + ni * 8 + ncol;
            const float bx = __ldg(Bv + n);
            const float by = __ldg(Bv + n + 1);
            size_t o  = (size_t)m * N_DIM + n;
            size_t o2 = o + (size_t)8 * N_DIM;
            float2 v0, v1;
            v0.x = bx + (g_mask[o]      ? acc[mi][ni][0] : 0.0f);
            v0.y = by + (g_mask[o + 1]  ? acc[mi][ni][1] : 0.0f);
            v1.x = bx + (g_mask[o2]     ? acc[mi][ni][2] : 0.0f);
            v1.y = by + (g_mask[o2 + 1] ? acc[mi][ni][3] : 0.0f);
            *reinterpret_cast<float2*>(&Out[o])  = v0;
            *reinterpret_cast<float2*>(&Out[o2]) = v1;
        }
    }
}

// ---------------------------------------------------------------------------
// Gate GEMM: y1h = Xh0@Wh0^T, s2h = (Xh0^2)@(Wh0^2)^T over K0=256.
// Square operands derived IN REGISTERS from the same ldmatrix fragments
// (identical layout), halving smem traffic. 3-stage ring, ONE sync/chunk.
// Classify with band; certain -> mask; uncertain -> list for exact fixup.
// ---------------------------------------------------------------------------
__global__ __launch_bounds__(256, 2)
void gate_gemm()
{
    extern __shared__ __align__(1024) char smem[];
    const uint32_t sbase = smem_u32(smem);
    const int tid  = threadIdx.x;
    const int wid  = tid >> 5;
    const int lane = tid & 31;

    const int bm = blockIdx.y * GBM;
    const int bn = blockIdx.x * GBN;

    const int warpM = (wid & 3) * 32;     // 0..96
    const int warpN = (wid >> 2) * 32;    // 0 or 32

    const int subl = lane >> 3;
    const int tr   = lane & 7;
    const int aRow = (subl & 1) * 8 + tr;
    const int aK8  = (subl >> 1);
    const int bRow = (subl >> 1) * 8 + tr;
    const int bK8  = (subl & 1);

    float accY[2][4][4], accS[2][4][4];
    #pragma unroll
    for (int i = 0; i < 2; ++i)
        #pragma unroll
        for (int j = 0; j < 4; ++j)
            #pragma unroll
            for (int q = 0; q < 4; ++q) { accY[i][j][q] = 0.0f; accS[i][j][q] = 0.0f; }

    auto load_chunk = [&](int ck, int buf) {
        const __half* Ah = g_Xh + (size_t)bm * K_DIM + ck * 64;
        const __half* Bh = g_Wh + (size_t)bn * K_DIM + ck * 64;
        const uint32_t s0 = buf * G_STAGE;
        #pragma unroll
        for (int l = 0; l < 4; ++l) {                 // Ah: 1024 lines
            int idx = tid + l * 256;
            int r = idx >> 3, c = idx & 7;
            cp_async16(sbase + s0 + SWZ128((uint32_t)(r * 128 + c * 16)),
                       Ah + (size_t)r * K_DIM + c * 8);
        }
        #pragma unroll
        for (int l = 0; l < 2; ++l) {                 // Bh: 512 lines
            int idx = tid + l * 256;
            int r = idx >> 3, c = idx & 7;
            cp_async16(sbase + s0 + G_AH + SWZ128((uint32_t)(r * 128 + c * 16)),
                       Bh + (size_t)r * K_DIM + c * 8);
        }
    };

    load_chunk(0, 0); CP_COMMIT();

    #pragma unroll
    for (int ck = 0; ck < 4; ++ck) {
        if (ck + 1 < 4) {
            load_chunk(ck + 1, (ck + 1) % G_NSTAGE);
            CP_COMMIT();
            CP_WAIT1();
        } else {
            CP_WAIT0();
        }
        __syncthreads();             // single barrier per chunk (3-stage ring)

        const uint32_t hA = sbase + (ck % G_NSTAGE) * G_STAGE;
        const uint32_t hB = hA + G_AH;

        #pragma unroll
        for (int ks = 0; ks < 4; ++ks) {
            uint32_t ah[2][4], aq[2][4];
            #pragma unroll
            for (int mi = 0; mi < 2; ++mi) {
                int row = warpM + mi * 16 + aRow;
                uint32_t byte = (uint32_t)(row * 128) +
                                ((uint32_t)((ks * 2 + aK8) * 16) ^ ((row & 7) * 16));
                ldsm_x4(ah[mi][0], ah[mi][1], ah[mi][2], ah[mi][3], hA + byte);
                #pragma unroll
                for (int r = 0; r < 4; ++r) aq[mi][r] = sq_h2(ah[mi][r]);
            }
            #pragma unroll
            for (int pr = 0; pr < 2; ++pr) {
                int row = warpN + pr * 16 + bRow;
                uint32_t byte = (uint32_t)(row * 128) +
                                ((uint32_t)((ks * 2 + bK8) * 16) ^ ((row & 7) * 16));
                uint32_t h0, h1, h2, h3;
                ldsm_x4(h0, h1, h2, h3, hB + byte);
                uint32_t q0 = sq_h2(h0), q1 = sq_h2(h1);
                uint32_t q2 = sq_h2(h2), q3 = sq_h2(h3);
                #pragma unroll
                for (int mi = 0; mi < 2; ++mi) {
                    mma_fp16(accY[mi][pr * 2 + 0], ah[mi], h0, h1);
                    mma_fp16(accY[mi][pr * 2 + 1], ah[mi], h2, h3);
                    mma_fp16(accS[mi][pr * 2 + 0], aq[mi], q0, q1);
                    mma_fp16(accS[mi][pr * 2 + 1], aq[mi], q2, q3);
                }
            }
        }
    }

    // Epilogue: classify each element
    const int mrow = lane >> 2;
    const int ncol = (lane & 3) * 2;
    #pragma unroll
    for (int mi = 0; mi < 2; ++mi) {
        #pragma unroll
        for (int ni = 0; ni < 4; ++ni) {
            #pragma unroll
            for (int h = 0; h < 2; ++h) {             // row halves (+0, +8)
                const int m = bm + warpM + mi * 16 + mrow + h * 8;
                const int n = bn + warpN + ni * 8 + ncol;
                #pragma unroll
                for (int q = 0; q < 2; ++q) {
                    float y = accY[mi][ni][h * 2 + q];
                    float s = accS[mi][ni][h * 2 + q];
                    float denom = sqrtf(s * (1.0f / 256.0f) + EPS);
                    float t = fabsf(y) / fmaxf(denom, EPS);
                    size_t o = (size_t)m * N_DIM + n + q;
                    if (t < TAU - BAND) {
                        g_mask[o] = 0;
                    } else if (t > TAU + BAND) {
                        g_mask[o] = 1;
                    } else {
                        g_mask[o] = 1;                 // placeholder; fixup overwrites
                        int idx = atomicAdd(&g_count, 1);
                        if (idx < LIST_CAP)
                            g_list[idx] = ((uint32_t)m << 12) | (uint32_t)(n + q);
                    }
                }
            }
        }
    }
}

// ---------------------------------------------------------------------------
// Fixup: exact fp32 recompute of y1/s2 for uncertain elements (1 warp each).
// ---------------------------------------------------------------------------
__global__ __launch_bounds__(256)
void fixup_kernel(const float* __restrict__ X, const float* __restrict__ W)
{
    const int lane = threadIdx.x & 31;
    const int wglobal = (blockIdx.x * 256 + threadIdx.x) >> 5;
    const int nwarps = (gridDim.x * 256) >> 5;
    int total = g_count; if (total > LIST_CAP) total = LIST_CAP;

    for (int i = wglobal; i < total; i += nwarps) {
        uint32_t p = g_list[i];
        int m = p >> 12;
        int n = p & 4095;
        const float* xr = X + (size_t)m * K_DIM;
        const float* wr = W + (size_t)n * K_DIM;
        float y = 0.0f, s = 0.0f;
        #pragma unroll
        for (int j = 0; j < 2; ++j) {
            float4 a = *reinterpret_cast<const float4*>(xr + lane * 8 + j * 4);
            float4 b = *reinterpret_cast<const float4*>(wr + lane * 8 + j * 4);
            y = fmaf(a.x, b.x, y); y = fmaf(a.y, b.y, y);
            y = fmaf(a.z, b.z, y); y = fmaf(a.w, b.w, y);
            float px = a.x * b.x, py = a.y * b.y, pz = a.z * b.z, pw = a.w * b.w;
            s = fmaf(px, px, s); s = fmaf(py, py, s);
            s = fmaf(pz, pz, s); s = fmaf(pw, pw, s);
        }
        #pragma unroll
        for (int off = 16; off > 0; off >>= 1) {
            y += __shfl_xor_sync(0xFFFFFFFF, y, off);
            s += __shfl_xor_sync(0xFFFFFFFF, s, off);
        }
        if (lane == 0) {
            float denom = sqrtf(s * (1.0f / 256.0f) + EPS);
            float t = fabsf(y) / fmaxf(denom, EPS);
            g_mask[(size_t)m * N_DIM + n] = (t < TAU) ? 0 : 1;
        }
    }
}

// ---------------------------------------------------------------------------
extern "C" void kernel_launch(void* const* d_in, const int* in_sizes, int n_in,
                              void* d_out, int out_size)
{
    const float* x  = (const float*)d_in[0];   // [8192, 4096]
    const float* w  = (const float*)d_in[1];   // [4096, 4096]
    const float* bv = (const float*)d_in[2];   // [4096]
    float* out      = (float*)d_out;           // [8192, 4096]
    (void)in_sizes; (void)n_in; (void)out_size;

    cudaFuncSetAttribute(big_gemm,
                         cudaFuncAttributeMaxDynamicSharedMemorySize, SMEM_BIG);
    cudaFuncSetAttribute(gate_gemm,
                         cudaFuncAttributeMaxDynamicSharedMemorySize, SMEM_GATE);

    __half *xh, *wh;
    cudaGetSymbolAddress((void**)&xh, g_Xh);
    cudaGetSymbolAddress((void**)&wh, g_Wh);

    zero_count<<<1, 1>>>();
    conv_kernel<<<M_DIM * (K_DIM / 4) / 256, 256>>>(x, xh, M_DIM);
    conv_kernel<<<N_DIM * (K_DIM / 4) / 256, 256>>>(w, wh, N_DIM);

    // Gate (classify + uncertain list), then exact fixup -> mask final
    dim3 gateGrid(N_DIM / GBN, M_DIM / GBM);   // (64, 64)
    gate_gemm<<<gateGrid, 256, SMEM_GATE>>>();
    fixup_kernel<<<512, 256>>>(x, w);

    // Full-K value GEMM with fused mask+bias epilogue
    dim3 bigGrid(N_DIM / BN, M_DIM / BM);      // (16, 64)
    big_gemm<<<bigGrid, 256, SMEM_BIG>>>(out, bv);
}

// round 11
// speedup vs baseline: 1.6817x; 1.0404x over previous
#include <cuda_runtime.h>
#include <cuda_fp16.h>
#include <cstdint>

// ---------------------------------------------------------------------------
// Problem shape (fixed by setup_inputs: B=4, S=2048, K=4096, N=4096)
// ---------------------------------------------------------------------------
namespace {
constexpr int M_DIM = 8192;
constexpr int N_DIM = 4096;
constexpr int K_DIM = 4096;
constexpr int K0C   = 256;
constexpr float TAU = 3.0f;
constexpr float EPS = 1e-6f;
constexpr float BAND = 0.05f;              // gate uncertainty band on t (~8 sigma)

// Big GEMM tiling: CTA 128x256, 8 warps (2m x 4n), warp 64x64, BK=64
constexpr int BM = 128;
constexpr int BN = 256;
constexpr int BK = 64;
constexpr int NCHUNK = K_DIM / BK;          // 64
constexpr int STAGE_A = BM * 128;           // 16384
constexpr int STAGE_B = BN * 128;           // 32768
constexpr int STAGE_BYTES = STAGE_A + STAGE_B;     // 49152
constexpr int NSTAGE = 4;
constexpr int SMEM_BIG = NSTAGE * STAGE_BYTES;     // 196608

// Gate: CTA covers 128m x 128n as 2 sub-tiles of 64n. A-head (128x256 fp16,
// 64KB) resident for the whole CTA; B in a 4-stage ring of 8KB chunks.
constexpr int GBM = 128;
constexpr int GBN_SUB = 64;
constexpr int G_NSUB = 2;
constexpr int G_NITER = 4 * G_NSUB;          // 8 chunk-iterations
constexpr int G_A_BYTES = 4 * GBM * 128;     // 65536 (4 chunks x 16KB)
constexpr int G_B_STAGE = GBN_SUB * 128;     // 8192
constexpr int G_B_OFF   = G_A_BYTES;         // 65536
constexpr int G_MASK_OFF = G_B_OFF + 4 * G_B_STAGE;   // 98304 (8KB stage)
constexpr int G_LBUF_OFF = G_MASK_OFF + GBM * GBN_SUB; // 106496 (1024 x u32)
constexpr int G_LBUF_CAP = 1024;
constexpr int G_LCOUNT_OFF = G_LBUF_OFF + G_LBUF_CAP * 4;  // 110592
constexpr int G_LBASE_OFF  = G_LCOUNT_OFF + 4;             // 110596
constexpr int G_LNUM_OFF   = G_LBASE_OFF + 4;              // 110600
constexpr int SMEM_GATE = 110608;            // 2 CTAs/SM: 221216 <= 228KB

constexpr int LIST_CAP = 1 << 25;           // 33.5M (full-size safe)
}

// ---------------------------------------------------------------------------
// Device scratch (static; no dynamic allocation allowed)
// ---------------------------------------------------------------------------
__device__ __align__(1024) unsigned char g_mask[(size_t)M_DIM * N_DIM];
__device__ __align__(1024) __half        g_Xh[(size_t)M_DIM * K_DIM];
__device__ __align__(1024) __half        g_Wh[(size_t)N_DIM * K_DIM];
__device__ __align__(1024) uint32_t      g_list[LIST_CAP];
__device__ int                           g_count;

// ---------------------------------------------------------------------------
// Helpers (base-ISA only: cp.async / ldmatrix / mma.sync)
// ---------------------------------------------------------------------------
__device__ __forceinline__ uint32_t smem_u32(const void* p) {
    uint32_t a;
    asm("{ .reg .u64 t; cvta.to.shared.u64 t, %1; cvt.u32.u64 %0, t; }" : "=r"(a) : "l"(p));
    return a;
}
#define SWZ128(off) ((off) ^ (((off) >> 3) & 0x70))

__device__ __forceinline__ void cp_async16(uint32_t dst, const void* src) {
    asm volatile("cp.async.cg.shared.global [%0], [%1], 16;"
                 :: "r"(dst), "l"(__cvta_generic_to_global(src)) : "memory");
}
#define CP_COMMIT() asm volatile("cp.async.commit_group;" ::: "memory")
#define CP_WAIT2()  asm volatile("cp.async.wait_group 2;" ::: "memory")

__device__ __forceinline__ void ldsm_x4(uint32_t& r0, uint32_t& r1, uint32_t& r2,
                                        uint32_t& r3, uint32_t addr) {
    asm volatile("ldmatrix.sync.aligned.m8n8.x4.shared.b16 {%0,%1,%2,%3}, [%4];"
                 : "=r"(r0), "=r"(r1), "=r"(r2), "=r"(r3) : "r"(addr));
}
__device__ __forceinline__ void mma_fp16(float* c, const uint32_t* a,
                                         uint32_t b0, uint32_t b1) {
    asm volatile("mma.sync.aligned.m16n8k16.row.col.f32.f16.f16.f32 "
                 "{%0,%1,%2,%3}, {%4,%5,%6,%7}, {%8,%9}, {%0,%1,%2,%3};"
                 : "+f"(c[0]), "+f"(c[1]), "+f"(c[2]), "+f"(c[3])
                 : "r"(a[0]), "r"(a[1]), "r"(a[2]), "r"(a[3]), "r"(b0), "r"(b1));
}
__device__ __forceinline__ uint32_t sq_h2(uint32_t v) {
    uint32_t r;
    asm("mul.rn.f16x2 %0, %1, %1;" : "=r"(r) : "r"(v));
    return r;
}

// ---------------------------------------------------------------------------
// Zero the uncertain-list counter (determinism across graph replays)
// ---------------------------------------------------------------------------
__global__ void zero_count() { g_count = 0; }

// ---------------------------------------------------------------------------
// Convert: fp32 -> fp16 (RN) for both X and W in one launch
// ---------------------------------------------------------------------------
__global__ __launch_bounds__(256)
void conv_all(const float* __restrict__ X, const float* __restrict__ W,
              __half* __restrict__ Xh, __half* __restrict__ Wh)
{
    int idx = blockIdx.x * 256 + threadIdx.x;     // one float4 per thread
    if (idx >= (M_DIM + N_DIM) * (K_DIM / 4)) return;
    int r  = idx >> 10;
    int c4 = idx & 1023;
    const float* src; __half* dst; int row;
    if (r < M_DIM) { src = X; dst = g_Xh; row = r; }
    else           { src = W; dst = g_Wh; row = r - M_DIM; }
    (void)Xh; (void)Wh;
    float4 v = *reinterpret_cast<const float4*>(src + (size_t)row * K_DIM + c4 * 4);
    __half2 h0 = __floats2half2_rn(v.x, v.y);
    __half2 h1 = __floats2half2_rn(v.z, v.w);
    uint2 H;
    H.x = *reinterpret_cast<uint32_t*>(&h0);
    H.y = *reinterpret_cast<uint32_t*>(&h1);
    *reinterpret_cast<uint2*>(dst + (size_t)row * K_DIM + c4 * 4) = H;
}

// ---------------------------------------------------------------------------
// Big GEMM + fused merge: Out = bias + (mask ? Xh@Wh^T : 0) over full K=4096.
// CTA 128x256, warp 64x64, 4-stage ring, prefetch distance 2, ONE sync/chunk.
// (unchanged from R10)
// ---------------------------------------------------------------------------
__global__ __launch_bounds__(256, 1)
void big_gemm(float* __restrict__ Out, const float* __restrict__ Bv)
{
    extern __shared__ __align__(1024) char smem[];
    const uint32_t sbase = smem_u32(smem);
    const int tid  = threadIdx.x;
    const int wid  = tid >> 5;
    const int lane = tid & 31;

    const int bm = blockIdx.y * BM;
    const int bn = blockIdx.x * BN;

    const int warpM = (wid & 1) * 64;
    const int warpN = (wid >> 1) * 64;

    const int subl = lane >> 3;
    const int tr   = lane & 7;
    const int aRow = (subl & 1) * 8 + tr;
    const int aK8  = (subl >> 1);
    const int bRow = (subl >> 1) * 8 + tr;
    const int bK8  = (subl & 1);

    float acc[4][8][4];
    #pragma unroll
    for (int i = 0; i < 4; ++i)
        #pragma unroll
        for (int j = 0; j < 8; ++j)
            #pragma unroll
            for (int q = 0; q < 4; ++q) acc[i][j][q] = 0.0f;

    auto load_chunk = [&](int it, int buf) {
        const __half* Ap = g_Xh + (size_t)bm * K_DIM + it * BK;
        const __half* Bp = g_Wh + (size_t)bn * K_DIM + it * BK;
        const uint32_t aOff = buf * STAGE_BYTES;
        const uint32_t bOff = aOff + STAGE_A;
        #pragma unroll
        for (int l = 0; l < 4; ++l) {
            int idx = tid + l * 256;
            int r = idx >> 3, c = idx & 7;
            cp_async16(sbase + aOff + SWZ128((uint32_t)(r * 128 + c * 16)),
                       Ap + (size_t)r * K_DIM + c * 8);
        }
        #pragma unroll
        for (int l = 0; l < 8; ++l) {
            int idx = tid + l * 256;
            int r = idx >> 3, c = idx & 7;
            cp_async16(sbase + bOff + SWZ128((uint32_t)(r * 128 + c * 16)),
                       Bp + (size_t)r * K_DIM + c * 8);
        }
    };

    load_chunk(0, 0); CP_COMMIT();
    load_chunk(1, 1); CP_COMMIT();

    int buf = 0;
    for (int it = 0; it < NCHUNK; ++it) {
        if (it + 2 < NCHUNK) {
            int nb = buf + 2; if (nb >= NSTAGE) nb -= NSTAGE;
            load_chunk(it + 2, nb);
        }
        CP_COMMIT();
        CP_WAIT2();
        __syncthreads();

        const uint32_t aBase = sbase + buf * STAGE_BYTES;
        const uint32_t bBase = aBase + STAGE_A;

        #pragma unroll
        for (int ks = 0; ks < 4; ++ks) {
            uint32_t afrag[4][4];
            #pragma unroll
            for (int mi = 0; mi < 4; ++mi) {
                int row = warpM + mi * 16 + aRow;
                uint32_t byte = (uint32_t)(row * 128) +
                                ((uint32_t)((ks * 2 + aK8) * 16) ^ ((row & 7) * 16));
                ldsm_x4(afrag[mi][0], afrag[mi][1], afrag[mi][2], afrag[mi][3],
                        aBase + byte);
            }
            #pragma unroll
            for (int pr = 0; pr < 4; ++pr) {
                int row = warpN + pr * 16 + bRow;
                uint32_t byte = (uint32_t)(row * 128) +
                                ((uint32_t)((ks * 2 + bK8) * 16) ^ ((row & 7) * 16));
                uint32_t b0, b1, b2, b3;
                ldsm_x4(b0, b1, b2, b3, bBase + byte);
                #pragma unroll
                for (int mi = 0; mi < 4; ++mi) {
                    mma_fp16(acc[mi][pr * 2 + 0], afrag[mi], b0, b1);
                    mma_fp16(acc[mi][pr * 2 + 1], afrag[mi], b2, b3);
                }
            }
        }
        ++buf; if (buf == NSTAGE) buf = 0;
    }

    const int mrow = lane >> 2;
    const int ncol = (lane & 3) * 2;
    #pragma unroll
    for (int mi = 0; mi < 4; ++mi) {
        #pragma unroll
        for (int ni = 0; ni < 8; ++ni) {
            const int m = bm + warpM + mi * 16 + mrow;
            const int n = bn + warpN + ni * 8 + ncol;
            const float bx = __ldg(Bv + n);
            const float by = __ldg(Bv + n + 1);
            size_t o  = (size_t)m * N_DIM + n;
            size_t o2 = o + (size_t)8 * N_DIM;
            float2 v0, v1;
            v0.x = bx + (g_mask[o]      ? acc[mi][ni][0] : 0.0f);
            v0.y = by + (g_mask[o + 1]  ? acc[mi][ni][1] : 0.0f);
            v1.x = bx + (g_mask[o2]     ? acc[mi][ni][2] : 0.0f);
            v1.y = by + (g_mask[o2 + 1] ? acc[mi][ni][3] : 0.0f);
            *reinterpret_cast<float2*>(&Out[o])  = v0;
            *reinterpret_cast<float2*>(&Out[o2]) = v1;
        }
    }
}

// ---------------------------------------------------------------------------
// Gate GEMM v3: A-head resident (64KB), 2 N-sub-tiles per CTA, 4-stage B ring
// (distance 2 — same safe geometry as big_gemm). Squares in registers.
// Coalesced mask output via smem staging; CTA-aggregated uncertain list
// (one global atomic per CTA instead of per element).
// ---------------------------------------------------------------------------
__global__ __launch_bounds__(256, 2)
void gate_gemm()
{
    extern __shared__ __align__(1024) char smem[];
    const uint32_t sbase = smem_u32(smem);
    const int tid  = threadIdx.x;
    const int wid  = tid >> 5;
    const int lane = tid & 31;

    const int bm = blockIdx.y * GBM;
    const int bn = blockIdx.x * (GBN_SUB * G_NSUB);   // 128-wide CTA N footprint

    const int warpM = (wid & 3) * 32;     // 0..96
    const int warpN = (wid >> 2) * 32;    // 0 or 32

    const int subl = lane >> 3;
    const int tr   = lane & 7;
    const int aRow = (subl & 1) * 8 + tr;
    const int aK8  = (subl >> 1);
    const int bRow = (subl >> 1) * 8 + tr;
    const int bK8  = (subl & 1);

    unsigned char* stage = reinterpret_cast<unsigned char*>(smem + G_MASK_OFF);
    uint32_t* lbuf  = reinterpret_cast<uint32_t*>(smem + G_LBUF_OFF);
    int* lcount = reinterpret_cast<int*>(smem + G_LCOUNT_OFF);
    int* lbase  = reinterpret_cast<int*>(smem + G_LBASE_OFF);
    int* lnum   = reinterpret_cast<int*>(smem + G_LNUM_OFF);
    if (tid == 0) *lcount = 0;

    float accY[2][4][4], accS[2][4][4];
    #pragma unroll
    for (int i = 0; i < 2; ++i)
        #pragma unroll
        for (int j = 0; j < 4; ++j)
            #pragma unroll
            for (int q = 0; q < 4; ++q) { accY[i][j][q] = 0.0f; accS[i][j][q] = 0.0f; }

    // Load full A head (128 rows x 256 cols fp16 = 64KB, 4 chunks of 16KB)
    {
        #pragma unroll
        for (int l = 0; l < 16; ++l) {
            int idx = tid + l * 256;              // 0..4095 16B lines
            int chunk = idx >> 10;
            int line  = idx & 1023;
            int r = line >> 3, c = line & 7;
            cp_async16(sbase + chunk * 16384 + SWZ128((uint32_t)(r * 128 + c * 16)),
                       g_Xh + (size_t)(bm + r) * K_DIM + chunk * 64 + c * 8);
        }
    }

    auto load_B = [&](int it) {                    // B chunk for iteration it
        int sub = it >> 2, ck = it & 3;
        const __half* Bp = g_Wh + (size_t)(bn + sub * GBN_SUB) * K_DIM + ck * 64;
        const uint32_t s0 = G_B_OFF + (it & 3) * G_B_STAGE;
        #pragma unroll
        for (int l = 0; l < 2; ++l) {              // 512 lines / 256 threads
            int idx = tid + l * 256;
            int r = idx >> 3, c = idx & 7;
            cp_async16(sbase + s0 + SWZ128((uint32_t)(r * 128 + c * 16)),
                       Bp + (size_t)r * K_DIM + c * 8);
        }
    };

    load_B(0); CP_COMMIT();                        // group0 = A + B0
    load_B(1); CP_COMMIT();                        // group1 = B1

    for (int it = 0; it < G_NITER; ++it) {
        if (it + 2 < G_NITER) load_B(it + 2);
        CP_COMMIT();
        CP_WAIT2();
        __syncthreads();

        const uint32_t aBase = sbase + (it & 3) * 16384;
        const uint32_t bBase = sbase + G_B_OFF + (it & 3) * G_B_STAGE;

        #pragma unroll
        for (int ks = 0; ks < 4; ++ks) {
            uint32_t ah[2][4], aq[2][4];
            #pragma unroll
            for (int mi = 0; mi < 2; ++mi) {
                int row = warpM + mi * 16 + aRow;
                uint32_t byte = (uint32_t)(row * 128) +
                                ((uint32_t)((ks * 2 + aK8) * 16) ^ ((row & 7) * 16));
                ldsm_x4(ah[mi][0], ah[mi][1], ah[mi][2], ah[mi][3], aBase + byte);
                #pragma unroll
                for (int r = 0; r < 4; ++r) aq[mi][r] = sq_h2(ah[mi][r]);
            }
            #pragma unroll
            for (int pr = 0; pr < 2; ++pr) {
                int row = warpN + pr * 16 + bRow;
                uint32_t byte = (uint32_t)(row * 128) +
                                ((uint32_t)((ks * 2 + bK8) * 16) ^ ((row & 7) * 16));
                uint32_t h0, h1, h2, h3;
                ldsm_x4(h0, h1, h2, h3, bBase + byte);
                uint32_t q0 = sq_h2(h0), q1 = sq_h2(h1);
                uint32_t q2 = sq_h2(h2), q3 = sq_h2(h3);
                #pragma unroll
                for (int mi = 0; mi < 2; ++mi) {
                    mma_fp16(accY[mi][pr * 2 + 0], ah[mi], h0, h1);
                    mma_fp16(accY[mi][pr * 2 + 1], ah[mi], h2, h3);
                    mma_fp16(accS[mi][pr * 2 + 0], aq[mi], q0, q1);
                    mma_fp16(accS[mi][pr * 2 + 1], aq[mi], q2, q3);
                }
            }
        }

        if ((it & 3) == 3) {
            // ---- classify sub-tile, stage mask bytes in smem, collect list ----
            const int sub = it >> 2;
            const int mrow = lane >> 2;
            const int ncol = (lane & 3) * 2;
            #pragma unroll
            for (int mi = 0; mi < 2; ++mi)
                #pragma unroll
                for (int ni = 0; ni < 4; ++ni)
                    #pragma unroll
                    for (int h = 0; h < 2; ++h) {
                        const int mr = warpM + mi * 16 + mrow + h * 8;       // 0..127
                        const int nc = warpN + ni * 8 + ncol;                // 0..62
                        #pragma unroll
                        for (int q = 0; q < 2; ++q) {
                            float y = accY[mi][ni][h * 2 + q];
                            float s = accS[mi][ni][h * 2 + q];
                            float denom = sqrtf(s * (1.0f / 256.0f) + EPS);
                            float t = fabsf(y) / fmaxf(denom, EPS);
                            unsigned char mv;
                            if (t < TAU - BAND)      mv = 0;
                            else if (t > TAU + BAND) mv = 1;
                            else {
                                mv = 1;             // placeholder; fixup overwrites
                                int li = atomicAdd(lcount, 1);
                                uint32_t pk = ((uint32_t)(bm + mr) << 12) |
                                              (uint32_t)(bn + sub * GBN_SUB + nc + q);
                                if (li < G_LBUF_CAP) lbuf[li] = pk;
                                else {
                                    int gi = atomicAdd(&g_count, 1);
                                    if (gi < LIST_CAP) g_list[gi] = pk;
                                }
                            }
                            stage[mr * 64 + nc + q] = mv;
                        }
                    }
            __syncthreads();
            // ---- coalesced mask copy-out + CTA-aggregated list flush ----
            {
                int mr = tid >> 1, half = (tid & 1) * 32;
                uint4 v0 = *reinterpret_cast<uint4*>(stage + mr * 64 + half);
                uint4 v1 = *reinterpret_cast<uint4*>(stage + mr * 64 + half + 16);
                size_t go = (size_t)(bm + mr) * N_DIM + bn + sub * GBN_SUB + half;
                *reinterpret_cast<uint4*>(g_mask + go)      = v0;
                *reinterpret_cast<uint4*>(g_mask + go + 16) = v1;
            }
            if (tid == 0) {
                int ln = *lcount; if (ln > G_LBUF_CAP) ln = G_LBUF_CAP;
                *lbase = atomicAdd(&g_count, ln);
                *lnum  = ln;
                *lcount = 0;
            }
            __syncthreads();
            {
                int ln = *lnum, base = *lbase;
                for (int i = tid; i < ln; i += 256) {
                    int gi = base + i;
                    if (gi < LIST_CAP) g_list[gi] = lbuf[i];
                }
            }
            // reset accumulators for next sub-tile
            #pragma unroll
            for (int i = 0; i < 2; ++i)
                #pragma unroll
                for (int j = 0; j < 4; ++j)
                    #pragma unroll
                    for (int q = 0; q < 4; ++q) { accY[i][j][q] = 0.0f; accS[i][j][q] = 0.0f; }
        }
    }
}

// ---------------------------------------------------------------------------
// Fixup: exact fp32 recompute of y1/s2 for uncertain elements (1 warp each).
// ---------------------------------------------------------------------------
__global__ __launch_bounds__(256)
void fixup_kernel(const float* __restrict__ X, const float* __restrict__ W)
{
    const int lane = threadIdx.x & 31;
    const int wglobal = (blockIdx.x * 256 + threadIdx.x) >> 5;
    const int nwarps = (gridDim.x * 256) >> 5;
    int total = g_count; if (total > LIST_CAP) total = LIST_CAP;

    for (int i = wglobal; i < total; i += nwarps) {
        uint32_t p = g_list[i];
        int m = p >> 12;
        int n = p & 4095;
        const float* xr = X + (size_t)m * K_DIM;
        const float* wr = W + (size_t)n * K_DIM;
        float y = 0.0f, s = 0.0f;
        #pragma unroll
        for (int j = 0; j < 2; ++j) {
            float4 a = *reinterpret_cast<const float4*>(xr + lane * 8 + j * 4);
            float4 b = *reinterpret_cast<const float4*>(wr + lane * 8 + j * 4);
            y = fmaf(a.x, b.x, y); y = fmaf(a.y, b.y, y);
            y = fmaf(a.z, b.z, y); y = fmaf(a.w, b.w, y);
            float px = a.x * b.x, py = a.y * b.y, pz = a.z * b.z, pw = a.w * b.w;
            s = fmaf(px, px, s); s = fmaf(py, py, s);
            s = fmaf(pz, pz, s); s = fmaf(pw, pw, s);
        }
        #pragma unroll
        for (int off = 16; off > 0; off >>= 1) {
            y += __shfl_xor_sync(0xFFFFFFFF, y, off);
            s += __shfl_xor_sync(0xFFFFFFFF, s, off);
        }
        if (lane == 0) {
            float denom = sqrtf(s * (1.0f / 256.0f) + EPS);
            float t = fabsf(y) / fmaxf(denom, EPS);
            g_mask[(size_t)m * N_DIM + n] = (t < TAU) ? 0 : 1;
        }
    }
}

// ---------------------------------------------------------------------------
extern "C" void kernel_launch(void* const* d_in, const int* in_sizes, int n_in,
                              void* d_out, int out_size)
{
    const float* x  = (const float*)d_in[0];   // [8192, 4096]
    const float* w  = (const float*)d_in[1];   // [4096, 4096]
    const float* bv = (const float*)d_in[2];   // [4096]
    float* out      = (float*)d_out;           // [8192, 4096]
    (void)in_sizes; (void)n_in; (void)out_size;

    cudaFuncSetAttribute(big_gemm,
                         cudaFuncAttributeMaxDynamicSharedMemorySize, SMEM_BIG);
    cudaFuncSetAttribute(gate_gemm,
                         cudaFuncAttributeMaxDynamicSharedMemorySize, SMEM_GATE);

    __half *xh, *wh;
    cudaGetSymbolAddress((void**)&xh, g_Xh);
    cudaGetSymbolAddress((void**)&wh, g_Wh);

    zero_count<<<1, 1>>>();
    conv_all<<<(M_DIM + N_DIM) * (K_DIM / 4) / 256, 256>>>(x, w, xh, wh);

    // Gate (classify + uncertain list), then exact fixup -> mask final
    dim3 gateGrid(N_DIM / (GBN_SUB * G_NSUB), M_DIM / GBM);   // (32, 64)
    gate_gemm<<<gateGrid, 256, SMEM_GATE>>>();
    fixup_kernel<<<512, 256>>>(x, w);

    // Full-K value GEMM with fused mask+bias epilogue
    dim3 bigGrid(N_DIM / BN, M_DIM / BM);      // (16, 64)
    big_gemm<<<bigGrid, 256, SMEM_BIG>>>(out, bv);
}

// round 12
// speedup vs baseline: 1.7263x; 1.0266x over previous
#include <cuda_runtime.h>
#include <cuda_fp16.h>
#include <cstdint>

// ---------------------------------------------------------------------------
// Problem shape (fixed by setup_inputs: B=4, S=2048, K=4096, N=4096)
// ---------------------------------------------------------------------------
namespace {
constexpr int M_DIM = 8192;
constexpr int N_DIM = 4096;
constexpr int K_DIM = 4096;
constexpr int K0C   = 256;
constexpr float TAU = 3.0f;
constexpr float EPS = 1e-6f;
constexpr float BAND = 0.05f;              // gate uncertainty band on t (~8 sigma)

// Big GEMM tiling: CTA 128x256, 8 warps (2m x 4n), warp 64x64, BK=64
constexpr int BM = 128;
constexpr int BN = 256;
constexpr int BK = 64;
constexpr int NCHUNK = K_DIM / BK;          // 64
constexpr int STAGE_A = BM * 128;           // 16384
constexpr int STAGE_B = BN * 128;           // 32768
constexpr int STAGE_BYTES = STAGE_A + STAGE_B;     // 49152
constexpr int NSTAGE = 4;
constexpr int SMEM_BIG = NSTAGE * STAGE_BYTES;     // 196608

// Gate: CTA covers 128m x 128n as 2 sub-tiles of 64n. A-head (128x256 fp16,
// 64KB) resident for the whole CTA; B in a 4-stage ring of 8KB chunks.
constexpr int GBM = 128;
constexpr int GBN_SUB = 64;
constexpr int G_NSUB = 2;
constexpr int G_NITER = 4 * G_NSUB;          // 8 chunk-iterations
constexpr int G_A_BYTES = 4 * GBM * 128;     // 65536 (4 chunks x 16KB)
constexpr int G_B_STAGE = GBN_SUB * 128;     // 8192
constexpr int G_B_OFF   = G_A_BYTES;         // 65536
constexpr int G_MASK_OFF = G_B_OFF + 4 * G_B_STAGE;   // 98304 (8KB stage)
constexpr int G_LBUF_OFF = G_MASK_OFF + GBM * GBN_SUB; // 106496 (1024 x u32)
constexpr int G_LBUF_CAP = 1024;
constexpr int G_LCOUNT_OFF = G_LBUF_OFF + G_LBUF_CAP * 4;  // 110592
constexpr int G_LBASE_OFF  = G_LCOUNT_OFF + 4;             // 110596
constexpr int G_LNUM_OFF   = G_LBASE_OFF + 4;              // 110600
constexpr int SMEM_GATE = 110608;            // 2 CTAs/SM: 221216 <= 228KB

constexpr int LIST_CAP = 1 << 25;           // 33.5M (full-size safe)
}

// ---------------------------------------------------------------------------
// Device scratch (static; no dynamic allocation allowed)
// ---------------------------------------------------------------------------
__device__ __align__(1024) unsigned char g_mask[(size_t)M_DIM * N_DIM];
__device__ __align__(1024) __half        g_Xh[(size_t)M_DIM * K_DIM];
__device__ __align__(1024) __half        g_Wh[(size_t)N_DIM * K_DIM];
__device__ __align__(1024) uint32_t      g_list[LIST_CAP];
__device__ int                           g_count;

// ---------------------------------------------------------------------------
// Helpers (base-ISA only: cp.async / ldmatrix / mma.sync)
// ---------------------------------------------------------------------------
__device__ __forceinline__ uint32_t smem_u32(const void* p) {
    uint32_t a;
    asm("{ .reg .u64 t; cvta.to.shared.u64 t, %1; cvt.u32.u64 %0, t; }" : "=r"(a) : "l"(p));
    return a;
}
#define SWZ128(off) ((off) ^ (((off) >> 3) & 0x70))

__device__ __forceinline__ void cp_async16(uint32_t dst, const void* src) {
    asm volatile("cp.async.cg.shared.global [%0], [%1], 16;"
                 :: "r"(dst), "l"(__cvta_generic_to_global(src)) : "memory");
}
#define CP_COMMIT() asm volatile("cp.async.commit_group;" ::: "memory")
#define CP_WAIT2()  asm volatile("cp.async.wait_group 2;" ::: "memory")

__device__ __forceinline__ void ldsm_x4(uint32_t& r0, uint32_t& r1, uint32_t& r2,
                                        uint32_t& r3, uint32_t addr) {
    asm volatile("ldmatrix.sync.aligned.m8n8.x4.shared.b16 {%0,%1,%2,%3}, [%4];"
                 : "=r"(r0), "=r"(r1), "=r"(r2), "=r"(r3) : "r"(addr));
}
__device__ __forceinline__ void mma_fp16(float* c, const uint32_t* a,
                                         uint32_t b0, uint32_t b1) {
    asm volatile("mma.sync.aligned.m16n8k16.row.col.f32.f16.f16.f32 "
                 "{%0,%1,%2,%3}, {%4,%5,%6,%7}, {%8,%9}, {%0,%1,%2,%3};"
                 : "+f"(c[0]), "+f"(c[1]), "+f"(c[2]), "+f"(c[3])
                 : "r"(a[0]), "r"(a[1]), "r"(a[2]), "r"(a[3]), "r"(b0), "r"(b1));
}
__device__ __forceinline__ uint32_t sq_h2(uint32_t v) {
    uint32_t r;
    asm("mul.rn.f16x2 %0, %1, %1;" : "=r"(r) : "r"(v));
    return r;
}

// ---------------------------------------------------------------------------
// Zero the uncertain-list counter (determinism across graph replays)
// ---------------------------------------------------------------------------
__global__ void zero_count() { g_count = 0; }

// ---------------------------------------------------------------------------
// Convert: fp32 -> fp16 (RN) for both X and W. 16 floats per thread
// (4x float4 read, 2x uint4 write) for MLP=4 latency coverage.
// ---------------------------------------------------------------------------
__global__ __launch_bounds__(256)
void conv_all(const float* __restrict__ X, const float* __restrict__ W)
{
    int idx = blockIdx.x * 256 + threadIdx.x;      // one 16-float slab per thread
    int r   = idx >> 8;                             // 256 slabs per row
    int c   = (idx & 255) * 16;
    const float* src; __half* dst; int row;
    if (r < M_DIM) { src = X; dst = g_Xh; row = r; }
    else           { src = W; dst = g_Wh; row = r - M_DIM; }
    const float4* s = reinterpret_cast<const float4*>(src + (size_t)row * K_DIM + c);
    float4 v0 = s[0], v1 = s[1], v2 = s[2], v3 = s[3];
    uint32_t o[8];
    __half2 h;
    h = __floats2half2_rn(v0.x, v0.y); o[0] = *reinterpret_cast<uint32_t*>(&h);
    h = __floats2half2_rn(v0.z, v0.w); o[1] = *reinterpret_cast<uint32_t*>(&h);
    h = __floats2half2_rn(v1.x, v1.y); o[2] = *reinterpret_cast<uint32_t*>(&h);
    h = __floats2half2_rn(v1.z, v1.w); o[3] = *reinterpret_cast<uint32_t*>(&h);
    h = __floats2half2_rn(v2.x, v2.y); o[4] = *reinterpret_cast<uint32_t*>(&h);
    h = __floats2half2_rn(v2.z, v2.w); o[5] = *reinterpret_cast<uint32_t*>(&h);
    h = __floats2half2_rn(v3.x, v3.y); o[6] = *reinterpret_cast<uint32_t*>(&h);
    h = __floats2half2_rn(v3.z, v3.w); o[7] = *reinterpret_cast<uint32_t*>(&h);
    uint4* d = reinterpret_cast<uint4*>(dst + (size_t)row * K_DIM + c);
    d[0] = make_uint4(o[0], o[1], o[2], o[3]);
    d[1] = make_uint4(o[4], o[5], o[6], o[7]);
}

// ---------------------------------------------------------------------------
// Big GEMM + fused merge: Out = bias + (mask ? Xh@Wh^T : 0) over full K=4096.
// CTA 128x256, warp 64x64, 4-stage ring, prefetch distance 2, ONE sync/chunk.
// Epilogue v2: mask tile (32KB) + bias row (1KB) staged coalesced into the
// dead stage buffers, then read via LDS (no scattered global byte loads).
// ---------------------------------------------------------------------------
__global__ __launch_bounds__(256, 1)
void big_gemm(float* __restrict__ Out, const float* __restrict__ Bv)
{
    extern __shared__ __align__(1024) char smem[];
    const uint32_t sbase = smem_u32(smem);
    const int tid  = threadIdx.x;
    const int wid  = tid >> 5;
    const int lane = tid & 31;

    const int bm = blockIdx.y * BM;
    const int bn = blockIdx.x * BN;

    const int warpM = (wid & 1) * 64;
    const int warpN = (wid >> 1) * 64;

    const int subl = lane >> 3;
    const int tr   = lane & 7;
    const int aRow = (subl & 1) * 8 + tr;
    const int aK8  = (subl >> 1);
    const int bRow = (subl >> 1) * 8 + tr;
    const int bK8  = (subl & 1);

    float acc[4][8][4];
    #pragma unroll
    for (int i = 0; i < 4; ++i)
        #pragma unroll
        for (int j = 0; j < 8; ++j)
            #pragma unroll
            for (int q = 0; q < 4; ++q) acc[i][j][q] = 0.0f;

    auto load_chunk = [&](int it, int buf) {
        const __half* Ap = g_Xh + (size_t)bm * K_DIM + it * BK;
        const __half* Bp = g_Wh + (size_t)bn * K_DIM + it * BK;
        const uint32_t aOff = buf * STAGE_BYTES;
        const uint32_t bOff = aOff + STAGE_A;
        #pragma unroll
        for (int l = 0; l < 4; ++l) {
            int idx = tid + l * 256;
            int r = idx >> 3, c = idx & 7;
            cp_async16(sbase + aOff + SWZ128((uint32_t)(r * 128 + c * 16)),
                       Ap + (size_t)r * K_DIM + c * 8);
        }
        #pragma unroll
        for (int l = 0; l < 8; ++l) {
            int idx = tid + l * 256;
            int r = idx >> 3, c = idx & 7;
            cp_async16(sbase + bOff + SWZ128((uint32_t)(r * 128 + c * 16)),
                       Bp + (size_t)r * K_DIM + c * 8);
        }
    };

    load_chunk(0, 0); CP_COMMIT();
    load_chunk(1, 1); CP_COMMIT();

    int buf = 0;
    for (int it = 0; it < NCHUNK; ++it) {
        if (it + 2 < NCHUNK) {
            int nb = buf + 2; if (nb >= NSTAGE) nb -= NSTAGE;
            load_chunk(it + 2, nb);
        }
        CP_COMMIT();
        CP_WAIT2();
        __syncthreads();

        const uint32_t aBase = sbase + buf * STAGE_BYTES;
        const uint32_t bBase = aBase + STAGE_A;

        #pragma unroll
        for (int ks = 0; ks < 4; ++ks) {
            uint32_t afrag[4][4];
            #pragma unroll
            for (int mi = 0; mi < 4; ++mi) {
                int row = warpM + mi * 16 + aRow;
                uint32_t byte = (uint32_t)(row * 128) +
                                ((uint32_t)((ks * 2 + aK8) * 16) ^ ((row & 7) * 16));
                ldsm_x4(afrag[mi][0], afrag[mi][1], afrag[mi][2], afrag[mi][3],
                        aBase + byte);
            }
            #pragma unroll
            for (int pr = 0; pr < 4; ++pr) {
                int row = warpN + pr * 16 + bRow;
                uint32_t byte = (uint32_t)(row * 128) +
                                ((uint32_t)((ks * 2 + bK8) * 16) ^ ((row & 7) * 16));
                uint32_t b0, b1, b2, b3;
                ldsm_x4(b0, b1, b2, b3, bBase + byte);
                #pragma unroll
                for (int mi = 0; mi < 4; ++mi) {
                    mma_fp16(acc[mi][pr * 2 + 0], afrag[mi], b0, b1);
                    mma_fp16(acc[mi][pr * 2 + 1], afrag[mi], b2, b3);
                }
            }
        }
        ++buf; if (buf == NSTAGE) buf = 0;
    }

    // ---- epilogue: stage mask tile + bias row into (dead) smem buffers ----
    __syncthreads();   // all warps done reading stage buffers
    {
        #pragma unroll
        for (int l = 0; l < 8; ++l) {                 // 2048 uint4 of mask
            int idx = tid + l * 256;
            int r = idx >> 4, c = (idx & 15) * 16;
            *reinterpret_cast<uint4*>(smem + r * 256 + c) =
                *reinterpret_cast<const uint4*>(g_mask + (size_t)(bm + r) * N_DIM + bn + c);
        }
        if (tid < 64) {                               // 256 bias floats
            *reinterpret_cast<float4*>(smem + 32768 + tid * 16) =
                *reinterpret_cast<const float4*>(Bv + bn + tid * 4);
        }
    }
    __syncthreads();
    const unsigned char* maskS = reinterpret_cast<const unsigned char*>(smem);
    const float*         biasS = reinterpret_cast<const float*>(smem + 32768);

    const int mrow = lane >> 2;
    const int ncol = (lane & 3) * 2;
    #pragma unroll
    for (int mi = 0; mi < 4; ++mi) {
        #pragma unroll
        for (int ni = 0; ni < 8; ++ni) {
            const int mr = warpM + mi * 16 + mrow;       // 0..127 (local)
            const int nc = warpN + ni * 8 + ncol;        // 0..254 (local)
            const float bx = biasS[nc];
            const float by = biasS[nc + 1];
            size_t o  = (size_t)(bm + mr) * N_DIM + bn + nc;
            size_t o2 = o + (size_t)8 * N_DIM;
            float2 v0, v1;
            v0.x = bx + (maskS[mr * 256 + nc]           ? acc[mi][ni][0] : 0.0f);
            v0.y = by + (maskS[mr * 256 + nc + 1]       ? acc[mi][ni][1] : 0.0f);
            v1.x = bx + (maskS[(mr + 8) * 256 + nc]     ? acc[mi][ni][2] : 0.0f);
            v1.y = by + (maskS[(mr + 8) * 256 + nc + 1] ? acc[mi][ni][3] : 0.0f);
            *reinterpret_cast<float2*>(&Out[o])  = v0;
            *reinterpret_cast<float2*>(&Out[o2]) = v1;
        }
    }
}

// ---------------------------------------------------------------------------
// Gate GEMM v3 (unchanged from R11): A-head resident, 2 N-sub-tiles per CTA,
// 4-stage B ring, squares in registers, coalesced mask staging,
// CTA-aggregated uncertain list.
// ---------------------------------------------------------------------------
__global__ __launch_bounds__(256, 2)
void gate_gemm()
{
    extern __shared__ __align__(1024) char smem[];
    const uint32_t sbase = smem_u32(smem);
    const int tid  = threadIdx.x;
    const int wid  = tid >> 5;
    const int lane = tid & 31;

    const int bm = blockIdx.y * GBM;
    const int bn = blockIdx.x * (GBN_SUB * G_NSUB);

    const int warpM = (wid & 3) * 32;
    const int warpN = (wid >> 2) * 32;

    const int subl = lane >> 3;
    const int tr   = lane & 7;
    const int aRow = (subl & 1) * 8 + tr;
    const int aK8  = (subl >> 1);
    const int bRow = (subl >> 1) * 8 + tr;
    const int bK8  = (subl & 1);

    unsigned char* stage = reinterpret_cast<unsigned char*>(smem + G_MASK_OFF);
    uint32_t* lbuf  = reinterpret_cast<uint32_t*>(smem + G_LBUF_OFF);
    int* lcount = reinterpret_cast<int*>(smem + G_LCOUNT_OFF);
    int* lbase  = reinterpret_cast<int*>(smem + G_LBASE_OFF);
    int* lnum   = reinterpret_cast<int*>(smem + G_LNUM_OFF);
    if (tid == 0) *lcount = 0;

    float accY[2][4][4], accS[2][4][4];
    #pragma unroll
    for (int i = 0; i < 2; ++i)
        #pragma unroll
        for (int j = 0; j < 4; ++j)
            #pragma unroll
            for (int q = 0; q < 4; ++q) { accY[i][j][q] = 0.0f; accS[i][j][q] = 0.0f; }

    {
        #pragma unroll
        for (int l = 0; l < 16; ++l) {
            int idx = tid + l * 256;
            int chunk = idx >> 10;
            int line  = idx & 1023;
            int r = line >> 3, c = line & 7;
            cp_async16(sbase + chunk * 16384 + SWZ128((uint32_t)(r * 128 + c * 16)),
                       g_Xh + (size_t)(bm + r) * K_DIM + chunk * 64 + c * 8);
        }
    }

    auto load_B = [&](int it) {
        int sub = it >> 2, ck = it & 3;
        const __half* Bp = g_Wh + (size_t)(bn + sub * GBN_SUB) * K_DIM + ck * 64;
        const uint32_t s0 = G_B_OFF + (it & 3) * G_B_STAGE;
        #pragma unroll
        for (int l = 0; l < 2; ++l) {
            int idx = tid + l * 256;
            int r = idx >> 3, c = idx & 7;
            cp_async16(sbase + s0 + SWZ128((uint32_t)(r * 128 + c * 16)),
                       Bp + (size_t)r * K_DIM + c * 8);
        }
    };

    load_B(0); CP_COMMIT();
    load_B(1); CP_COMMIT();

    for (int it = 0; it < G_NITER; ++it) {
        if (it + 2 < G_NITER) load_B(it + 2);
        CP_COMMIT();
        CP_WAIT2();
        __syncthreads();

        const uint32_t aBase = sbase + (it & 3) * 16384;
        const uint32_t bBase = sbase + G_B_OFF + (it & 3) * G_B_STAGE;

        #pragma unroll
        for (int ks = 0; ks < 4; ++ks) {
            uint32_t ah[2][4], aq[2][4];
            #pragma unroll
            for (int mi = 0; mi < 2; ++mi) {
                int row = warpM + mi * 16 + aRow;
                uint32_t byte = (uint32_t)(row * 128) +
                                ((uint32_t)((ks * 2 + aK8) * 16) ^ ((row & 7) * 16));
                ldsm_x4(ah[mi][0], ah[mi][1], ah[mi][2], ah[mi][3], aBase + byte);
                #pragma unroll
                for (int r = 0; r < 4; ++r) aq[mi][r] = sq_h2(ah[mi][r]);
            }
            #pragma unroll
            for (int pr = 0; pr < 2; ++pr) {
                int row = warpN + pr * 16 + bRow;
                uint32_t byte = (uint32_t)(row * 128) +
                                ((uint32_t)((ks * 2 + bK8) * 16) ^ ((row & 7) * 16));
                uint32_t h0, h1, h2, h3;
                ldsm_x4(h0, h1, h2, h3, bBase + byte);
                uint32_t q0 = sq_h2(h0), q1 = sq_h2(h1);
                uint32_t q2 = sq_h2(h2), q3 = sq_h2(h3);
                #pragma unroll
                for (int mi = 0; mi < 2; ++mi) {
                    mma_fp16(accY[mi][pr * 2 + 0], ah[mi], h0, h1);
                    mma_fp16(accY[mi][pr * 2 + 1], ah[mi], h2, h3);
                    mma_fp16(accS[mi][pr * 2 + 0], aq[mi], q0, q1);
                    mma_fp16(accS[mi][pr * 2 + 1], aq[mi], q2, q3);
                }
            }
        }

        if ((it & 3) == 3) {
            const int sub = it >> 2;
            const int mrow = lane >> 2;
            const int ncol = (lane & 3) * 2;
            #pragma unroll
            for (int mi = 0; mi < 2; ++mi)
                #pragma unroll
                for (int ni = 0; ni < 4; ++ni)
                    #pragma unroll
                    for (int h = 0; h < 2; ++h) {
                        const int mr = warpM + mi * 16 + mrow + h * 8;
                        const int nc = warpN + ni * 8 + ncol;
                        #pragma unroll
                        for (int q = 0; q < 2; ++q) {
                            float y = accY[mi][ni][h * 2 + q];
                            float s = accS[mi][ni][h * 2 + q];
                            float denom = sqrtf(s * (1.0f / 256.0f) + EPS);
                            float t = fabsf(y) / fmaxf(denom, EPS);
                            unsigned char mv;
                            if (t < TAU - BAND)      mv = 0;
                            else if (t > TAU + BAND) mv = 1;
                            else {
                                mv = 1;
                                int li = atomicAdd(lcount, 1);
                                uint32_t pk = ((uint32_t)(bm + mr) << 12) |
                                              (uint32_t)(bn + sub * GBN_SUB + nc + q);
                                if (li < G_LBUF_CAP) lbuf[li] = pk;
                                else {
                                    int gi = atomicAdd(&g_count, 1);
                                    if (gi < LIST_CAP) g_list[gi] = pk;
                                }
                            }
                            stage[mr * 64 + nc + q] = mv;
                        }
                    }
            __syncthreads();
            {
                int mr = tid >> 1, half = (tid & 1) * 32;
                uint4 v0 = *reinterpret_cast<uint4*>(stage + mr * 64 + half);
                uint4 v1 = *reinterpret_cast<uint4*>(stage + mr * 64 + half + 16);
                size_t go = (size_t)(bm + mr) * N_DIM + bn + sub * GBN_SUB + half;
                *reinterpret_cast<uint4*>(g_mask + go)      = v0;
                *reinterpret_cast<uint4*>(g_mask + go + 16) = v1;
            }
            if (tid == 0) {
                int ln = *lcount; if (ln > G_LBUF_CAP) ln = G_LBUF_CAP;
                *lbase = atomicAdd(&g_count, ln);
                *lnum  = ln;
                *lcount = 0;
            }
            __syncthreads();
            {
                int ln = *lnum, base = *lbase;
                for (int i = tid; i < ln; i += 256) {
                    int gi = base + i;
                    if (gi < LIST_CAP) g_list[gi] = lbuf[i];
                }
            }
            #pragma unroll
            for (int i = 0; i < 2; ++i)
                #pragma unroll
                for (int j = 0; j < 4; ++j)
                    #pragma unroll
                    for (int q = 0; q < 4; ++q) { accY[i][j][q] = 0.0f; accS[i][j][q] = 0.0f; }
        }
    }
}

// ---------------------------------------------------------------------------
// Fixup: exact fp32 recompute of y1/s2 for uncertain elements (1 warp each).
// ---------------------------------------------------------------------------
__global__ __launch_bounds__(256)
void fixup_kernel(const float* __restrict__ X, const float* __restrict__ W)
{
    const int lane = threadIdx.x & 31;
    const int wglobal = (blockIdx.x * 256 + threadIdx.x) >> 5;
    const int nwarps = (gridDim.x * 256) >> 5;
    int total = g_count; if (total > LIST_CAP) total = LIST_CAP;

    for (int i = wglobal; i < total; i += nwarps) {
        uint32_t p = g_list[i];
        int m = p >> 12;
        int n = p & 4095;
        const float* xr = X + (size_t)m * K_DIM;
        const float* wr = W + (size_t)n * K_DIM;
        float y = 0.0f, s = 0.0f;
        #pragma unroll
        for (int j = 0; j < 2; ++j) {
            float4 a = *reinterpret_cast<const float4*>(xr + lane * 8 + j * 4);
            float4 b = *reinterpret_cast<const float4*>(wr + lane * 8 + j * 4);
            y = fmaf(a.x, b.x, y); y = fmaf(a.y, b.y, y);
            y = fmaf(a.z, b.z, y); y = fmaf(a.w, b.w, y);
            float px = a.x * b.x, py = a.y * b.y, pz = a.z * b.z, pw = a.w * b.w;
            s = fmaf(px, px, s); s = fmaf(py, py, s);
            s = fmaf(pz, pz, s); s = fmaf(pw, pw, s);
        }
        #pragma unroll
        for (int off = 16; off > 0; off >>= 1) {
            y += __shfl_xor_sync(0xFFFFFFFF, y, off);
            s += __shfl_xor_sync(0xFFFFFFFF, s, off);
        }
        if (lane == 0) {
            float denom = sqrtf(s * (1.0f / 256.0f) + EPS);
            float t = fabsf(y) / fmaxf(denom, EPS);
            g_mask[(size_t)m * N_DIM + n] = (t < TAU) ? 0 : 1;
        }
    }
}

// ---------------------------------------------------------------------------
extern "C" void kernel_launch(void* const* d_in, const int* in_sizes, int n_in,
                              void* d_out, int out_size)
{
    const float* x  = (const float*)d_in[0];   // [8192, 4096]
    const float* w  = (const float*)d_in[1];   // [4096, 4096]
    const float* bv = (const float*)d_in[2];   // [4096]
    float* out      = (float*)d_out;           // [8192, 4096]
    (void)in_sizes; (void)n_in; (void)out_size;

    cudaFuncSetAttribute(big_gemm,
                         cudaFuncAttributeMaxDynamicSharedMemorySize, SMEM_BIG);
    cudaFuncSetAttribute(gate_gemm,
                         cudaFuncAttributeMaxDynamicSharedMemorySize, SMEM_GATE);

    zero_count<<<1, 1>>>();
    conv_all<<<(M_DIM + N_DIM) * 256 / 256, 256>>>(x, w);   // 12288 blocks

    // Gate (classify + uncertain list), then exact fixup -> mask final
    dim3 gateGrid(N_DIM / (GBN_SUB * G_NSUB), M_DIM / GBM);   // (32, 64)
    gate_gemm<<<gateGrid, 256, SMEM_GATE>>>();
    fixup_kernel<<<512, 256>>>(x, w);

    // Full-K value GEMM with fused mask+bias epilogue
    dim3 bigGrid(N_DIM / BN, M_DIM / BM);      // (16, 64)
    big_gemm<<<bigGrid, 256, SMEM_BIG>>>(out, bv);
}

// round 13
// speedup vs baseline: 1.7337x; 1.0043x over previous
#include <cuda_runtime.h>
#include <cuda_fp16.h>
#include <cstdint>

// ---------------------------------------------------------------------------
// Problem shape (fixed by setup_inputs: B=4, S=2048, K=4096, N=4096)
// ---------------------------------------------------------------------------
namespace {
constexpr int M_DIM = 8192;
constexpr int N_DIM = 4096;
constexpr int K_DIM = 4096;
constexpr int K0C   = 256;
constexpr float TAU = 3.0f;
constexpr float EPS = 1e-6f;
constexpr float BAND = 0.05f;              // gate uncertainty band on t (~8 sigma)

// Big GEMM tiling: CTA 128x256, 8 warps (2m x 4n), warp 64x64, BK=64
constexpr int BM = 128;
constexpr int BN = 256;
constexpr int BK = 64;
constexpr int NCHUNK = K_DIM / BK;          // 64
constexpr int STAGE_A = BM * 128;           // 16384
constexpr int STAGE_B = BN * 128;           // 32768
constexpr int STAGE_BYTES = STAGE_A + STAGE_B;     // 49152
constexpr int NSTAGE = 4;
constexpr int SMEM_BIG = NSTAGE * STAGE_BYTES;     // 196608

// Gate: CTA covers 128m x 128n as 2 sub-tiles of 64n. A-head (128x256 fp16,
// 64KB) resident for the whole CTA; B in a 4-stage ring of 8KB chunks.
constexpr int GBM = 128;
constexpr int GBN_SUB = 64;
constexpr int G_NSUB = 2;
constexpr int G_NITER = 4 * G_NSUB;          // 8 chunk-iterations
constexpr int G_A_BYTES = 4 * GBM * 128;     // 65536 (4 chunks x 16KB)
constexpr int G_B_STAGE = GBN_SUB * 128;     // 8192
constexpr int G_B_OFF   = G_A_BYTES;         // 65536
constexpr int G_MASK_OFF = G_B_OFF + 4 * G_B_STAGE;   // 98304 (8KB stage)
constexpr int G_LBUF_OFF = G_MASK_OFF + GBM * GBN_SUB; // 106496 (1024 x u32)
constexpr int G_LBUF_CAP = 1024;
constexpr int G_LCOUNT_OFF = G_LBUF_OFF + G_LBUF_CAP * 4;  // 110592
constexpr int G_LBASE_OFF  = G_LCOUNT_OFF + 4;             // 110596
constexpr int G_LNUM_OFF   = G_LBASE_OFF + 4;              // 110600
constexpr int SMEM_GATE = 110608;            // 2 CTAs/SM: 221216 <= 228KB

constexpr int LIST_CAP = 1 << 25;           // 33.5M (full-size safe)
}

// ---------------------------------------------------------------------------
// Device scratch (static; no dynamic allocation allowed)
// ---------------------------------------------------------------------------
__device__ __align__(1024) unsigned char g_mask[(size_t)M_DIM * N_DIM];
__device__ __align__(1024) __half        g_Xh[(size_t)M_DIM * K_DIM];
__device__ __align__(1024) __half        g_Wh[(size_t)N_DIM * K_DIM];
__device__ __align__(1024) uint32_t      g_list[LIST_CAP];
__device__ int                           g_count;

// ---------------------------------------------------------------------------
// Helpers (base-ISA only: cp.async / ldmatrix / mma.sync)
// ---------------------------------------------------------------------------
__device__ __forceinline__ uint32_t smem_u32(const void* p) {
    uint32_t a;
    asm("{ .reg .u64 t; cvta.to.shared.u64 t, %1; cvt.u32.u64 %0, t; }" : "=r"(a) : "l"(p));
    return a;
}
#define SWZ128(off) ((off) ^ (((off) >> 3) & 0x70))

__device__ __forceinline__ void cp_async16(uint32_t dst, const void* src) {
    asm volatile("cp.async.cg.shared.global [%0], [%1], 16;"
                 :: "r"(dst), "l"(__cvta_generic_to_global(src)) : "memory");
}
#define CP_COMMIT() asm volatile("cp.async.commit_group;" ::: "memory")
#define CP_WAIT2()  asm volatile("cp.async.wait_group 2;" ::: "memory")

__device__ __forceinline__ void ldsm_x4(uint32_t& r0, uint32_t& r1, uint32_t& r2,
                                        uint32_t& r3, uint32_t addr) {
    asm volatile("ldmatrix.sync.aligned.m8n8.x4.shared.b16 {%0,%1,%2,%3}, [%4];"
                 : "=r"(r0), "=r"(r1), "=r"(r2), "=r"(r3) : "r"(addr));
}
__device__ __forceinline__ void mma_fp16(float* c, const uint32_t* a,
                                         uint32_t b0, uint32_t b1) {
    asm volatile("mma.sync.aligned.m16n8k16.row.col.f32.f16.f16.f32 "
                 "{%0,%1,%2,%3}, {%4,%5,%6,%7}, {%8,%9}, {%0,%1,%2,%3};"
                 : "+f"(c[0]), "+f"(c[1]), "+f"(c[2]), "+f"(c[3])
                 : "r"(a[0]), "r"(a[1]), "r"(a[2]), "r"(a[3]), "r"(b0), "r"(b1));
}
__device__ __forceinline__ uint32_t sq_h2(uint32_t v) {
    uint32_t r;
    asm("mul.rn.f16x2 %0, %1, %1;" : "=r"(r) : "r"(v));
    return r;
}

// ---------------------------------------------------------------------------
// Convert: fp32 -> fp16 (RN) for both X and W. 16 floats per thread
// (4x float4 read, 2x uint4 write) for MLP=4 latency coverage.
// Also zeroes g_count (block 0 / thread 0) — saves a separate launch.
// ---------------------------------------------------------------------------
__global__ __launch_bounds__(256)
void conv_all(const float* __restrict__ X, const float* __restrict__ W)
{
    if (blockIdx.x == 0 && threadIdx.x == 0) g_count = 0;
    int idx = blockIdx.x * 256 + threadIdx.x;      // one 16-float slab per thread
    int r   = idx >> 8;                             // 256 slabs per row
    int c   = (idx & 255) * 16;
    const float* src; __half* dst; int row;
    if (r < M_DIM) { src = X; dst = g_Xh; row = r; }
    else           { src = W; dst = g_Wh; row = r - M_DIM; }
    const float4* s = reinterpret_cast<const float4*>(src + (size_t)row * K_DIM + c);
    float4 v0 = s[0], v1 = s[1], v2 = s[2], v3 = s[3];
    uint32_t o[8];
    __half2 h;
    h = __floats2half2_rn(v0.x, v0.y); o[0] = *reinterpret_cast<uint32_t*>(&h);
    h = __floats2half2_rn(v0.z, v0.w); o[1] = *reinterpret_cast<uint32_t*>(&h);
    h = __floats2half2_rn(v1.x, v1.y); o[2] = *reinterpret_cast<uint32_t*>(&h);
    h = __floats2half2_rn(v1.z, v1.w); o[3] = *reinterpret_cast<uint32_t*>(&h);
    h = __floats2half2_rn(v2.x, v2.y); o[4] = *reinterpret_cast<uint32_t*>(&h);
    h = __floats2half2_rn(v2.z, v2.w); o[5] = *reinterpret_cast<uint32_t*>(&h);
    h = __floats2half2_rn(v3.x, v3.y); o[6] = *reinterpret_cast<uint32_t*>(&h);
    h = __floats2half2_rn(v3.z, v3.w); o[7] = *reinterpret_cast<uint32_t*>(&h);
    uint4* d = reinterpret_cast<uint4*>(dst + (size_t)row * K_DIM + c);
    d[0] = make_uint4(o[0], o[1], o[2], o[3]);
    d[1] = make_uint4(o[4], o[5], o[6], o[7]);
}

// ---------------------------------------------------------------------------
// Big GEMM + fused merge: Out = bias + (mask ? Xh@Wh^T : 0) over full K=4096.
// CTA 128x256, warp 64x64, 4-stage smem ring (distance 2), ONE sync/chunk.
// NEW: register-level fragment double-buffering — while MMAs consume k-step
// `cur`, the 8 LDSMs for `ks+1` issue into the other buffer, hiding LDS
// latency that 2 warps/SMSP cannot otherwise cover.
// Epilogue: mask tile + bias row staged into dead smem, read via LDS.
// ---------------------------------------------------------------------------
__global__ __launch_bounds__(256, 1)
void big_gemm(float* __restrict__ Out, const float* __restrict__ Bv)
{
    extern __shared__ __align__(1024) char smem[];
    const uint32_t sbase = smem_u32(smem);
    const int tid  = threadIdx.x;
    const int wid  = tid >> 5;
    const int lane = tid & 31;

    const int bm = blockIdx.y * BM;
    const int bn = blockIdx.x * BN;

    const int warpM = (wid & 1) * 64;
    const int warpN = (wid >> 1) * 64;

    const int subl = lane >> 3;
    const int tr   = lane & 7;
    const int aRow = (subl & 1) * 8 + tr;
    const int aK8  = (subl >> 1);
    const int bRow = (subl >> 1) * 8 + tr;
    const int bK8  = (subl & 1);

    float acc[4][8][4];
    #pragma unroll
    for (int i = 0; i < 4; ++i)
        #pragma unroll
        for (int j = 0; j < 8; ++j)
            #pragma unroll
            for (int q = 0; q < 4; ++q) acc[i][j][q] = 0.0f;

    auto load_chunk = [&](int it, int buf) {
        const __half* Ap = g_Xh + (size_t)bm * K_DIM + it * BK;
        const __half* Bp = g_Wh + (size_t)bn * K_DIM + it * BK;
        const uint32_t aOff = buf * STAGE_BYTES;
        const uint32_t bOff = aOff + STAGE_A;
        #pragma unroll
        for (int l = 0; l < 4; ++l) {
            int idx = tid + l * 256;
            int r = idx >> 3, c = idx & 7;
            cp_async16(sbase + aOff + SWZ128((uint32_t)(r * 128 + c * 16)),
                       Ap + (size_t)r * K_DIM + c * 8);
        }
        #pragma unroll
        for (int l = 0; l < 8; ++l) {
            int idx = tid + l * 256;
            int r = idx >> 3, c = idx & 7;
            cp_async16(sbase + bOff + SWZ128((uint32_t)(r * 128 + c * 16)),
                       Bp + (size_t)r * K_DIM + c * 8);
        }
    };

    load_chunk(0, 0); CP_COMMIT();
    load_chunk(1, 1); CP_COMMIT();

    uint32_t af[2][4][4], bf[2][4][4];

    auto load_frags = [&](int ks, int slot, uint32_t aBase, uint32_t bBase) {
        #pragma unroll
        for (int mi = 0; mi < 4; ++mi) {
            int row = warpM + mi * 16 + aRow;
            uint32_t byte = (uint32_t)(row * 128) +
                            ((uint32_t)((ks * 2 + aK8) * 16) ^ ((row & 7) * 16));
            ldsm_x4(af[slot][mi][0], af[slot][mi][1],
                    af[slot][mi][2], af[slot][mi][3], aBase + byte);
        }
        #pragma unroll
        for (int pr = 0; pr < 4; ++pr) {
            int row = warpN + pr * 16 + bRow;
            uint32_t byte = (uint32_t)(row * 128) +
                            ((uint32_t)((ks * 2 + bK8) * 16) ^ ((row & 7) * 16));
            ldsm_x4(bf[slot][pr][0], bf[slot][pr][1],
                    bf[slot][pr][2], bf[slot][pr][3], bBase + byte);
        }
    };

    int buf = 0;
    for (int it = 0; it < NCHUNK; ++it) {
        if (it + 2 < NCHUNK) {
            int nb = buf + 2; if (nb >= NSTAGE) nb -= NSTAGE;
            load_chunk(it + 2, nb);
        }
        CP_COMMIT();
        CP_WAIT2();
        __syncthreads();

        const uint32_t aBase = sbase + buf * STAGE_BYTES;
        const uint32_t bBase = aBase + STAGE_A;

        load_frags(0, 0, aBase, bBase);
        #pragma unroll
        for (int ks = 0; ks < 4; ++ks) {
            const int cur = ks & 1;
            if (ks < 3) load_frags(ks + 1, cur ^ 1, aBase, bBase);
            #pragma unroll
            for (int pr = 0; pr < 4; ++pr)
                #pragma unroll
                for (int mi = 0; mi < 4; ++mi) {
                    mma_fp16(acc[mi][pr * 2 + 0], af[cur][mi],
                             bf[cur][pr][0], bf[cur][pr][1]);
                    mma_fp16(acc[mi][pr * 2 + 1], af[cur][mi],
                             bf[cur][pr][2], bf[cur][pr][3]);
                }
        }
        ++buf; if (buf == NSTAGE) buf = 0;
    }

    // ---- epilogue: stage mask tile + bias row into (dead) smem buffers ----
    __syncthreads();   // all warps done reading stage buffers
    {
        #pragma unroll
        for (int l = 0; l < 8; ++l) {                 // 2048 uint4 of mask
            int idx = tid + l * 256;
            int r = idx >> 4, c = (idx & 15) * 16;
            *reinterpret_cast<uint4*>(smem + r * 256 + c) =
                *reinterpret_cast<const uint4*>(g_mask + (size_t)(bm + r) * N_DIM + bn + c);
        }
        if (tid < 64) {                               // 256 bias floats
            *reinterpret_cast<float4*>(smem + 32768 + tid * 16) =
                *reinterpret_cast<const float4*>(Bv + bn + tid * 4);
        }
    }
    __syncthreads();
    const unsigned char* maskS = reinterpret_cast<const unsigned char*>(smem);
    const float*         biasS = reinterpret_cast<const float*>(smem + 32768);

    const int mrow = lane >> 2;
    const int ncol = (lane & 3) * 2;
    #pragma unroll
    for (int mi = 0; mi < 4; ++mi) {
        #pragma unroll
        for (int ni = 0; ni < 8; ++ni) {
            const int mr = warpM + mi * 16 + mrow;       // 0..127 (local)
            const int nc = warpN + ni * 8 + ncol;        // 0..254 (local)
            const float bx = biasS[nc];
            const float by = biasS[nc + 1];
            size_t o  = (size_t)(bm + mr) * N_DIM + bn + nc;
            size_t o2 = o + (size_t)8 * N_DIM;
            float2 v0, v1;
            v0.x = bx + (maskS[mr * 256 + nc]           ? acc[mi][ni][0] : 0.0f);
            v0.y = by + (maskS[mr * 256 + nc + 1]       ? acc[mi][ni][1] : 0.0f);
            v1.x = bx + (maskS[(mr + 8) * 256 + nc]     ? acc[mi][ni][2] : 0.0f);
            v1.y = by + (maskS[(mr + 8) * 256 + nc + 1] ? acc[mi][ni][3] : 0.0f);
            *reinterpret_cast<float2*>(&Out[o])  = v0;
            *reinterpret_cast<float2*>(&Out[o2]) = v1;
        }
    }
}

// ---------------------------------------------------------------------------
// Gate GEMM v3 (unchanged from R12): A-head resident, 2 N-sub-tiles per CTA,
// 4-stage B ring, squares in registers, coalesced mask staging,
// CTA-aggregated uncertain list.
// ---------------------------------------------------------------------------
__global__ __launch_bounds__(256, 2)
void gate_gemm()
{
    extern __shared__ __align__(1024) char smem[];
    const uint32_t sbase = smem_u32(smem);
    const int tid  = threadIdx.x;
    const int wid  = tid >> 5;
    const int lane = tid & 31;

    const int bm = blockIdx.y * GBM;
    const int bn = blockIdx.x * (GBN_SUB * G_NSUB);

    const int warpM = (wid & 3) * 32;
    const int warpN = (wid >> 2) * 32;

    const int subl = lane >> 3;
    const int tr   = lane & 7;
    const int aRow = (subl & 1) * 8 + tr;
    const int aK8  = (subl >> 1);
    const int bRow = (subl >> 1) * 8 + tr;
    const int bK8  = (subl & 1);

    unsigned char* stage = reinterpret_cast<unsigned char*>(smem + G_MASK_OFF);
    uint32_t* lbuf  = reinterpret_cast<uint32_t*>(smem + G_LBUF_OFF);
    int* lcount = reinterpret_cast<int*>(smem + G_LCOUNT_OFF);
    int* lbase  = reinterpret_cast<int*>(smem + G_LBASE_OFF);
    int* lnum   = reinterpret_cast<int*>(smem + G_LNUM_OFF);
    if (tid == 0) *lcount = 0;

    float accY[2][4][4], accS[2][4][4];
    #pragma unroll
    for (int i = 0; i < 2; ++i)
        #pragma unroll
        for (int j = 0; j < 4; ++j)
            #pragma unroll
            for (int q = 0; q < 4; ++q) { accY[i][j][q] = 0.0f; accS[i][j][q] = 0.0f; }

    {
        #pragma unroll
        for (int l = 0; l < 16; ++l) {
            int idx = tid + l * 256;
            int chunk = idx >> 10;
            int line  = idx & 1023;
            int r = line >> 3, c = line & 7;
            cp_async16(sbase + chunk * 16384 + SWZ128((uint32_t)(r * 128 + c * 16)),
                       g_Xh + (size_t)(bm + r) * K_DIM + chunk * 64 + c * 8);
        }
    }

    auto load_B = [&](int it) {
        int sub = it >> 2, ck = it & 3;
        const __half* Bp = g_Wh + (size_t)(bn + sub * GBN_SUB) * K_DIM + ck * 64;
        const uint32_t s0 = G_B_OFF + (it & 3) * G_B_STAGE;
        #pragma unroll
        for (int l = 0; l < 2; ++l) {
            int idx = tid + l * 256;
            int r = idx >> 3, c = idx & 7;
            cp_async16(sbase + s0 + SWZ128((uint32_t)(r * 128 + c * 16)),
                       Bp + (size_t)r * K_DIM + c * 8);
        }
    };

    load_B(0); CP_COMMIT();
    load_B(1); CP_COMMIT();

    for (int it = 0; it < G_NITER; ++it) {
        if (it + 2 < G_NITER) load_B(it + 2);
        CP_COMMIT();
        CP_WAIT2();
        __syncthreads();

        const uint32_t aBase = sbase + (it & 3) * 16384;
        const uint32_t bBase = sbase + G_B_OFF + (it & 3) * G_B_STAGE;

        #pragma unroll
        for (int ks = 0; ks < 4; ++ks) {
            uint32_t ah[2][4], aq[2][4];
            #pragma unroll
            for (int mi = 0; mi < 2; ++mi) {
                int row = warpM + mi * 16 + aRow;
                uint32_t byte = (uint32_t)(row * 128) +
                                ((uint32_t)((ks * 2 + aK8) * 16) ^ ((row & 7) * 16));
                ldsm_x4(ah[mi][0], ah[mi][1], ah[mi][2], ah[mi][3], aBase + byte);
                #pragma unroll
                for (int r = 0; r < 4; ++r) aq[mi][r] = sq_h2(ah[mi][r]);
            }
            #pragma unroll
            for (int pr = 0; pr < 2; ++pr) {
                int row = warpN + pr * 16 + bRow;
                uint32_t byte = (uint32_t)(row * 128) +
                                ((uint32_t)((ks * 2 + bK8) * 16) ^ ((row & 7) * 16));
                uint32_t h0, h1, h2, h3;
                ldsm_x4(h0, h1, h2, h3, bBase + byte);
                uint32_t q0 = sq_h2(h0), q1 = sq_h2(h1);
                uint32_t q2 = sq_h2(h2), q3 = sq_h2(h3);
                #pragma unroll
                for (int mi = 0; mi < 2; ++mi) {
                    mma_fp16(accY[mi][pr * 2 + 0], ah[mi], h0, h1);
                    mma_fp16(accY[mi][pr * 2 + 1], ah[mi], h2, h3);
                    mma_fp16(accS[mi][pr * 2 + 0], aq[mi], q0, q1);
                    mma_fp16(accS[mi][pr * 2 + 1], aq[mi], q2, q3);
                }
            }
        }

        if ((it & 3) == 3) {
            const int sub = it >> 2;
            const int mrow = lane >> 2;
            const int ncol = (lane & 3) * 2;
            #pragma unroll
            for (int mi = 0; mi < 2; ++mi)
                #pragma unroll
                for (int ni = 0; ni < 4; ++ni)
                    #pragma unroll
                    for (int h = 0; h < 2; ++h) {
                        const int mr = warpM + mi * 16 + mrow + h * 8;
                        const int nc = warpN + ni * 8 + ncol;
                        #pragma unroll
                        for (int q = 0; q < 2; ++q) {
                            float y = accY[mi][ni][h * 2 + q];
                            float s = accS[mi][ni][h * 2 + q];
                            float denom = sqrtf(s * (1.0f / 256.0f) + EPS);
                            float t = fabsf(y) / fmaxf(denom, EPS);
                            unsigned char mv;
                            if (t < TAU - BAND)      mv = 0;
                            else if (t > TAU + BAND) mv = 1;
                            else {
                                mv = 1;
                                int li = atomicAdd(lcount, 1);
                                uint32_t pk = ((uint32_t)(bm + mr) << 12) |
                                              (uint32_t)(bn + sub * GBN_SUB + nc + q);
                                if (li < G_LBUF_CAP) lbuf[li] = pk;
                                else {
                                    int gi = atomicAdd(&g_count, 1);
                                    if (gi < LIST_CAP) g_list[gi] = pk;
                                }
                            }
                            stage[mr * 64 + nc + q] = mv;
                        }
                    }
            __syncthreads();
            {
                int mr = tid >> 1, half = (tid & 1) * 32;
                uint4 v0 = *reinterpret_cast<uint4*>(stage + mr * 64 + half);
                uint4 v1 = *reinterpret_cast<uint4*>(stage + mr * 64 + half + 16);
                size_t go = (size_t)(bm + mr) * N_DIM + bn + sub * GBN_SUB + half;
                *reinterpret_cast<uint4*>(g_mask + go)      = v0;
                *reinterpret_cast<uint4*>(g_mask + go + 16) = v1;
            }
            if (tid == 0) {
                int ln = *lcount; if (ln > G_LBUF_CAP) ln = G_LBUF_CAP;
                *lbase = atomicAdd(&g_count, ln);
                *lnum  = ln;
                *lcount = 0;
            }
            __syncthreads();
            {
                int ln = *lnum, base = *lbase;
                for (int i = tid; i < ln; i += 256) {
                    int gi = base + i;
                    if (gi < LIST_CAP) g_list[gi] = lbuf[i];
                }
            }
            #pragma unroll
            for (int i = 0; i < 2; ++i)
                #pragma unroll
                for (int j = 0; j < 4; ++j)
                    #pragma unroll
                    for (int q = 0; q < 4; ++q) { accY[i][j][q] = 0.0f; accS[i][j][q] = 0.0f; }
        }
    }
}

// ---------------------------------------------------------------------------
// Fixup: exact fp32 recompute of y1/s2 for uncertain elements (1 warp each).
// ---------------------------------------------------------------------------
__global__ __launch_bounds__(256)
void fixup_kernel(const float* __restrict__ X, const float* __restrict__ W)
{
    const int lane = threadIdx.x & 31;
    const int wglobal = (blockIdx.x * 256 + threadIdx.x) >> 5;
    const int nwarps = (gridDim.x * 256) >> 5;
    int total = g_count; if (total > LIST_CAP) total = LIST_CAP;

    for (int i = wglobal; i < total; i += nwarps) {
        uint32_t p = g_list[i];
        int m = p >> 12;
        int n = p & 4095;
        const float* xr = X + (size_t)m * K_DIM;
        const float* wr = W + (size_t)n * K_DIM;
        float y = 0.0f, s = 0.0f;
        #pragma unroll
        for (int j = 0; j < 2; ++j) {
            float4 a = *reinterpret_cast<const float4*>(xr + lane * 8 + j * 4);
            float4 b = *reinterpret_cast<const float4*>(wr + lane * 8 + j * 4);
            y = fmaf(a.x, b.x, y); y = fmaf(a.y, b.y, y);
            y = fmaf(a.z, b.z, y); y = fmaf(a.w, b.w, y);
            float px = a.x * b.x, py = a.y * b.y, pz = a.z * b.z, pw = a.w * b.w;
            s = fmaf(px, px, s); s = fmaf(py, py, s);
            s = fmaf(pz, pz, s); s = fmaf(pw, pw, s);
        }
        #pragma unroll
        for (int off = 16; off > 0; off >>= 1) {
            y += __shfl_xor_sync(0xFFFFFFFF, y, off);
            s += __shfl_xor_sync(0xFFFFFFFF, s, off);
        }
        if (lane == 0) {
            float denom = sqrtf(s * (1.0f / 256.0f) + EPS);
            float t = fabsf(y) / fmaxf(denom, EPS);
            g_mask[(size_t)m * N_DIM + n] = (t < TAU) ? 0 : 1;
        }
    }
}

// ---------------------------------------------------------------------------
extern "C" void kernel_launch(void* const* d_in, const int* in_sizes, int n_in,
                              void* d_out, int out_size)
{
    const float* x  = (const float*)d_in[0];   // [8192, 4096]
    const float* w  = (const float*)d_in[1];   // [4096, 4096]
    const float* bv = (const float*)d_in[2];   // [4096]
    float* out      = (float*)d_out;           // [8192, 4096]
    (void)in_sizes; (void)n_in; (void)out_size;

    cudaFuncSetAttribute(big_gemm,
                         cudaFuncAttributeMaxDynamicSharedMemorySize, SMEM_BIG);
    cudaFuncSetAttribute(gate_gemm,
                         cudaFuncAttributeMaxDynamicSharedMemorySize, SMEM_GATE);

    conv_all<<<(M_DIM + N_DIM) * 256 / 256, 256>>>(x, w);   // 12288 blocks

    // Gate (classify + uncertain list), then exact fixup -> mask final
    dim3 gateGrid(N_DIM / (GBN_SUB * G_NSUB), M_DIM / GBM);   // (32, 64)
    gate_gemm<<<gateGrid, 256, SMEM_GATE>>>();
    fixup_kernel<<<512, 256>>>(x, w);

    // Full-K value GEMM with fused mask+bias epilogue
    dim3 bigGrid(N_DIM / BN, M_DIM / BM);      // (16, 64)
    big_gemm<<<bigGrid, 256, SMEM_BIG>>>(out, bv);
}

// round 14
// speedup vs baseline: 1.7408x; 1.0041x over previous
#include <cuda_runtime.h>
#include <cuda_fp16.h>
#include <cstdint>

// ---------------------------------------------------------------------------
// Problem shape (fixed by setup_inputs: B=4, S=2048, K=4096, N=4096)
// ---------------------------------------------------------------------------
namespace {
constexpr int M_DIM = 8192;
constexpr int N_DIM = 4096;
constexpr int K_DIM = 4096;
constexpr int K0C   = 256;
constexpr float TAU = 3.0f;
constexpr float EPS = 1e-6f;
constexpr float BAND = 0.05f;              // gate uncertainty band on t (~8 sigma)

// Big GEMM tiling: CTA 128x256, 8 warps (2m x 4n), warp 64x64, BK=128
constexpr int BM = 128;
constexpr int BN = 256;
constexpr int BK = 128;                     // fp16 K elems per chunk (2 x 64-col halves)
constexpr int NCHUNK = K_DIM / BK;          // 32
constexpr int A_STAGE = BM * 256;           // 32768 (2 halves x 16KB)
constexpr int B_STAGE = BN * 256;           // 65536 (2 halves x 32KB)
constexpr int STAGE2 = A_STAGE + B_STAGE;   // 98304
constexpr int SMEM_BIG = 2 * STAGE2;        // 196608

// Gate: CTA covers 128m x 128n as 2 sub-tiles of 64n. A-head (128x256 fp16,
// 64KB) resident for the whole CTA; B in a 4-stage ring of 8KB chunks.
constexpr int GBM = 128;
constexpr int GBN_SUB = 64;
constexpr int G_NSUB = 2;
constexpr int G_NITER = 4 * G_NSUB;          // 8 chunk-iterations
constexpr int G_A_BYTES = 4 * GBM * 128;     // 65536 (4 chunks x 16KB)
constexpr int G_B_STAGE = GBN_SUB * 128;     // 8192
constexpr int G_B_OFF   = G_A_BYTES;         // 65536
constexpr int G_MASK_OFF = G_B_OFF + 4 * G_B_STAGE;   // 98304 (8KB stage)
constexpr int G_LBUF_OFF = G_MASK_OFF + GBM * GBN_SUB; // 106496 (1024 x u32)
constexpr int G_LBUF_CAP = 1024;
constexpr int G_LCOUNT_OFF = G_LBUF_OFF + G_LBUF_CAP * 4;  // 110592
constexpr int G_LBASE_OFF  = G_LCOUNT_OFF + 4;             // 110596
constexpr int G_LNUM_OFF   = G_LBASE_OFF + 4;              // 110600
constexpr int SMEM_GATE = 110608;            // 2 CTAs/SM: 221216 <= 228KB

constexpr int LIST_CAP = 1 << 25;           // 33.5M (full-size safe)
}

// ---------------------------------------------------------------------------
// Device scratch (static; no dynamic allocation allowed)
// ---------------------------------------------------------------------------
__device__ __align__(1024) unsigned char g_mask[(size_t)M_DIM * N_DIM];
__device__ __align__(1024) __half        g_Xh[(size_t)M_DIM * K_DIM];
__device__ __align__(1024) __half        g_Wh[(size_t)N_DIM * K_DIM];
__device__ __align__(1024) uint32_t      g_list[LIST_CAP];
__device__ int                           g_count;

// ---------------------------------------------------------------------------
// Helpers (base-ISA only: cp.async / ldmatrix / mma.sync)
// ---------------------------------------------------------------------------
__device__ __forceinline__ uint32_t smem_u32(const void* p) {
    uint32_t a;
    asm("{ .reg .u64 t; cvta.to.shared.u64 t, %1; cvt.u32.u64 %0, t; }" : "=r"(a) : "l"(p));
    return a;
}
#define SWZ128(off) ((off) ^ (((off) >> 3) & 0x70))

__device__ __forceinline__ void cp_async16(uint32_t dst, const void* src) {
    asm volatile("cp.async.cg.shared.global [%0], [%1], 16;"
                 :: "r"(dst), "l"(__cvta_generic_to_global(src)) : "memory");
}
#define CP_COMMIT() asm volatile("cp.async.commit_group;" ::: "memory")
#define CP_WAIT0()  asm volatile("cp.async.wait_group 0;" ::: "memory")
#define CP_WAIT2()  asm volatile("cp.async.wait_group 2;" ::: "memory")

__device__ __forceinline__ void ldsm_x4(uint32_t& r0, uint32_t& r1, uint32_t& r2,
                                        uint32_t& r3, uint32_t addr) {
    asm volatile("ldmatrix.sync.aligned.m8n8.x4.shared.b16 {%0,%1,%2,%3}, [%4];"
                 : "=r"(r0), "=r"(r1), "=r"(r2), "=r"(r3) : "r"(addr));
}
__device__ __forceinline__ void mma_fp16(float* c, const uint32_t* a,
                                         uint32_t b0, uint32_t b1) {
    asm volatile("mma.sync.aligned.m16n8k16.row.col.f32.f16.f16.f32 "
                 "{%0,%1,%2,%3}, {%4,%5,%6,%7}, {%8,%9}, {%0,%1,%2,%3};"
                 : "+f"(c[0]), "+f"(c[1]), "+f"(c[2]), "+f"(c[3])
                 : "r"(a[0]), "r"(a[1]), "r"(a[2]), "r"(a[3]), "r"(b0), "r"(b1));
}
__device__ __forceinline__ uint32_t sq_h2(uint32_t v) {
    uint32_t r;
    asm("mul.rn.f16x2 %0, %1, %1;" : "=r"(r) : "r"(v));
    return r;
}

// ---------------------------------------------------------------------------
// Convert: fp32 -> fp16 (RN) for both X and W. 16 floats per thread.
// Also zeroes g_count (block 0 / thread 0).
// ---------------------------------------------------------------------------
__global__ __launch_bounds__(256)
void conv_all(const float* __restrict__ X, const float* __restrict__ W)
{
    if (blockIdx.x == 0 && threadIdx.x == 0) g_count = 0;
    int idx = blockIdx.x * 256 + threadIdx.x;
    int r   = idx >> 8;
    int c   = (idx & 255) * 16;
    const float* src; __half* dst; int row;
    if (r < M_DIM) { src = X; dst = g_Xh; row = r; }
    else           { src = W; dst = g_Wh; row = r - M_DIM; }
    const float4* s = reinterpret_cast<const float4*>(src + (size_t)row * K_DIM + c);
    float4 v0 = s[0], v1 = s[1], v2 = s[2], v3 = s[3];
    uint32_t o[8];
    __half2 h;
    h = __floats2half2_rn(v0.x, v0.y); o[0] = *reinterpret_cast<uint32_t*>(&h);
    h = __floats2half2_rn(v0.z, v0.w); o[1] = *reinterpret_cast<uint32_t*>(&h);
    h = __floats2half2_rn(v1.x, v1.y); o[2] = *reinterpret_cast<uint32_t*>(&h);
    h = __floats2half2_rn(v1.z, v1.w); o[3] = *reinterpret_cast<uint32_t*>(&h);
    h = __floats2half2_rn(v2.x, v2.y); o[4] = *reinterpret_cast<uint32_t*>(&h);
    h = __floats2half2_rn(v2.z, v2.w); o[5] = *reinterpret_cast<uint32_t*>(&h);
    h = __floats2half2_rn(v3.x, v3.y); o[6] = *reinterpret_cast<uint32_t*>(&h);
    h = __floats2half2_rn(v3.z, v3.w); o[7] = *reinterpret_cast<uint32_t*>(&h);
    uint4* d = reinterpret_cast<uint4*>(dst + (size_t)row * K_DIM + c);
    d[0] = make_uint4(o[0], o[1], o[2], o[3]);
    d[1] = make_uint4(o[4], o[5], o[6], o[7]);
}

// ---------------------------------------------------------------------------
// Big GEMM + fused merge: Out = bias + (mask ? Xh@Wh^T : 0) over full K=4096.
// CTA 128x256, warp 64x64, BK=128 (2x 64-col halves), 2-stage ring.
// Per-chunk order: WAIT0 -> sync -> prefetch(it+1 into buf^1) -> compute(it).
// The sync both publishes completed cp.asyncs and orders last-reads of buf^1
// before the prefetch overwrites it. 32 syncs total (was 64).
// Register-level fragment double-buffering across the 8 k-steps.
// ---------------------------------------------------------------------------
__global__ __launch_bounds__(256, 1)
void big_gemm(float* __restrict__ Out, const float* __restrict__ Bv)
{
    extern __shared__ __align__(1024) char smem[];
    const uint32_t sbase = smem_u32(smem);
    const int tid  = threadIdx.x;
    const int wid  = tid >> 5;
    const int lane = tid & 31;

    const int bm = blockIdx.y * BM;
    const int bn = blockIdx.x * BN;

    const int warpM = (wid & 1) * 64;
    const int warpN = (wid >> 1) * 64;

    const int subl = lane >> 3;
    const int tr   = lane & 7;
    const int aRow = (subl & 1) * 8 + tr;
    const int aK8  = (subl >> 1);
    const int bRow = (subl >> 1) * 8 + tr;
    const int bK8  = (subl & 1);

    float acc[4][8][4];
    #pragma unroll
    for (int i = 0; i < 4; ++i)
        #pragma unroll
        for (int j = 0; j < 8; ++j)
            #pragma unroll
            for (int q = 0; q < 4; ++q) acc[i][j][q] = 0.0f;

    // A: 2048 16B lines (2 halves x 1024), B: 4096 lines (2 halves x 2048)
    auto load_chunk = [&](int it, int buf) {
        const __half* Ap = g_Xh + (size_t)bm * K_DIM + it * BK;
        const __half* Bp = g_Wh + (size_t)bn * K_DIM + it * BK;
        const uint32_t aOff = buf * STAGE2;
        const uint32_t bOff = aOff + A_STAGE;
        #pragma unroll
        for (int l = 0; l < 8; ++l) {
            int idx  = tid + l * 256;
            int h    = idx >> 10;
            int line = idx & 1023;
            int r = line >> 3, c = line & 7;
            cp_async16(sbase + aOff + h * 16384 + SWZ128((uint32_t)(r * 128 + c * 16)),
                       Ap + (size_t)r * K_DIM + h * 64 + c * 8);
        }
        #pragma unroll
        for (int l = 0; l < 16; ++l) {
            int idx  = tid + l * 256;
            int h    = idx >> 11;
            int line = idx & 2047;
            int r = line >> 3, c = line & 7;
            cp_async16(sbase + bOff + h * 32768 + SWZ128((uint32_t)(r * 128 + c * 16)),
                       Bp + (size_t)r * K_DIM + h * 64 + c * 8);
        }
    };

    uint32_t af[2][4][4], bf[2][4][4];

    auto load_frags = [&](int ks, int slot, uint32_t aBase, uint32_t bBase) {
        const int half = ks >> 2;
        const int ksl  = ks & 3;
        const uint32_t aB = aBase + half * 16384;
        const uint32_t bB = bBase + half * 32768;
        #pragma unroll
        for (int mi = 0; mi < 4; ++mi) {
            int row = warpM + mi * 16 + aRow;
            uint32_t byte = (uint32_t)(row * 128) +
                            ((uint32_t)((ksl * 2 + aK8) * 16) ^ ((row & 7) * 16));
            ldsm_x4(af[slot][mi][0], af[slot][mi][1],
                    af[slot][mi][2], af[slot][mi][3], aB + byte);
        }
        #pragma unroll
        for (int pr = 0; pr < 4; ++pr) {
            int row = warpN + pr * 16 + bRow;
            uint32_t byte = (uint32_t)(row * 128) +
                            ((uint32_t)((ksl * 2 + bK8) * 16) ^ ((row & 7) * 16));
            ldsm_x4(bf[slot][pr][0], bf[slot][pr][1],
                    bf[slot][pr][2], bf[slot][pr][3], bB + byte);
        }
    };

    load_chunk(0, 0); CP_COMMIT();

    int buf = 0;
    for (int it = 0; it < NCHUNK; ++it) {
        CP_WAIT0();           // chunk `it` fully landed (prefetched last iter)
        __syncthreads();      // publish cp.async data + protect buf^1 reads
        if (it + 1 < NCHUNK) {
            load_chunk(it + 1, buf ^ 1);
            CP_COMMIT();
        }

        const uint32_t aBase = sbase + buf * STAGE2;
        const uint32_t bBase = aBase + A_STAGE;

        load_frags(0, 0, aBase, bBase);
        #pragma unroll
        for (int ks = 0; ks < 8; ++ks) {
            const int cur = ks & 1;
            if (ks < 7) load_frags(ks + 1, cur ^ 1, aBase, bBase);
            #pragma unroll
            for (int pr = 0; pr < 4; ++pr)
                #pragma unroll
                for (int mi = 0; mi < 4; ++mi) {
                    mma_fp16(acc[mi][pr * 2 + 0], af[cur][mi],
                             bf[cur][pr][0], bf[cur][pr][1]);
                    mma_fp16(acc[mi][pr * 2 + 1], af[cur][mi],
                             bf[cur][pr][2], bf[cur][pr][3]);
                }
        }
        buf ^= 1;
    }

    // ---- epilogue: stage mask tile + bias row into (dead) smem buffers ----
    __syncthreads();   // all warps done reading stage buffers
    {
        #pragma unroll
        for (int l = 0; l < 8; ++l) {                 // 2048 uint4 of mask
            int idx = tid + l * 256;
            int r = idx >> 4, c = (idx & 15) * 16;
            *reinterpret_cast<uint4*>(smem + r * 256 + c) =
                *reinterpret_cast<const uint4*>(g_mask + (size_t)(bm + r) * N_DIM + bn + c);
        }
        if (tid < 64) {                               // 256 bias floats
            *reinterpret_cast<float4*>(smem + 32768 + tid * 16) =
                *reinterpret_cast<const float4*>(Bv + bn + tid * 4);
        }
    }
    __syncthreads();
    const unsigned char* maskS = reinterpret_cast<const unsigned char*>(smem);
    const float*         biasS = reinterpret_cast<const float*>(smem + 32768);

    const int mrow = lane >> 2;
    const int ncol = (lane & 3) * 2;
    #pragma unroll
    for (int mi = 0; mi < 4; ++mi) {
        #pragma unroll
        for (int ni = 0; ni < 8; ++ni) {
            const int mr = warpM + mi * 16 + mrow;
            const int nc = warpN + ni * 8 + ncol;
            const float bx = biasS[nc];
            const float by = biasS[nc + 1];
            size_t o  = (size_t)(bm + mr) * N_DIM + bn + nc;
            size_t o2 = o + (size_t)8 * N_DIM;
            float2 v0, v1;
            v0.x = bx + (maskS[mr * 256 + nc]           ? acc[mi][ni][0] : 0.0f);
            v0.y = by + (maskS[mr * 256 + nc + 1]       ? acc[mi][ni][1] : 0.0f);
            v1.x = bx + (maskS[(mr + 8) * 256 + nc]     ? acc[mi][ni][2] : 0.0f);
            v1.y = by + (maskS[(mr + 8) * 256 + nc + 1] ? acc[mi][ni][3] : 0.0f);
            *reinterpret_cast<float2*>(&Out[o])  = v0;
            *reinterpret_cast<float2*>(&Out[o2]) = v1;
        }
    }
}

// ---------------------------------------------------------------------------
// Gate GEMM v3 (unchanged): A-head resident, 2 N-sub-tiles per CTA,
// 4-stage B ring, squares in registers, coalesced mask staging,
// CTA-aggregated uncertain list.
// ---------------------------------------------------------------------------
__global__ __launch_bounds__(256, 2)
void gate_gemm()
{
    extern __shared__ __align__(1024) char smem[];
    const uint32_t sbase = smem_u32(smem);
    const int tid  = threadIdx.x;
    const int wid  = tid >> 5;
    const int lane = tid & 31;

    const int bm = blockIdx.y * GBM;
    const int bn = blockIdx.x * (GBN_SUB * G_NSUB);

    const int warpM = (wid & 3) * 32;
    const int warpN = (wid >> 2) * 32;

    const int subl = lane >> 3;
    const int tr   = lane & 7;
    const int aRow = (subl & 1) * 8 + tr;
    const int aK8  = (subl >> 1);
    const int bRow = (subl >> 1) * 8 + tr;
    const int bK8  = (subl & 1);

    unsigned char* stage = reinterpret_cast<unsigned char*>(smem + G_MASK_OFF);
    uint32_t* lbuf  = reinterpret_cast<uint32_t*>(smem + G_LBUF_OFF);
    int* lcount = reinterpret_cast<int*>(smem + G_LCOUNT_OFF);
    int* lbase  = reinterpret_cast<int*>(smem + G_LBASE_OFF);
    int* lnum   = reinterpret_cast<int*>(smem + G_LNUM_OFF);
    if (tid == 0) *lcount = 0;

    float accY[2][4][4], accS[2][4][4];
    #pragma unroll
    for (int i = 0; i < 2; ++i)
        #pragma unroll
        for (int j = 0; j < 4; ++j)
            #pragma unroll
            for (int q = 0; q < 4; ++q) { accY[i][j][q] = 0.0f; accS[i][j][q] = 0.0f; }

    {
        #pragma unroll
        for (int l = 0; l < 16; ++l) {
            int idx = tid + l * 256;
            int chunk = idx >> 10;
            int line  = idx & 1023;
            int r = line >> 3, c = line & 7;
            cp_async16(sbase + chunk * 16384 + SWZ128((uint32_t)(r * 128 + c * 16)),
                       g_Xh + (size_t)(bm + r) * K_DIM + chunk * 64 + c * 8);
        }
    }

    auto load_B = [&](int it) {
        int sub = it >> 2, ck = it & 3;
        const __half* Bp = g_Wh + (size_t)(bn + sub * GBN_SUB) * K_DIM + ck * 64;
        const uint32_t s0 = G_B_OFF + (it & 3) * G_B_STAGE;
        #pragma unroll
        for (int l = 0; l < 2; ++l) {
            int idx = tid + l * 256;
            int r = idx >> 3, c = idx & 7;
            cp_async16(sbase + s0 + SWZ128((uint32_t)(r * 128 + c * 16)),
                       Bp + (size_t)r * K_DIM + c * 8);
        }
    };

    load_B(0); CP_COMMIT();
    load_B(1); CP_COMMIT();

    for (int it = 0; it < G_NITER; ++it) {
        if (it + 2 < G_NITER) load_B(it + 2);
        CP_COMMIT();
        CP_WAIT2();
        __syncthreads();

        const uint32_t aBase = sbase + (it & 3) * 16384;
        const uint32_t bBase = sbase + G_B_OFF + (it & 3) * G_B_STAGE;

        #pragma unroll
        for (int ks = 0; ks < 4; ++ks) {
            uint32_t ah[2][4], aq[2][4];
            #pragma unroll
            for (int mi = 0; mi < 2; ++mi) {
                int row = warpM + mi * 16 + aRow;
                uint32_t byte = (uint32_t)(row * 128) +
                                ((uint32_t)((ks * 2 + aK8) * 16) ^ ((row & 7) * 16));
                ldsm_x4(ah[mi][0], ah[mi][1], ah[mi][2], ah[mi][3], aBase + byte);
                #pragma unroll
                for (int r = 0; r < 4; ++r) aq[mi][r] = sq_h2(ah[mi][r]);
            }
            #pragma unroll
            for (int pr = 0; pr < 2; ++pr) {
                int row = warpN + pr * 16 + bRow;
                uint32_t byte = (uint32_t)(row * 128) +
                                ((uint32_t)((ks * 2 + bK8) * 16) ^ ((row & 7) * 16));
                uint32_t h0, h1, h2, h3;
                ldsm_x4(h0, h1, h2, h3, bBase + byte);
                uint32_t q0 = sq_h2(h0), q1 = sq_h2(h1);
                uint32_t q2 = sq_h2(h2), q3 = sq_h2(h3);
                #pragma unroll
                for (int mi = 0; mi < 2; ++mi) {
                    mma_fp16(accY[mi][pr * 2 + 0], ah[mi], h0, h1);
                    mma_fp16(accY[mi][pr * 2 + 1], ah[mi], h2, h3);
                    mma_fp16(accS[mi][pr * 2 + 0], aq[mi], q0, q1);
                    mma_fp16(accS[mi][pr * 2 + 1], aq[mi], q2, q3);
                }
            }
        }

        if ((it & 3) == 3) {
            const int sub = it >> 2;
            const int mrow = lane >> 2;
            const int ncol = (lane & 3) * 2;
            #pragma unroll
            for (int mi = 0; mi < 2; ++mi)
                #pragma unroll
                for (int ni = 0; ni < 4; ++ni)
                    #pragma unroll
                    for (int h = 0; h < 2; ++h) {
                        const int mr = warpM + mi * 16 + mrow + h * 8;
                        const int nc = warpN + ni * 8 + ncol;
                        #pragma unroll
                        for (int q = 0; q < 2; ++q) {
                            float y = accY[mi][ni][h * 2 + q];
                            float s = accS[mi][ni][h * 2 + q];
                            float denom = sqrtf(s * (1.0f / 256.0f) + EPS);
                            float t = fabsf(y) / fmaxf(denom, EPS);
                            unsigned char mv;
                            if (t < TAU - BAND)      mv = 0;
                            else if (t > TAU + BAND) mv = 1;
                            else {
                                mv = 1;
                                int li = atomicAdd(lcount, 1);
                                uint32_t pk = ((uint32_t)(bm + mr) << 12) |
                                              (uint32_t)(bn + sub * GBN_SUB + nc + q);
                                if (li < G_LBUF_CAP) lbuf[li] = pk;
                                else {
                                    int gi = atomicAdd(&g_count, 1);
                                    if (gi < LIST_CAP) g_list[gi] = pk;
                                }
                            }
                            stage[mr * 64 + nc + q] = mv;
                        }
                    }
            __syncthreads();
            {
                int mr = tid >> 1, half = (tid & 1) * 32;
                uint4 v0 = *reinterpret_cast<uint4*>(stage + mr * 64 + half);
                uint4 v1 = *reinterpret_cast<uint4*>(stage + mr * 64 + half + 16);
                size_t go = (size_t)(bm + mr) * N_DIM + bn + sub * GBN_SUB + half;
                *reinterpret_cast<uint4*>(g_mask + go)      = v0;
                *reinterpret_cast<uint4*>(g_mask + go + 16) = v1;
            }
            if (tid == 0) {
                int ln = *lcount; if (ln > G_LBUF_CAP) ln = G_LBUF_CAP;
                *lbase = atomicAdd(&g_count, ln);
                *lnum  = ln;
                *lcount = 0;
            }
            __syncthreads();
            {
                int ln = *lnum, base = *lbase;
                for (int i = tid; i < ln; i += 256) {
                    int gi = base + i;
                    if (gi < LIST_CAP) g_list[gi] = lbuf[i];
                }
            }
            #pragma unroll
            for (int i = 0; i < 2; ++i)
                #pragma unroll
                for (int j = 0; j < 4; ++j)
                    #pragma unroll
                    for (int q = 0; q < 4; ++q) { accY[i][j][q] = 0.0f; accS[i][j][q] = 0.0f; }
        }
    }
}

// ---------------------------------------------------------------------------
// Fixup: exact fp32 recompute of y1/s2 for uncertain elements (1 warp each).
// ---------------------------------------------------------------------------
__global__ __launch_bounds__(256)
void fixup_kernel(const float* __restrict__ X, const float* __restrict__ W)
{
    const int lane = threadIdx.x & 31;
    const int wglobal = (blockIdx.x * 256 + threadIdx.x) >> 5;
    const int nwarps = (gridDim.x * 256) >> 5;
    int total = g_count; if (total > LIST_CAP) total = LIST_CAP;

    for (int i = wglobal; i < total; i += nwarps) {
        uint32_t p = g_list[i];
        int m = p >> 12;
        int n = p & 4095;
        const float* xr = X + (size_t)m * K_DIM;
        const float* wr = W + (size_t)n * K_DIM;
        float y = 0.0f, s = 0.0f;
        #pragma unroll
        for (int j = 0; j < 2; ++j) {
            float4 a = *reinterpret_cast<const float4*>(xr + lane * 8 + j * 4);
            float4 b = *reinterpret_cast<const float4*>(wr + lane * 8 + j * 4);
            y = fmaf(a.x, b.x, y); y = fmaf(a.y, b.y, y);
            y = fmaf(a.z, b.z, y); y = fmaf(a.w, b.w, y);
            float px = a.x * b.x, py = a.y * b.y, pz = a.z * b.z, pw = a.w * b.w;
            s = fmaf(px, px, s); s = fmaf(py, py, s);
            s = fmaf(pz, pz, s); s = fmaf(pw, pw, s);
        }
        #pragma unroll
        for (int off = 16; off > 0; off >>= 1) {
            y += __shfl_xor_sync(0xFFFFFFFF, y, off);
            s += __shfl_xor_sync(0xFFFFFFFF, s, off);
        }
        if (lane == 0) {
            float denom = sqrtf(s * (1.0f / 256.0f) + EPS);
            float t = fabsf(y) / fmaxf(denom, EPS);
            g_mask[(size_t)m * N_DIM + n] = (t < TAU) ? 0 : 1;
        }
    }
}

// ---------------------------------------------------------------------------
extern "C" void kernel_launch(void* const* d_in, const int* in_sizes, int n_in,
                              void* d_out, int out_size)
{
    const float* x  = (const float*)d_in[0];   // [8192, 4096]
    const float* w  = (const float*)d_in[1];   // [4096, 4096]
    const float* bv = (const float*)d_in[2];   // [4096]
    float* out      = (float*)d_out;           // [8192, 4096]
    (void)in_sizes; (void)n_in; (void)out_size;

    cudaFuncSetAttribute(big_gemm,
                         cudaFuncAttributeMaxDynamicSharedMemorySize, SMEM_BIG);
    cudaFuncSetAttribute(gate_gemm,
                         cudaFuncAttributeMaxDynamicSharedMemorySize, SMEM_GATE);

    conv_all<<<(M_DIM + N_DIM) * 256 / 256, 256>>>(x, w);   // 12288 blocks

    // Gate (classify + uncertain list), then exact fixup -> mask final
    dim3 gateGrid(N_DIM / (GBN_SUB * G_NSUB), M_DIM / GBM);   // (32, 64)
    gate_gemm<<<gateGrid, 256, SMEM_GATE>>>();
    fixup_kernel<<<512, 256>>>(x, w);

    // Full-K value GEMM with fused mask+bias epilogue
    dim3 bigGrid(N_DIM / BN, M_DIM / BM);      // (16, 64)
    big_gemm<<<bigGrid, 256, SMEM_BIG>>>(out, bv);
}